// round 2
// baseline (speedup 1.0000x reference)
#include <cuda_runtime.h>

// ---------------------------------------------------------------------------
// MultiHeadAttention: x[B,S,D] -> out[B,S,D]
// B=4, S=2048, D=1024, H=16, dk=64
// Pipeline:
//   1) gemm_nt<1> x3 : Q/K/V = (x @ W^T + b) -> [B,H,S,dk]   (Q pre-scaled 1/8)
//   2) flash_attn    : ctx[B,S,D] = softmax(Q K^T) V  (online softmax, fp32)
//   3) gemm_nt<0>    : out = ctx @ Wo^T + bo
// ---------------------------------------------------------------------------

constexpr int D_MODEL = 1024;
constexpr int H       = 16;
constexpr int DKH     = 64;
constexpr int SEQ     = 2048;
constexpr int BATCH   = 4;
constexpr int MROWS   = BATCH * SEQ;      // 8192

__device__ float g_q[BATCH * H * SEQ * DKH];
__device__ float g_k[BATCH * H * SEQ * DKH];
__device__ float g_v[BATCH * H * SEQ * DKH];
__device__ float g_ctx[BATCH * SEQ * D_MODEL];

// ---------------------------------------------------------------------------
// C[M,N] = A[M,K] @ W[N,K]^T + bias   (both operands K-contiguous)
// MODE 0: C row-major [M,N]
// MODE 1: scatter to [B,H,S,dk] layout, multiplied by `scale`
// Tiles: BM=128, BN=128, BK=8; 256 threads; 8x8 per thread.
// ---------------------------------------------------------------------------
template <int MODE>
__global__ void __launch_bounds__(256)
gemm_nt(const float* __restrict__ A, const float* __restrict__ W,
        const float* __restrict__ bias, float* __restrict__ C,
        int M, int N, int K, float scale)
{
    __shared__ float As[8][128];
    __shared__ float Bs[8][128];

    const int tid = threadIdx.x;
    const int m0  = blockIdx.y * 128;
    const int n0  = blockIdx.x * 128;
    const int tx  = tid & 15;          // 0..15 -> column groups
    const int ty  = tid >> 4;          // 0..15 -> row groups
    const int lr  = tid >> 1;          // 0..127 load row
    const int lc  = (tid & 1) << 2;    // 0 or 4 load col

    float acc[8][8];
    #pragma unroll
    for (int i = 0; i < 8; i++)
        #pragma unroll
        for (int j = 0; j < 8; j++) acc[i][j] = 0.f;

    const float* Aptr = A + (size_t)(m0 + lr) * K + lc;
    const float* Wptr = W + (size_t)(n0 + lr) * K + lc;

    for (int k0 = 0; k0 < K; k0 += 8) {
        float4 av = *(const float4*)(Aptr + k0);
        float4 wv = *(const float4*)(Wptr + k0);
        __syncthreads();
        As[lc + 0][lr] = av.x; As[lc + 1][lr] = av.y;
        As[lc + 2][lr] = av.z; As[lc + 3][lr] = av.w;
        Bs[lc + 0][lr] = wv.x; Bs[lc + 1][lr] = wv.y;
        Bs[lc + 2][lr] = wv.z; Bs[lc + 3][lr] = wv.w;
        __syncthreads();

        #pragma unroll
        for (int kk = 0; kk < 8; kk++) {
            float ar[8], br[8];
            *(float4*)&ar[0] = *(const float4*)&As[kk][ty * 8];
            *(float4*)&ar[4] = *(const float4*)&As[kk][ty * 8 + 4];
            *(float4*)&br[0] = *(const float4*)&Bs[kk][tx * 4];
            *(float4*)&br[4] = *(const float4*)&Bs[kk][64 + tx * 4];
            #pragma unroll
            for (int i = 0; i < 8; i++)
                #pragma unroll
                for (int j = 0; j < 8; j++)
                    acc[i][j] = fmaf(ar[i], br[j], acc[i][j]);
        }
    }

    #pragma unroll
    for (int i = 0; i < 8; i++) {
        const int m = m0 + ty * 8 + i;
        #pragma unroll
        for (int j = 0; j < 8; j++) {
            const int n = n0 + ((j < 4) ? (tx * 4 + j) : (64 + tx * 4 + j - 4));
            float v = acc[i][j] + bias[n];
            if (MODE == 0) {
                C[(size_t)m * N + n] = v;
            } else {
                const int b  = m >> 11;          // /SEQ
                const int s_ = m & (SEQ - 1);
                const int h  = n >> 6;           // /dk
                const int d  = n & 63;
                C[(((size_t)(b * H + h)) * SEQ + s_) * DKH + d] = v * scale;
            }
        }
    }
}

// ---------------------------------------------------------------------------
// Flash attention, fp32. One block = 64 query rows of one (b,h).
// 256 threads as 16x16; each thread owns a 4x4 microtile of S and of O.
// Smem (static 48KB): Qt[d][r], Kt[d][c] (aliased by Ps[r][c] after S-compute),
// Vs[c][d]. Q is pre-scaled by 1/sqrt(dk) at projection time.
// ---------------------------------------------------------------------------
__global__ void __launch_bounds__(256)
flash_attn(const float* __restrict__ Q, const float* __restrict__ K,
           const float* __restrict__ V, float* __restrict__ ctx)
{
    __shared__ float sm[3 * 64 * 64];
    float* Qt = sm;                // [64][64]  (d-major)
    float* Kt = sm + 64 * 64;      // [64][64]  (d-major); reused as Ps [r][c]
    float* Vs = sm + 2 * 64 * 64;  // [64][64]  (c-major rows)
    float* Ps = Kt;                // alias: K tile dead after S=QK^T

    const int tid = threadIdx.x;
    const int tx  = tid & 15;
    const int ty  = tid >> 4;
    const int bh  = blockIdx.y;
    const int q0  = blockIdx.x * 64;

    const float* Qb = Q + (size_t)bh * SEQ * DKH;
    const float* Kb = K + (size_t)bh * SEQ * DKH;
    const float* Vb = V + (size_t)bh * SEQ * DKH;

    // Fill Qt transposed (once)
    #pragma unroll
    for (int rep = 0; rep < 4; rep++) {
        const int idx = tid + rep * 256;
        const int row = idx >> 4;
        const int d4  = (idx & 15) << 2;
        float4 v = *(const float4*)(Qb + (size_t)(q0 + row) * DKH + d4);
        Qt[(d4 + 0) * 64 + row] = v.x;
        Qt[(d4 + 1) * 64 + row] = v.y;
        Qt[(d4 + 2) * 64 + row] = v.z;
        Qt[(d4 + 3) * 64 + row] = v.w;
    }

    float o[4][4];
    float mrow[4], lrow[4];
    #pragma unroll
    for (int i = 0; i < 4; i++) {
        mrow[i] = -1e30f;
        lrow[i] = 0.f;
        #pragma unroll
        for (int j = 0; j < 4; j++) o[i][j] = 0.f;
    }

    for (int kt = 0; kt < SEQ / 64; kt++) {
        const int c0 = kt * 64;
        __syncthreads();   // protect Kt(=Ps)/Vs from previous iteration's readers
        #pragma unroll
        for (int rep = 0; rep < 4; rep++) {
            const int idx = tid + rep * 256;
            const int row = idx >> 4;
            const int d4  = (idx & 15) << 2;
            float4 kv = *(const float4*)(Kb + (size_t)(c0 + row) * DKH + d4);
            Kt[(d4 + 0) * 64 + row] = kv.x;
            Kt[(d4 + 1) * 64 + row] = kv.y;
            Kt[(d4 + 2) * 64 + row] = kv.z;
            Kt[(d4 + 3) * 64 + row] = kv.w;
            float4 vv = *(const float4*)(Vb + (size_t)(c0 + row) * DKH + d4);
            *(float4*)&Vs[row * 64 + d4] = vv;
        }
        __syncthreads();

        // S tile = Q K^T (64x64), this thread's 4x4
        float sacc[4][4];
        #pragma unroll
        for (int i = 0; i < 4; i++)
            #pragma unroll
            for (int j = 0; j < 4; j++) sacc[i][j] = 0.f;

        #pragma unroll 4
        for (int kk = 0; kk < 64; kk++) {
            float qr[4], kr[4];
            *(float4*)qr = *(const float4*)&Qt[kk * 64 + ty * 4];
            *(float4*)kr = *(const float4*)&Kt[kk * 64 + tx * 4];
            #pragma unroll
            for (int i = 0; i < 4; i++)
                #pragma unroll
                for (int j = 0; j < 4; j++)
                    sacc[i][j] = fmaf(qr[i], kr[j], sacc[i][j]);
        }

        __syncthreads();   // all K-tile reads done before Ps overwrites Kt

        // Online softmax per row (reduce across the 16 tx lanes)
        #pragma unroll
        for (int i = 0; i < 4; i++) {
            float tm = fmaxf(fmaxf(sacc[i][0], sacc[i][1]),
                             fmaxf(sacc[i][2], sacc[i][3]));
            #pragma unroll
            for (int off = 8; off > 0; off >>= 1)
                tm = fmaxf(tm, __shfl_xor_sync(0xffffffffu, tm, off, 16));
            const float mn = fmaxf(mrow[i], tm);
            const float alpha = __expf(mrow[i] - mn);
            mrow[i] = mn;
            float rs = 0.f;
            #pragma unroll
            for (int j = 0; j < 4; j++) {
                sacc[i][j] = __expf(sacc[i][j] - mn);
                rs += sacc[i][j];
            }
            #pragma unroll
            for (int off = 8; off > 0; off >>= 1)
                rs += __shfl_xor_sync(0xffffffffu, rs, off, 16);
            lrow[i] = lrow[i] * alpha + rs;
            #pragma unroll
            for (int j = 0; j < 4; j++) o[i][j] *= alpha;
            *(float4*)&Ps[(ty * 4 + i) * 64 + tx * 4] =
                make_float4(sacc[i][0], sacc[i][1], sacc[i][2], sacc[i][3]);
        }
        __syncthreads();

        // O += P @ V
        #pragma unroll 4
        for (int cc0 = 0; cc0 < 64; cc0 += 4) {
            float pr[4][4], vr[4][4];
            #pragma unroll
            for (int i = 0; i < 4; i++)
                *(float4*)pr[i] = *(const float4*)&Ps[(ty * 4 + i) * 64 + cc0];
            #pragma unroll
            for (int c = 0; c < 4; c++)
                *(float4*)vr[c] = *(const float4*)&Vs[(cc0 + c) * 64 + tx * 4];
            #pragma unroll
            for (int i = 0; i < 4; i++)
                #pragma unroll
                for (int c = 0; c < 4; c++)
                    #pragma unroll
                    for (int j = 0; j < 4; j++)
                        o[i][j] = fmaf(pr[i][c], vr[c][j], o[i][j]);
        }
    }

    // Epilogue: normalize and write ctx in [B,S,D] layout
    const int b = bh >> 4;
    const int h = bh & 15;
    #pragma unroll
    for (int i = 0; i < 4; i++) {
        const float inv = 1.0f / lrow[i];
        float4 outv = make_float4(o[i][0] * inv, o[i][1] * inv,
                                  o[i][2] * inv, o[i][3] * inv);
        const size_t off = ((size_t)b * SEQ + q0 + ty * 4 + i) * D_MODEL
                         + h * 64 + tx * 4;
        *(float4*)(ctx + off) = outv;
    }
}

// ---------------------------------------------------------------------------
extern "C" void kernel_launch(void* const* d_in, const int* in_sizes, int n_in,
                              void* d_out, int out_size)
{
    const float* x  = (const float*)d_in[0];
    const float* Wq = (const float*)d_in[1];
    const float* bq = (const float*)d_in[2];
    const float* Wk = (const float*)d_in[3];
    const float* bk = (const float*)d_in[4];
    const float* Wv = (const float*)d_in[5];
    const float* bv = (const float*)d_in[6];
    const float* Wo = (const float*)d_in[7];
    const float* bo = (const float*)d_in[8];
    float* out = (float*)d_out;

    float *gq, *gk, *gv, *gctx;
    cudaGetSymbolAddress((void**)&gq,   g_q);
    cudaGetSymbolAddress((void**)&gk,   g_k);
    cudaGetSymbolAddress((void**)&gv,   g_v);
    cudaGetSymbolAddress((void**)&gctx, g_ctx);

    const dim3 gproj(D_MODEL / 128, MROWS / 128);   // (8, 64)
    const float qscale = 0.125f;                     // 1/sqrt(64)

    gemm_nt<1><<<gproj, 256>>>(x, Wq, bq, gq, MROWS, D_MODEL, D_MODEL, qscale);
    gemm_nt<1><<<gproj, 256>>>(x, Wk, bk, gk, MROWS, D_MODEL, D_MODEL, 1.0f);
    gemm_nt<1><<<gproj, 256>>>(x, Wv, bv, gv, MROWS, D_MODEL, D_MODEL, 1.0f);

    flash_attn<<<dim3(SEQ / 64, BATCH * H), 256>>>(gq, gk, gv, gctx);

    gemm_nt<0><<<gproj, 256>>>(gctx, Wo, bo, out, MROWS, D_MODEL, D_MODEL, 1.0f);
}

// round 3
// speedup vs baseline: 1.1854x; 1.1854x over previous
#include <cuda_runtime.h>

// ---------------------------------------------------------------------------
// MultiHeadAttention: x[B,S,D] -> out[B,S,D]
// B=4, S=2048, D=1024, H=16, dk=64
//   1) gemm_nt<1> x3 : Q/K/V = (x @ W^T + b) -> [B,H,S,dk]   (Q pre-scaled 1/8)
//   2) flash_attn    : ctx[B,S,D] = softmax(Q K^T) V  (online softmax, fp32)
//   3) gemm_nt<0>    : out = ctx @ Wo^T + bo
// All math fp32; inner products use packed fma.rn.f32x2 (2 FMAs/instr).
// ---------------------------------------------------------------------------

constexpr int D_MODEL = 1024;
constexpr int H       = 16;
constexpr int DKH     = 64;
constexpr int SEQ     = 2048;
constexpr int BATCH   = 4;
constexpr int MROWS   = BATCH * SEQ;      // 8192

__device__ float g_q[BATCH * H * SEQ * DKH];
__device__ float g_k[BATCH * H * SEQ * DKH];
__device__ float g_v[BATCH * H * SEQ * DKH];
__device__ float g_ctx[BATCH * SEQ * D_MODEL];

typedef unsigned long long ull;

__device__ __forceinline__ ull pk(float lo, float hi) {
    ull r;
    asm("mov.b64 %0, {%1, %2};" : "=l"(r) : "f"(lo), "f"(hi));
    return r;
}
__device__ __forceinline__ void upk(ull v, float& lo, float& hi) {
    asm("mov.b64 {%0, %1}, %2;" : "=f"(lo), "=f"(hi) : "l"(v));
}
__device__ __forceinline__ void fma2(ull& d, ull a, ull b) {
    asm("fma.rn.f32x2 %0, %1, %2, %0;" : "+l"(d) : "l"(a), "l"(b));
}
__device__ __forceinline__ void mul2(ull& d, ull a) {
    asm("mul.rn.f32x2 %0, %0, %1;" : "+l"(d) : "l"(a));
}

// ---------------------------------------------------------------------------
// C[M,N] = A[M,K] @ W[N,K]^T + bias   (both operands K-contiguous)
// MODE 0: C row-major [M,N];  MODE 1: scatter to [B,H,S,dk], * scale
// Tiles: BM=128, BN=128, BK=16; 256 threads; 8x8 per thread (f32x2 pairs).
// ---------------------------------------------------------------------------
template <int MODE>
__global__ void __launch_bounds__(256)
gemm_nt(const float* __restrict__ A, const float* __restrict__ W,
        const float* __restrict__ bias, float* __restrict__ C,
        int M, int N, int K, float scale)
{
    __shared__ float As[16][128];
    __shared__ float Bs[16][128];

    const int tid = threadIdx.x;
    const int m0  = blockIdx.y * 128;
    const int n0  = blockIdx.x * 128;
    const int tx  = tid & 15;
    const int ty  = tid >> 4;
    const int lr  = tid >> 2;          // 0..63
    const int lc  = (tid & 3) << 2;    // 0,4,8,12

    ull acc2[8][4];
    #pragma unroll
    for (int i = 0; i < 8; i++)
        #pragma unroll
        for (int p = 0; p < 4; p++) acc2[i][p] = 0ULL;

    const float* Ap  = A + (size_t)(m0 + lr) * K + lc;
    const float* Ap2 = Ap + (size_t)64 * K;
    const float* Wp  = W + (size_t)(n0 + lr) * K + lc;
    const float* Wp2 = Wp + (size_t)64 * K;

    for (int k0 = 0; k0 < K; k0 += 16) {
        float4 a0 = *(const float4*)(Ap  + k0);
        float4 a1 = *(const float4*)(Ap2 + k0);
        float4 b0 = *(const float4*)(Wp  + k0);
        float4 b1 = *(const float4*)(Wp2 + k0);
        __syncthreads();
        As[lc + 0][lr]      = a0.x; As[lc + 1][lr]      = a0.y;
        As[lc + 2][lr]      = a0.z; As[lc + 3][lr]      = a0.w;
        As[lc + 0][lr + 64] = a1.x; As[lc + 1][lr + 64] = a1.y;
        As[lc + 2][lr + 64] = a1.z; As[lc + 3][lr + 64] = a1.w;
        Bs[lc + 0][lr]      = b0.x; Bs[lc + 1][lr]      = b0.y;
        Bs[lc + 2][lr]      = b0.z; Bs[lc + 3][lr]      = b0.w;
        Bs[lc + 0][lr + 64] = b1.x; Bs[lc + 1][lr + 64] = b1.y;
        Bs[lc + 2][lr + 64] = b1.z; Bs[lc + 3][lr + 64] = b1.w;
        __syncthreads();

        #pragma unroll
        for (int kk = 0; kk < 16; kk++) {
            float ar[8], br[8];
            *(float4*)&ar[0] = *(const float4*)&As[kk][ty * 8];
            *(float4*)&ar[4] = *(const float4*)&As[kk][ty * 8 + 4];
            *(float4*)&br[0] = *(const float4*)&Bs[kk][tx * 4];
            *(float4*)&br[4] = *(const float4*)&Bs[kk][64 + tx * 4];
            ull bp[4];
            bp[0] = pk(br[0], br[1]); bp[1] = pk(br[2], br[3]);
            bp[2] = pk(br[4], br[5]); bp[3] = pk(br[6], br[7]);
            #pragma unroll
            for (int i = 0; i < 8; i++) {
                const ull ad = pk(ar[i], ar[i]);
                fma2(acc2[i][0], ad, bp[0]);
                fma2(acc2[i][1], ad, bp[1]);
                fma2(acc2[i][2], ad, bp[2]);
                fma2(acc2[i][3], ad, bp[3]);
            }
        }
    }

    #pragma unroll
    for (int i = 0; i < 8; i++) {
        const int m = m0 + ty * 8 + i;
        #pragma unroll
        for (int p = 0; p < 4; p++) {
            float v0, v1;
            upk(acc2[i][p], v0, v1);
            const int jb = (p < 2) ? (tx * 4 + 2 * p) : (64 + tx * 4 + 2 * (p - 2));
            const int na = n0 + jb, nb = na + 1;
            const float r0 = v0 + bias[na];
            const float r1 = v1 + bias[nb];
            if (MODE == 0) {
                C[(size_t)m * N + na] = r0;
                C[(size_t)m * N + nb] = r1;
            } else {
                const int b  = m >> 11;
                const int s_ = m & (SEQ - 1);
                const int ha = na >> 6, da = na & 63;
                const int hb = nb >> 6, db = nb & 63;
                C[(((size_t)(b * H + ha)) * SEQ + s_) * DKH + da] = r0 * scale;
                C[(((size_t)(b * H + hb)) * SEQ + s_) * DKH + db] = r1 * scale;
            }
        }
    }
}

// ---------------------------------------------------------------------------
// Flash attention, fp32 (f32x2 inner products).
// One block = 128 query rows of one (b,h); KV tiled 64 at a time.
// 256 threads as 16x16: thread owns 8 q-rows (ty*8..) x 4 keys (tx*4..)
// for S, and 8 q-rows x 4 dk-cols for O.
// Smem (96KB dynamic): Qt[64][128] d-major, Kt[64][64] d-major,
//                      Vs[64][64] key-major, Ps[128][64].
// Q is pre-scaled by 1/sqrt(dk) at projection time.
// ---------------------------------------------------------------------------
__global__ void __launch_bounds__(256, 2)
flash_attn(const float* __restrict__ Q, const float* __restrict__ K,
           const float* __restrict__ V, float* __restrict__ ctx)
{
    extern __shared__ float sm[];
    float* Qt = sm;                 // [64][128]
    float* Kt = sm + 64 * 128;      // [64][64]
    float* Vs = Kt + 64 * 64;       // [64][64]
    float* Ps = Vs + 64 * 64;       // [128][64]

    const int tid = threadIdx.x;
    const int tx  = tid & 15;
    const int ty  = tid >> 4;
    const int bh  = blockIdx.y;
    const int q0  = blockIdx.x * 128;

    const float* Qb = Q + (size_t)bh * SEQ * DKH;
    const float* Kb = K + (size_t)bh * SEQ * DKH;
    const float* Vb = V + (size_t)bh * SEQ * DKH;

    // Load Q tile (128 x 64) transposed into Qt[d][row]
    #pragma unroll
    for (int rep = 0; rep < 8; rep++) {
        const int idx = tid + rep * 256;
        const int row = idx >> 4;
        const int d4  = (idx & 15) << 2;
        float4 v = *(const float4*)(Qb + (size_t)(q0 + row) * DKH + d4);
        Qt[(d4 + 0) * 128 + row] = v.x;
        Qt[(d4 + 1) * 128 + row] = v.y;
        Qt[(d4 + 2) * 128 + row] = v.z;
        Qt[(d4 + 3) * 128 + row] = v.w;
    }

    ull o2[8][2];
    float mrow[8], lrow[8];
    #pragma unroll
    for (int i = 0; i < 8; i++) {
        o2[i][0] = 0ULL; o2[i][1] = 0ULL;
        mrow[i] = -1e30f; lrow[i] = 0.f;
    }

    for (int kt = 0; kt < SEQ / 64; kt++) {
        const int c0 = kt * 64;
        __syncthreads();   // prev PV readers of Vs/Ps done before overwrite
        #pragma unroll
        for (int rep = 0; rep < 4; rep++) {
            const int idx = tid + rep * 256;
            const int row = idx >> 4;
            const int d4  = (idx & 15) << 2;
            float4 kv = *(const float4*)(Kb + (size_t)(c0 + row) * DKH + d4);
            Kt[(d4 + 0) * 64 + row] = kv.x;
            Kt[(d4 + 1) * 64 + row] = kv.y;
            Kt[(d4 + 2) * 64 + row] = kv.z;
            Kt[(d4 + 3) * 64 + row] = kv.w;
            float4 vv = *(const float4*)(Vb + (size_t)(c0 + row) * DKH + d4);
            *(float4*)&Vs[row * 64 + d4] = vv;
        }
        __syncthreads();

        // S tile: 128x64, this thread's 8x4 (as 8x2 f32x2 pairs)
        ull s2[8][2];
        #pragma unroll
        for (int i = 0; i < 8; i++) { s2[i][0] = 0ULL; s2[i][1] = 0ULL; }

        #pragma unroll 4
        for (int kk = 0; kk < 64; kk++) {
            float qr[8];
            *(float4*)&qr[0] = *(const float4*)&Qt[kk * 128 + ty * 8];
            *(float4*)&qr[4] = *(const float4*)&Qt[kk * 128 + ty * 8 + 4];
            float4 kv4 = *(const float4*)&Kt[kk * 64 + tx * 4];
            const ull kp0 = pk(kv4.x, kv4.y);
            const ull kp1 = pk(kv4.z, kv4.w);
            #pragma unroll
            for (int i = 0; i < 8; i++) {
                const ull ad = pk(qr[i], qr[i]);
                fma2(s2[i][0], ad, kp0);
                fma2(s2[i][1], ad, kp1);
            }
        }

        // Online softmax (row stats across the 16 tx lanes, shfl width 16)
        #pragma unroll
        for (int i = 0; i < 8; i++) {
            float p0, p1, p2, p3;
            upk(s2[i][0], p0, p1);
            upk(s2[i][1], p2, p3);
            float tm = fmaxf(fmaxf(p0, p1), fmaxf(p2, p3));
            #pragma unroll
            for (int off = 8; off > 0; off >>= 1)
                tm = fmaxf(tm, __shfl_xor_sync(0xffffffffu, tm, off, 16));
            const float mn = fmaxf(mrow[i], tm);
            const float alpha = __expf(mrow[i] - mn);
            mrow[i] = mn;
            p0 = __expf(p0 - mn); p1 = __expf(p1 - mn);
            p2 = __expf(p2 - mn); p3 = __expf(p3 - mn);
            float rs = (p0 + p1) + (p2 + p3);
            #pragma unroll
            for (int off = 8; off > 0; off >>= 1)
                rs += __shfl_xor_sync(0xffffffffu, rs, off, 16);
            lrow[i] = lrow[i] * alpha + rs;
            const ull al2 = pk(alpha, alpha);
            mul2(o2[i][0], al2);
            mul2(o2[i][1], al2);
            *(float4*)&Ps[(ty * 8 + i) * 64 + tx * 4] = make_float4(p0, p1, p2, p3);
        }
        __syncthreads();

        // O += P @ V   (8 rows x 4 dk-cols, pairs along dk)
        #pragma unroll 2
        for (int cc0 = 0; cc0 < 64; cc0 += 4) {
            ull vpA[4], vpB[4];
            #pragma unroll
            for (int c = 0; c < 4; c++) {
                float4 vr = *(const float4*)&Vs[(cc0 + c) * 64 + tx * 4];
                vpA[c] = pk(vr.x, vr.y);
                vpB[c] = pk(vr.z, vr.w);
            }
            #pragma unroll
            for (int i = 0; i < 8; i++) {
                float4 pr = *(const float4*)&Ps[(ty * 8 + i) * 64 + cc0];
                ull pd;
                pd = pk(pr.x, pr.x); fma2(o2[i][0], pd, vpA[0]); fma2(o2[i][1], pd, vpB[0]);
                pd = pk(pr.y, pr.y); fma2(o2[i][0], pd, vpA[1]); fma2(o2[i][1], pd, vpB[1]);
                pd = pk(pr.z, pr.z); fma2(o2[i][0], pd, vpA[2]); fma2(o2[i][1], pd, vpB[2]);
                pd = pk(pr.w, pr.w); fma2(o2[i][0], pd, vpA[3]); fma2(o2[i][1], pd, vpB[3]);
            }
        }
    }

    // Epilogue: normalize and write ctx in [B,S,D] layout
    const int b = bh >> 4;
    const int h = bh & 15;
    #pragma unroll
    for (int i = 0; i < 8; i++) {
        const float inv = 1.0f / lrow[i];
        float a, bb, c, d;
        upk(o2[i][0], a, bb);
        upk(o2[i][1], c, d);
        float4 outv = make_float4(a * inv, bb * inv, c * inv, d * inv);
        const size_t off = ((size_t)b * SEQ + q0 + ty * 8 + i) * D_MODEL
                         + h * 64 + tx * 4;
        *(float4*)(ctx + off) = outv;
    }
}

// ---------------------------------------------------------------------------
extern "C" void kernel_launch(void* const* d_in, const int* in_sizes, int n_in,
                              void* d_out, int out_size)
{
    const float* x  = (const float*)d_in[0];
    const float* Wq = (const float*)d_in[1];
    const float* bq = (const float*)d_in[2];
    const float* Wk = (const float*)d_in[3];
    const float* bk = (const float*)d_in[4];
    const float* Wv = (const float*)d_in[5];
    const float* bv = (const float*)d_in[6];
    const float* Wo = (const float*)d_in[7];
    const float* bo = (const float*)d_in[8];
    float* out = (float*)d_out;

    float *gq, *gk, *gv, *gctx;
    cudaGetSymbolAddress((void**)&gq,   g_q);
    cudaGetSymbolAddress((void**)&gk,   g_k);
    cudaGetSymbolAddress((void**)&gv,   g_v);
    cudaGetSymbolAddress((void**)&gctx, g_ctx);

    const dim3 gproj(D_MODEL / 128, MROWS / 128);   // (8, 64)
    const float qscale = 0.125f;                     // 1/sqrt(64)

    gemm_nt<1><<<gproj, 256>>>(x, Wq, bq, gq, MROWS, D_MODEL, D_MODEL, qscale);
    gemm_nt<1><<<gproj, 256>>>(x, Wk, bk, gk, MROWS, D_MODEL, D_MODEL, 1.0f);
    gemm_nt<1><<<gproj, 256>>>(x, Wv, bv, gv, MROWS, D_MODEL, D_MODEL, 1.0f);

    const int smem = (64 * 128 + 64 * 64 + 64 * 64 + 128 * 64) * (int)sizeof(float); // 96KB
    cudaFuncSetAttribute(flash_attn, cudaFuncAttributeMaxDynamicSharedMemorySize, smem);
    flash_attn<<<dim3(SEQ / 128, BATCH * H), 256, smem>>>(gq, gk, gv, gctx);

    gemm_nt<0><<<gproj, 256>>>(gctx, Wo, bo, out, MROWS, D_MODEL, D_MODEL, 1.0f);
}

// round 6
// speedup vs baseline: 1.5849x; 1.3370x over previous
#include <cuda_runtime.h>
#include <cuda_bf16.h>
#include <cstdint>

// ---------------------------------------------------------------------------
// MultiHeadAttention: x[B,S,D] -> out[B,S,D]
// B=4, S=2048, D=1024, H=16, dk=64
//   0) split fp32 -> bf16 (hi, lo) for x and the 4 weight matrices
//   1) gemm_mma<1> x3 : Q/K/V = (x @ W^T + b) -> [B,H,S,dk]  (HMMA bf16-split)
//   2) flash_attn     : ctx = softmax(Q K^T) V   (fp32 SIMT, f32x2)
//   3) split ctx -> bf16 hi/lo
//   4) gemm_mma<0>    : out = ctx @ Wo^T + bo
// A*B ~= Ahi*Bhi + Ahi*Blo + Alo*Bhi  (fp32 accum)  -> ~1e-5 rel err
// NOTE: compile target is plain sm_100 (no 'a'): tcgen05 unavailable,
// mma.sync + ldmatrix are the tensor-core path.
// ---------------------------------------------------------------------------

constexpr int D_MODEL = 1024;
constexpr int H       = 16;
constexpr int DKH     = 64;
constexpr int SEQ     = 2048;
constexpr int BATCH   = 4;
constexpr int MROWS   = BATCH * SEQ;      // 8192

__device__ float g_q[BATCH * H * SEQ * DKH];
__device__ float g_k[BATCH * H * SEQ * DKH];
__device__ float g_v[BATCH * H * SEQ * DKH];
__device__ float g_ctx[BATCH * SEQ * D_MODEL];

__device__ __nv_bfloat16 g_xhi[MROWS * D_MODEL];
__device__ __nv_bfloat16 g_xlo[MROWS * D_MODEL];
__device__ __nv_bfloat16 g_whi[4][D_MODEL * D_MODEL];
__device__ __nv_bfloat16 g_wlo[4][D_MODEL * D_MODEL];
__device__ __nv_bfloat16 g_chi[MROWS * D_MODEL];
__device__ __nv_bfloat16 g_clo[MROWS * D_MODEL];

typedef unsigned long long ull;

// ---------------- f32x2 helpers (flash) ----------------
__device__ __forceinline__ ull pk(float lo, float hi) {
    ull r; asm("mov.b64 %0, {%1, %2};" : "=l"(r) : "f"(lo), "f"(hi)); return r;
}
__device__ __forceinline__ void upk(ull v, float& lo, float& hi) {
    asm("mov.b64 {%0, %1}, %2;" : "=f"(lo), "=f"(hi) : "l"(v));
}
__device__ __forceinline__ void fma2(ull& d, ull a, ull b) {
    asm("fma.rn.f32x2 %0, %1, %2, %0;" : "+l"(d) : "l"(a), "l"(b));
}
__device__ __forceinline__ void mul2(ull& d, ull a) {
    asm("mul.rn.f32x2 %0, %0, %1;" : "+l"(d) : "l"(a));
}

// ---------------- mma.sync helpers ----------------
__device__ __forceinline__ uint32_t smem_u32(const void* p) {
    uint32_t a;
    asm("{ .reg .u64 t; cvta.to.shared.u64 t, %1; cvt.u32.u64 %0, t; }"
        : "=r"(a) : "l"(p));
    return a;
}
__device__ __forceinline__ void ldsm4(uint32_t* r, uint32_t addr) {
    asm volatile("ldmatrix.sync.aligned.m8n8.x4.shared.b16 {%0,%1,%2,%3}, [%4];"
        : "=r"(r[0]), "=r"(r[1]), "=r"(r[2]), "=r"(r[3]) : "r"(addr));
}
__device__ __forceinline__ void mma16816(float* c, const uint32_t* a,
                                         const uint32_t* b) {
    asm volatile(
        "mma.sync.aligned.m16n8k16.row.col.f32.bf16.bf16.f32 "
        "{%0,%1,%2,%3}, {%4,%5,%6,%7}, {%8,%9}, {%0,%1,%2,%3};"
        : "+f"(c[0]), "+f"(c[1]), "+f"(c[2]), "+f"(c[3])
        : "r"(a[0]), "r"(a[1]), "r"(a[2]), "r"(a[3]), "r"(b[0]), "r"(b[1]));
}

// ---------------------------------------------------------------------------
// split fp32 -> (bf16 hi, bf16 lo), vectorized by 4
// ---------------------------------------------------------------------------
__global__ void __launch_bounds__(256)
split_bf16(const float4* __restrict__ src, uint2* __restrict__ hi,
           uint2* __restrict__ lo, int n4)
{
    const int i = blockIdx.x * 256 + threadIdx.x;
    if (i >= n4) return;
    float4 v = src[i];
    __nv_bfloat16 h0 = __float2bfloat16_rn(v.x);
    __nv_bfloat16 h1 = __float2bfloat16_rn(v.y);
    __nv_bfloat16 h2 = __float2bfloat16_rn(v.z);
    __nv_bfloat16 h3 = __float2bfloat16_rn(v.w);
    __nv_bfloat16 l0 = __float2bfloat16_rn(v.x - __bfloat162float(h0));
    __nv_bfloat16 l1 = __float2bfloat16_rn(v.y - __bfloat162float(h1));
    __nv_bfloat16 l2 = __float2bfloat16_rn(v.z - __bfloat162float(h2));
    __nv_bfloat16 l3 = __float2bfloat16_rn(v.w - __bfloat162float(h3));
    uint2 hw, lw;
    hw.x = (uint32_t)__bfloat16_as_ushort(h0) | ((uint32_t)__bfloat16_as_ushort(h1) << 16);
    hw.y = (uint32_t)__bfloat16_as_ushort(h2) | ((uint32_t)__bfloat16_as_ushort(h3) << 16);
    lw.x = (uint32_t)__bfloat16_as_ushort(l0) | ((uint32_t)__bfloat16_as_ushort(l1) << 16);
    lw.y = (uint32_t)__bfloat16_as_ushort(l2) | ((uint32_t)__bfloat16_as_ushort(l3) << 16);
    hi[i] = hw;
    lo[i] = lw;
}

// ---------------------------------------------------------------------------
// HMMA GEMM: C[8192, 1024] = A @ B^T + bias  (A,B as bf16 hi/lo; fp32 accum)
// CTA tile 128x128, 8 warps (2m x 4n -> 64x32 per warp), BK=32.
// Smem: 4 tiles of [128][40] bf16 (80B padded rows, ldmatrix conflict-free).
// Register prefetch of the next K-chunk overlaps LDG with HMMA.
// MODE 0: row-major out.  MODE 1: scatter [B,H,S,dk], *scale.
// ---------------------------------------------------------------------------
constexpr int TSTR = 80;   // bytes per smem tile row (40 bf16)

template <int MODE>
__global__ void __launch_bounds__(256, 1)
gemm_mma(const __nv_bfloat16* __restrict__ Ahi, const __nv_bfloat16* __restrict__ Alo,
         const __nv_bfloat16* __restrict__ Bhi, const __nv_bfloat16* __restrict__ Blo,
         const float* __restrict__ bias, float* __restrict__ C, float scale)
{
    __shared__ __align__(16) char smc[4 * 128 * TSTR];   // 40 KB

    const int tid  = threadIdx.x;
    const int wid  = tid >> 5;
    const int lane = tid & 31;
    const int wm   = wid >> 2;          // 0..1
    const int wn   = wid & 3;           // 0..3
    const int m0   = blockIdx.y * 128;
    const int n0   = blockIdx.x * 128;

    const int lrow  = tid >> 1;         // 0..127
    const int lhalf = tid & 1;          // half-row (16 bf16)

    const __nv_bfloat16* gsrc[4] = {
        Ahi + (size_t)(m0 + lrow) * D_MODEL + lhalf * 16,
        Alo + (size_t)(m0 + lrow) * D_MODEL + lhalf * 16,
        Bhi + (size_t)(n0 + lrow) * D_MODEL + lhalf * 16,
        Blo + (size_t)(n0 + lrow) * D_MODEL + lhalf * 16,
    };
    char* stile[4] = { smc, smc + 128 * TSTR, smc + 2 * 128 * TSTR,
                       smc + 3 * 128 * TSTR };
    const uint32_t sbase = smem_u32(smc);

    // ldmatrix lane-address components
    const int lA_row = lane & 15;
    const int lA_kb  = (lane >> 4) * 16;
    const int lB_row = (lane & 7) + ((lane >> 4) << 3);
    const int lB_kb  = ((lane >> 3) & 1) * 16;

    float acc[4][4][4];
    #pragma unroll
    for (int mi = 0; mi < 4; mi++)
        #pragma unroll
        for (int nf = 0; nf < 4; nf++)
            #pragma unroll
            for (int r = 0; r < 4; r++) acc[mi][nf][r] = 0.f;

    uint4 v[4][2];
    #pragma unroll
    for (int t = 0; t < 4; t++) {
        v[t][0] = *(const uint4*)(gsrc[t]);
        v[t][1] = *(const uint4*)(gsrc[t] + 8);
    }

    for (int c = 0; c < D_MODEL / 32; ++c) {
        __syncthreads();
        #pragma unroll
        for (int t = 0; t < 4; t++) {
            *(uint4*)(stile[t] + lrow * TSTR + lhalf * 32)      = v[t][0];
            *(uint4*)(stile[t] + lrow * TSTR + lhalf * 32 + 16) = v[t][1];
        }
        __syncthreads();
        if (c + 1 < D_MODEL / 32) {
            #pragma unroll
            for (int t = 0; t < 4; t++) {
                v[t][0] = *(const uint4*)(gsrc[t] + (c + 1) * 32);
                v[t][1] = *(const uint4*)(gsrc[t] + (c + 1) * 32 + 8);
            }
        }

        #pragma unroll
        for (int ks = 0; ks < 2; ks++) {
            const int kb = ks * 32;
            uint32_t bh[2][4], bl[2][4];
            #pragma unroll
            for (int g = 0; g < 2; g++) {
                const uint32_t brel = (wn * 32 + g * 16 + lB_row) * TSTR + kb + lB_kb;
                ldsm4(bh[g], sbase + 2 * 128 * TSTR + brel);
                ldsm4(bl[g], sbase + 3 * 128 * TSTR + brel);
            }
            #pragma unroll
            for (int mi = 0; mi < 4; mi++) {
                uint32_t ah[4], al[4];
                const uint32_t arel = (wm * 64 + mi * 16 + lA_row) * TSTR + kb + lA_kb;
                ldsm4(ah, sbase + arel);
                ldsm4(al, sbase + 128 * TSTR + arel);
                #pragma unroll
                for (int nf = 0; nf < 4; nf++) {
                    const uint32_t* bhf = &bh[nf >> 1][(nf & 1) * 2];
                    const uint32_t* blf = &bl[nf >> 1][(nf & 1) * 2];
                    mma16816(acc[mi][nf], ah, bhf);
                    mma16816(acc[mi][nf], ah, blf);
                    mma16816(acc[mi][nf], al, bhf);
                }
            }
        }
    }

    // Epilogue: fragment rows (lane/4, +8), cols (lane%4)*2, +1
    #pragma unroll
    for (int mi = 0; mi < 4; mi++) {
        const int r0 = m0 + wm * 64 + mi * 16 + (lane >> 2);
        #pragma unroll
        for (int nf = 0; nf < 4; nf++) {
            const int n = n0 + wn * 32 + nf * 8 + (lane & 3) * 2;
            const float b0 = __ldg(bias + n);
            const float b1 = __ldg(bias + n + 1);
            float2 lo2, hi2;
            lo2.x = (acc[mi][nf][0] + b0) * scale;
            lo2.y = (acc[mi][nf][1] + b1) * scale;
            hi2.x = (acc[mi][nf][2] + b0) * scale;
            hi2.y = (acc[mi][nf][3] + b1) * scale;
            if (MODE == 0) {
                *(float2*)(C + (size_t)r0 * D_MODEL + n)       = lo2;
                *(float2*)(C + (size_t)(r0 + 8) * D_MODEL + n) = hi2;
            } else {
                const int h = n >> 6, d = n & 63;
                const int b  = r0 >> 11;
                const int s0 = r0 & (SEQ - 1);
                const size_t base = ((size_t)(b * H + h)) * SEQ;
                *(float2*)(C + (base + s0) * DKH + d)     = lo2;
                *(float2*)(C + (base + s0 + 8) * DKH + d) = hi2;
            }
        }
    }
}

// ---------------------------------------------------------------------------
// Flash attention, fp32 (f32x2) — unchanged from the passing R3 version.
// ---------------------------------------------------------------------------
__global__ void __launch_bounds__(256, 2)
flash_attn(const float* __restrict__ Q, const float* __restrict__ K,
           const float* __restrict__ V, float* __restrict__ ctx)
{
    extern __shared__ float sm[];
    float* Qt = sm;                 // [64][128]
    float* Kt = sm + 64 * 128;      // [64][64]
    float* Vs = Kt + 64 * 64;       // [64][64]
    float* Ps = Vs + 64 * 64;       // [128][64]

    const int tid = threadIdx.x;
    const int tx  = tid & 15;
    const int ty  = tid >> 4;
    const int bh  = blockIdx.y;
    const int q0  = blockIdx.x * 128;

    const float* Qb = Q + (size_t)bh * SEQ * DKH;
    const float* Kb = K + (size_t)bh * SEQ * DKH;
    const float* Vb = V + (size_t)bh * SEQ * DKH;

    #pragma unroll
    for (int rep = 0; rep < 8; rep++) {
        const int idx = tid + rep * 256;
        const int row = idx >> 4;
        const int d4  = (idx & 15) << 2;
        float4 v = *(const float4*)(Qb + (size_t)(q0 + row) * DKH + d4);
        Qt[(d4 + 0) * 128 + row] = v.x;
        Qt[(d4 + 1) * 128 + row] = v.y;
        Qt[(d4 + 2) * 128 + row] = v.z;
        Qt[(d4 + 3) * 128 + row] = v.w;
    }

    ull o2[8][2];
    float mrow[8], lrow[8];
    #pragma unroll
    for (int i = 0; i < 8; i++) {
        o2[i][0] = 0ULL; o2[i][1] = 0ULL;
        mrow[i] = -1e30f; lrow[i] = 0.f;
    }

    for (int kt = 0; kt < SEQ / 64; kt++) {
        const int c0 = kt * 64;
        __syncthreads();
        #pragma unroll
        for (int rep = 0; rep < 4; rep++) {
            const int idx = tid + rep * 256;
            const int row = idx >> 4;
            const int d4  = (idx & 15) << 2;
            float4 kv = *(const float4*)(Kb + (size_t)(c0 + row) * DKH + d4);
            Kt[(d4 + 0) * 64 + row] = kv.x;
            Kt[(d4 + 1) * 64 + row] = kv.y;
            Kt[(d4 + 2) * 64 + row] = kv.z;
            Kt[(d4 + 3) * 64 + row] = kv.w;
            float4 vv = *(const float4*)(Vb + (size_t)(c0 + row) * DKH + d4);
            *(float4*)&Vs[row * 64 + d4] = vv;
        }
        __syncthreads();

        ull s2[8][2];
        #pragma unroll
        for (int i = 0; i < 8; i++) { s2[i][0] = 0ULL; s2[i][1] = 0ULL; }

        #pragma unroll 4
        for (int kk = 0; kk < 64; kk++) {
            float qr[8];
            *(float4*)&qr[0] = *(const float4*)&Qt[kk * 128 + ty * 8];
            *(float4*)&qr[4] = *(const float4*)&Qt[kk * 128 + ty * 8 + 4];
            float4 kv4 = *(const float4*)&Kt[kk * 64 + tx * 4];
            const ull kp0 = pk(kv4.x, kv4.y);
            const ull kp1 = pk(kv4.z, kv4.w);
            #pragma unroll
            for (int i = 0; i < 8; i++) {
                const ull ad = pk(qr[i], qr[i]);
                fma2(s2[i][0], ad, kp0);
                fma2(s2[i][1], ad, kp1);
            }
        }

        #pragma unroll
        for (int i = 0; i < 8; i++) {
            float p0, p1, p2, p3;
            upk(s2[i][0], p0, p1);
            upk(s2[i][1], p2, p3);
            float tm = fmaxf(fmaxf(p0, p1), fmaxf(p2, p3));
            #pragma unroll
            for (int off = 8; off > 0; off >>= 1)
                tm = fmaxf(tm, __shfl_xor_sync(0xffffffffu, tm, off, 16));
            const float mn = fmaxf(mrow[i], tm);
            const float alpha = __expf(mrow[i] - mn);
            mrow[i] = mn;
            p0 = __expf(p0 - mn); p1 = __expf(p1 - mn);
            p2 = __expf(p2 - mn); p3 = __expf(p3 - mn);
            float rs = (p0 + p1) + (p2 + p3);
            #pragma unroll
            for (int off = 8; off > 0; off >>= 1)
                rs += __shfl_xor_sync(0xffffffffu, rs, off, 16);
            lrow[i] = lrow[i] * alpha + rs;
            const ull al2 = pk(alpha, alpha);
            mul2(o2[i][0], al2);
            mul2(o2[i][1], al2);
            *(float4*)&Ps[(ty * 8 + i) * 64 + tx * 4] = make_float4(p0, p1, p2, p3);
        }
        __syncthreads();

        #pragma unroll 2
        for (int cc0 = 0; cc0 < 64; cc0 += 4) {
            ull vpA[4], vpB[4];
            #pragma unroll
            for (int c = 0; c < 4; c++) {
                float4 vr = *(const float4*)&Vs[(cc0 + c) * 64 + tx * 4];
                vpA[c] = pk(vr.x, vr.y);
                vpB[c] = pk(vr.z, vr.w);
            }
            #pragma unroll
            for (int i = 0; i < 8; i++) {
                float4 pr = *(const float4*)&Ps[(ty * 8 + i) * 64 + cc0];
                ull pd;
                pd = pk(pr.x, pr.x); fma2(o2[i][0], pd, vpA[0]); fma2(o2[i][1], pd, vpB[0]);
                pd = pk(pr.y, pr.y); fma2(o2[i][0], pd, vpA[1]); fma2(o2[i][1], pd, vpB[1]);
                pd = pk(pr.z, pr.z); fma2(o2[i][0], pd, vpA[2]); fma2(o2[i][1], pd, vpB[2]);
                pd = pk(pr.w, pr.w); fma2(o2[i][0], pd, vpA[3]); fma2(o2[i][1], pd, vpB[3]);
            }
        }
    }

    const int b = bh >> 4;
    const int h = bh & 15;
    #pragma unroll
    for (int i = 0; i < 8; i++) {
        const float inv = 1.0f / lrow[i];
        float a, bb, c, d;
        upk(o2[i][0], a, bb);
        upk(o2[i][1], c, d);
        float4 outv = make_float4(a * inv, bb * inv, c * inv, d * inv);
        const size_t off = ((size_t)b * SEQ + q0 + ty * 8 + i) * D_MODEL
                         + h * 64 + tx * 4;
        *(float4*)(ctx + off) = outv;
    }
}

// ---------------------------------------------------------------------------
extern "C" void kernel_launch(void* const* d_in, const int* in_sizes, int n_in,
                              void* d_out, int out_size)
{
    const float* x  = (const float*)d_in[0];
    const float* Wq = (const float*)d_in[1];
    const float* bq = (const float*)d_in[2];
    const float* Wk = (const float*)d_in[3];
    const float* bk = (const float*)d_in[4];
    const float* Wv = (const float*)d_in[5];
    const float* bv = (const float*)d_in[6];
    const float* Wo = (const float*)d_in[7];
    const float* bo = (const float*)d_in[8];
    float* out = (float*)d_out;

    float *gq, *gk, *gv, *gctx;
    cudaGetSymbolAddress((void**)&gq,   g_q);
    cudaGetSymbolAddress((void**)&gk,   g_k);
    cudaGetSymbolAddress((void**)&gv,   g_v);
    cudaGetSymbolAddress((void**)&gctx, g_ctx);
    __nv_bfloat16 *xhi, *xlo, *whi, *wlo, *chi, *clo;
    cudaGetSymbolAddress((void**)&xhi, g_xhi);
    cudaGetSymbolAddress((void**)&xlo, g_xlo);
    cudaGetSymbolAddress((void**)&whi, g_whi);
    cudaGetSymbolAddress((void**)&wlo, g_wlo);
    cudaGetSymbolAddress((void**)&chi, g_chi);
    cudaGetSymbolAddress((void**)&clo, g_clo);

    const int WSZ = D_MODEL * D_MODEL;           // 1M elems per weight
    const int xn4 = MROWS * D_MODEL / 4;         // 2M float4
    const int wn4 = WSZ / 4;                     // 256K float4

    split_bf16<<<(xn4 + 255) / 256, 256>>>((const float4*)x,
        (uint2*)xhi, (uint2*)xlo, xn4);
    const float* Ws[4] = {Wq, Wk, Wv, Wo};
    for (int w = 0; w < 4; ++w)
        split_bf16<<<(wn4 + 255) / 256, 256>>>((const float4*)Ws[w],
            (uint2*)(whi + (size_t)w * WSZ), (uint2*)(wlo + (size_t)w * WSZ), wn4);

    const dim3 gg(D_MODEL / 128, MROWS / 128);   // (8, 64)
    const float qscale = 0.125f;                 // 1/sqrt(64)

    gemm_mma<1><<<gg, 256>>>(xhi, xlo, whi + 0 * (size_t)WSZ, wlo + 0 * (size_t)WSZ, bq, gq, qscale);
    gemm_mma<1><<<gg, 256>>>(xhi, xlo, whi + 1 * (size_t)WSZ, wlo + 1 * (size_t)WSZ, bk, gk, 1.0f);
    gemm_mma<1><<<gg, 256>>>(xhi, xlo, whi + 2 * (size_t)WSZ, wlo + 2 * (size_t)WSZ, bv, gv, 1.0f);

    const int fsmem = (64 * 128 + 64 * 64 + 64 * 64 + 128 * 64) * (int)sizeof(float); // 96KB
    cudaFuncSetAttribute(flash_attn, cudaFuncAttributeMaxDynamicSharedMemorySize, fsmem);
    flash_attn<<<dim3(SEQ / 128, BATCH * H), 256, fsmem>>>(gq, gk, gv, gctx);

    split_bf16<<<(xn4 + 255) / 256, 256>>>((const float4*)gctx,
        (uint2*)chi, (uint2*)clo, xn4);
    gemm_mma<0><<<gg, 256>>>(chi, clo, whi + 3 * (size_t)WSZ, wlo + 3 * (size_t)WSZ, bo, out, 1.0f);
}

// round 8
// speedup vs baseline: 2.5979x; 1.6391x over previous
#include <cuda_runtime.h>
#include <cuda_bf16.h>
#include <cstdint>

// ---------------------------------------------------------------------------
// MultiHeadAttention: x[B,S,D] -> out[B,S,D]
// B=4, S=2048, D=1024, H=16, dk=64
//   0) split fp32 -> bf16 (hi, lo): x, 4 weights
//   1) gemm_proj x3 : Q/K -> bf16 hi/lo [b,h,s,dk] (Q scaled 1/8),
//                     V   -> bf16 hi/lo [b,h,dk,s] (transposed)
//   2) flash_mma    : full tensor-core flash attention (mma.sync bf16-split),
//                     writes ctx as bf16 hi/lo [b,s,D]
//   3) gemm_out     : out = ctx @ Wo^T + bo  (fp32 out)
// Everywhere: A*B ~= Ahi*Bhi + Ahi*Blo + Alo*Bhi (fp32 accum) -> ~1e-5 rel err
// Target is plain sm_100: mma.sync + ldmatrix (no tcgen05).
// ---------------------------------------------------------------------------

constexpr int D_MODEL = 1024;
constexpr int H       = 16;
constexpr int DKH     = 64;
constexpr int SEQ     = 2048;
constexpr int BATCH   = 4;
constexpr int MROWS   = BATCH * SEQ;      // 8192

__device__ __nv_bfloat16 g_xhi[MROWS * D_MODEL];
__device__ __nv_bfloat16 g_xlo[MROWS * D_MODEL];
__device__ __nv_bfloat16 g_whi[4][D_MODEL * D_MODEL];
__device__ __nv_bfloat16 g_wlo[4][D_MODEL * D_MODEL];
__device__ __nv_bfloat16 g_qhi[BATCH * H * SEQ * DKH];
__device__ __nv_bfloat16 g_qlo[BATCH * H * SEQ * DKH];
__device__ __nv_bfloat16 g_khi[BATCH * H * SEQ * DKH];
__device__ __nv_bfloat16 g_klo[BATCH * H * SEQ * DKH];
__device__ __nv_bfloat16 g_vhi[BATCH * H * DKH * SEQ];   // transposed
__device__ __nv_bfloat16 g_vlo[BATCH * H * DKH * SEQ];
__device__ __nv_bfloat16 g_chi[MROWS * D_MODEL];
__device__ __nv_bfloat16 g_clo[MROWS * D_MODEL];

typedef unsigned long long ull;

// ---------------- helpers ----------------
__device__ __forceinline__ uint32_t smem_u32(const void* p) {
    uint32_t a;
    asm("{ .reg .u64 t; cvta.to.shared.u64 t, %1; cvt.u32.u64 %0, t; }"
        : "=r"(a) : "l"(p));
    return a;
}
__device__ __forceinline__ void ldsm4(uint32_t* r, uint32_t addr) {
    asm volatile("ldmatrix.sync.aligned.m8n8.x4.shared.b16 {%0,%1,%2,%3}, [%4];"
        : "=r"(r[0]), "=r"(r[1]), "=r"(r[2]), "=r"(r[3]) : "r"(addr));
}
__device__ __forceinline__ void mma16816(float* c, const uint32_t* a,
                                         const uint32_t* b) {
    asm volatile(
        "mma.sync.aligned.m16n8k16.row.col.f32.bf16.bf16.f32 "
        "{%0,%1,%2,%3}, {%4,%5,%6,%7}, {%8,%9}, {%0,%1,%2,%3};"
        : "+f"(c[0]), "+f"(c[1]), "+f"(c[2]), "+f"(c[3])
        : "r"(a[0]), "r"(a[1]), "r"(a[2]), "r"(a[3]), "r"(b[0]), "r"(b[1]));
}
__device__ __forceinline__ void split1(float v, __nv_bfloat16& h, __nv_bfloat16& l) {
    h = __float2bfloat16_rn(v);
    l = __float2bfloat16_rn(v - __bfloat162float(h));
}
// pack two (k-even, k-odd) floats -> bf16x2 hi reg and lo reg
__device__ __forceinline__ void pack_split(float e, float o, uint32_t& hr, uint32_t& lr) {
    __nv_bfloat16 he, le, ho, lo;
    split1(e, he, le);
    split1(o, ho, lo);
    hr = (uint32_t)__bfloat16_as_ushort(he) | ((uint32_t)__bfloat16_as_ushort(ho) << 16);
    lr = (uint32_t)__bfloat16_as_ushort(le) | ((uint32_t)__bfloat16_as_ushort(lo) << 16);
}

// ---------------------------------------------------------------------------
// split fp32 -> (bf16 hi, bf16 lo), vectorized by 4
// ---------------------------------------------------------------------------
__global__ void __launch_bounds__(256)
split_bf16(const float4* __restrict__ src, uint2* __restrict__ hi,
           uint2* __restrict__ lo, int n4)
{
    const int i = blockIdx.x * 256 + threadIdx.x;
    if (i >= n4) return;
    float4 v = src[i];
    __nv_bfloat16 h0, l0, h1, l1, h2, l2, h3, l3;
    split1(v.x, h0, l0); split1(v.y, h1, l1);
    split1(v.z, h2, l2); split1(v.w, h3, l3);
    uint2 hw, lw;
    hw.x = (uint32_t)__bfloat16_as_ushort(h0) | ((uint32_t)__bfloat16_as_ushort(h1) << 16);
    hw.y = (uint32_t)__bfloat16_as_ushort(h2) | ((uint32_t)__bfloat16_as_ushort(h3) << 16);
    lw.x = (uint32_t)__bfloat16_as_ushort(l0) | ((uint32_t)__bfloat16_as_ushort(l1) << 16);
    lw.y = (uint32_t)__bfloat16_as_ushort(l2) | ((uint32_t)__bfloat16_as_ushort(l3) << 16);
    hi[i] = hw;
    lo[i] = lw;
}

// ---------------------------------------------------------------------------
// HMMA GEMM core (128x128 CTA tile, 8 warps 2m x 4n, BK=32, bf16-split 3-term)
// TSTR=80B padded smem rows (ldmatrix conflict-free). Two epilogue flavors:
//  gemm_out : fp32 row-major [M][1024] + bias
//  gemm_proj<L>: bf16 hi/lo out; L=1 -> [b,h,s,dk] (*scale), L=2 -> [b,h,dk,s]
// ---------------------------------------------------------------------------
constexpr int TSTR = 80;

#define GEMM_MAIN_BODY                                                          \
    __shared__ __align__(16) char smc[4 * 128 * TSTR];                          \
    const int tid  = threadIdx.x;                                               \
    const int wid  = tid >> 5;                                                  \
    const int lane = tid & 31;                                                  \
    const int wm   = wid >> 2;                                                  \
    const int wn   = wid & 3;                                                   \
    const int m0   = blockIdx.y * 128;                                          \
    const int n0   = blockIdx.x * 128;                                          \
    const int lrow  = tid >> 1;                                                 \
    const int lhalf = tid & 1;                                                  \
    const __nv_bfloat16* gsrc[4] = {                                            \
        Ahi + (size_t)(m0 + lrow) * D_MODEL + lhalf * 16,                       \
        Alo + (size_t)(m0 + lrow) * D_MODEL + lhalf * 16,                       \
        Bhi + (size_t)(n0 + lrow) * D_MODEL + lhalf * 16,                       \
        Blo + (size_t)(n0 + lrow) * D_MODEL + lhalf * 16,                       \
    };                                                                          \
    char* stile[4] = { smc, smc + 128 * TSTR, smc + 2 * 128 * TSTR,             \
                       smc + 3 * 128 * TSTR };                                  \
    const uint32_t sbase = smem_u32(smc);                                       \
    const int lA_row = lane & 15;                                               \
    const int lA_kb  = (lane >> 4) * 16;                                        \
    const int lB_row = (lane & 7) + ((lane >> 4) << 3);                         \
    const int lB_kb  = ((lane >> 3) & 1) * 16;                                  \
    float acc[4][4][4];                                                         \
    _Pragma("unroll")                                                           \
    for (int mi = 0; mi < 4; mi++)                                              \
        _Pragma("unroll")                                                       \
        for (int nf = 0; nf < 4; nf++)                                          \
            _Pragma("unroll")                                                   \
            for (int r = 0; r < 4; r++) acc[mi][nf][r] = 0.f;                   \
    uint4 v[4][2];                                                              \
    _Pragma("unroll")                                                           \
    for (int t = 0; t < 4; t++) {                                               \
        v[t][0] = *(const uint4*)(gsrc[t]);                                     \
        v[t][1] = *(const uint4*)(gsrc[t] + 8);                                 \
    }                                                                           \
    for (int c = 0; c < D_MODEL / 32; ++c) {                                    \
        __syncthreads();                                                        \
        _Pragma("unroll")                                                       \
        for (int t = 0; t < 4; t++) {                                           \
            *(uint4*)(stile[t] + lrow * TSTR + lhalf * 32)      = v[t][0];      \
            *(uint4*)(stile[t] + lrow * TSTR + lhalf * 32 + 16) = v[t][1];      \
        }                                                                       \
        __syncthreads();                                                        \
        if (c + 1 < D_MODEL / 32) {                                             \
            _Pragma("unroll")                                                   \
            for (int t = 0; t < 4; t++) {                                       \
                v[t][0] = *(const uint4*)(gsrc[t] + (c + 1) * 32);              \
                v[t][1] = *(const uint4*)(gsrc[t] + (c + 1) * 32 + 8);          \
            }                                                                   \
        }                                                                       \
        _Pragma("unroll")                                                       \
        for (int ks = 0; ks < 2; ks++) {                                        \
            const int kb = ks * 32;                                             \
            uint32_t bh[2][4], bl[2][4];                                        \
            _Pragma("unroll")                                                   \
            for (int g = 0; g < 2; g++) {                                       \
                const uint32_t brel = (wn * 32 + g * 16 + lB_row) * TSTR + kb + lB_kb; \
                ldsm4(bh[g], sbase + 2 * 128 * TSTR + brel);                    \
                ldsm4(bl[g], sbase + 3 * 128 * TSTR + brel);                    \
            }                                                                   \
            _Pragma("unroll")                                                   \
            for (int mi = 0; mi < 4; mi++) {                                    \
                uint32_t ah[4], al[4];                                          \
                const uint32_t arel = (wm * 64 + mi * 16 + lA_row) * TSTR + kb + lA_kb; \
                ldsm4(ah, sbase + arel);                                        \
                ldsm4(al, sbase + 128 * TSTR + arel);                           \
                _Pragma("unroll")                                               \
                for (int nf = 0; nf < 4; nf++) {                                \
                    const uint32_t* bhf = &bh[nf >> 1][(nf & 1) * 2];           \
                    const uint32_t* blf = &bl[nf >> 1][(nf & 1) * 2];           \
                    mma16816(acc[mi][nf], ah, bhf);                             \
                    mma16816(acc[mi][nf], ah, blf);                             \
                    mma16816(acc[mi][nf], al, bhf);                             \
                }                                                               \
            }                                                                   \
        }                                                                       \
    }

__global__ void __launch_bounds__(256, 1)
gemm_out(const __nv_bfloat16* __restrict__ Ahi, const __nv_bfloat16* __restrict__ Alo,
         const __nv_bfloat16* __restrict__ Bhi, const __nv_bfloat16* __restrict__ Blo,
         const float* __restrict__ bias, float* __restrict__ C)
{
    GEMM_MAIN_BODY
    #pragma unroll
    for (int mi = 0; mi < 4; mi++) {
        const int r0 = m0 + wm * 64 + mi * 16 + (lane >> 2);
        #pragma unroll
        for (int nf = 0; nf < 4; nf++) {
            const int n = n0 + wn * 32 + nf * 8 + (lane & 3) * 2;
            const float b0 = __ldg(bias + n);
            const float b1 = __ldg(bias + n + 1);
            float2 lo2, hi2;
            lo2.x = acc[mi][nf][0] + b0;
            lo2.y = acc[mi][nf][1] + b1;
            hi2.x = acc[mi][nf][2] + b0;
            hi2.y = acc[mi][nf][3] + b1;
            *(float2*)(C + (size_t)r0 * D_MODEL + n)       = lo2;
            *(float2*)(C + (size_t)(r0 + 8) * D_MODEL + n) = hi2;
        }
    }
}

template <int LAYOUT>   // 1: [b,h,s,dk] (*scale)   2: transposed [b,h,dk,s]
__global__ void __launch_bounds__(256, 1)
gemm_proj(const __nv_bfloat16* __restrict__ Ahi, const __nv_bfloat16* __restrict__ Alo,
          const __nv_bfloat16* __restrict__ Bhi, const __nv_bfloat16* __restrict__ Blo,
          const float* __restrict__ bias,
          __nv_bfloat16* __restrict__ Dhi, __nv_bfloat16* __restrict__ Dlo,
          float scale)
{
    GEMM_MAIN_BODY
    #pragma unroll
    for (int mi = 0; mi < 4; mi++) {
        const int r0 = m0 + wm * 64 + mi * 16 + (lane >> 2);
        const int b  = r0 >> 11;
        const int s0 = r0 & (SEQ - 1);
        #pragma unroll
        for (int nf = 0; nf < 4; nf++) {
            const int n  = n0 + wn * 32 + nf * 8 + (lane & 3) * 2;
            const float b0 = __ldg(bias + n);
            const float b1 = __ldg(bias + n + 1);
            const float v00 = (acc[mi][nf][0] + b0) * scale;
            const float v01 = (acc[mi][nf][1] + b1) * scale;
            const float v10 = (acc[mi][nf][2] + b0) * scale;
            const float v11 = (acc[mi][nf][3] + b1) * scale;
            const int hd = n >> 6, d = n & 63;
            __nv_bfloat16 h00, l00, h01, l01, h10, l10, h11, l11;
            split1(v00, h00, l00); split1(v01, h01, l01);
            split1(v10, h10, l10); split1(v11, h11, l11);
            if (LAYOUT == 1) {
                const size_t base = ((size_t)(b * H + hd) * SEQ + s0) * DKH + d;
                *(__nv_bfloat162*)(Dhi + base) = __nv_bfloat162(h00, h01);
                *(__nv_bfloat162*)(Dlo + base) = __nv_bfloat162(l00, l01);
                *(__nv_bfloat162*)(Dhi + base + 8 * DKH) = __nv_bfloat162(h10, h11);
                *(__nv_bfloat162*)(Dlo + base + 8 * DKH) = __nv_bfloat162(l10, l11);
            } else {
                const size_t base = ((size_t)(b * H + hd) * DKH + d) * SEQ + s0;
                Dhi[base]           = h00; Dlo[base]           = l00;
                Dhi[base + SEQ]     = h01; Dlo[base + SEQ]     = l01;
                Dhi[base + 8]       = h10; Dlo[base + 8]       = l10;
                Dhi[base + SEQ + 8] = h11; Dlo[base + SEQ + 8] = l11;
            }
        }
    }
}

// ---------------------------------------------------------------------------
// Tensor-core flash attention.
// CTA = 128 q-rows of one (b,h); 8 warps x m16. KV tiled 64 keys.
// Q/K bf16 hi/lo in [b,h,s,dk]; V bf16 hi/lo in [b,h,dk,s] (k-major for PV).
// S = Qhi.Khi + Qhi.Klo + Qlo.Khi; online softmax on fragments;
// P split hi/lo in-registers (FA2 C->A remap); O += Phi.Vhi + Phi.Vlo + Plo.Vhi.
// Epilogue writes ctx directly as bf16 hi/lo [b,s,D].
// ---------------------------------------------------------------------------
constexpr int FSR = 144;   // smem row stride bytes for 64-bf16 rows

__global__ void __launch_bounds__(256, 1)
flash_mma(const __nv_bfloat16* __restrict__ qhi, const __nv_bfloat16* __restrict__ qlo,
          const __nv_bfloat16* __restrict__ khi, const __nv_bfloat16* __restrict__ klo,
          const __nv_bfloat16* __restrict__ vhi, const __nv_bfloat16* __restrict__ vlo,
          __nv_bfloat16* __restrict__ chi, __nv_bfloat16* __restrict__ clo)
{
    extern __shared__ char fsm[];
    char* sQh = fsm;
    char* sQl = fsm + 128 * FSR;
    char* sKh = fsm + 2 * 128 * FSR;
    char* sKl = sKh + 64 * FSR;
    char* sVh = sKl + 64 * FSR;
    char* sVl = sVh + 64 * FSR;
    const uint32_t bQh = smem_u32(sQh);
    const uint32_t bQl = smem_u32(sQl);
    const uint32_t bKh = smem_u32(sKh);
    const uint32_t bKl = smem_u32(sKl);
    const uint32_t bVh = smem_u32(sVh);
    const uint32_t bVl = smem_u32(sVl);

    const int tid  = threadIdx.x;
    const int lane = tid & 31;
    const int w    = tid >> 5;
    const int bh   = blockIdx.y;
    const int q0   = blockIdx.x * 128;
    const size_t boff = (size_t)bh * SEQ * DKH;   // same extent for Q/K and V^T

    // ---- load Q tile (128 x 64, hi/lo): 2 threads/row, 32 elems each ----
    {
        const int row = tid >> 1, half = tid & 1;
        const __nv_bfloat16* gq = qhi + boff + (size_t)(q0 + row) * DKH + half * 32;
        const __nv_bfloat16* gl = qlo + boff + (size_t)(q0 + row) * DKH + half * 32;
        #pragma unroll
        for (int i = 0; i < 4; i++) {
            *(uint4*)(sQh + row * FSR + half * 64 + i * 16) = *(const uint4*)(gq + i * 8);
            *(uint4*)(sQl + row * FSR + half * 64 + i * 16) = *(const uint4*)(gl + i * 8);
        }
    }
    __syncthreads();

    const int lA_row = lane & 15;
    const int lA_kb  = (lane >> 4) * 16;
    const int lB_row = (lane & 7) + ((lane >> 4) << 3);
    const int lB_kb  = ((lane >> 3) & 1) * 16;

    // ---- Q A-fragments, persistent in registers ----
    uint32_t qfh[4][4], qfl[4][4];
    #pragma unroll
    for (int kc2 = 0; kc2 < 4; kc2++) {
        const uint32_t arel = (w * 16 + lA_row) * FSR + kc2 * 32 + lA_kb;
        ldsm4(qfh[kc2], bQh + arel);
        ldsm4(qfl[kc2], bQl + arel);
    }

    float o[8][4];
    #pragma unroll
    for (int nf = 0; nf < 8; nf++)
        #pragma unroll
        for (int r = 0; r < 4; r++) o[nf][r] = 0.f;
    float mrow0 = -1e30f, mrow1 = -1e30f, lrow0 = 0.f, lrow1 = 0.f;

    for (int kt = 0; kt < SEQ / 64; kt++) {
        const int c0 = kt * 64;
        __syncthreads();
        // ---- load K (64x64) and V^T (64x64) tiles, hi/lo ----
        {
            const int row = tid >> 2, q4 = tid & 3;
            const __nv_bfloat16* gk  = khi + boff + (size_t)(c0 + row) * DKH + q4 * 16;
            const __nv_bfloat16* gkl = klo + boff + (size_t)(c0 + row) * DKH + q4 * 16;
            const __nv_bfloat16* gv  = vhi + boff + (size_t)row * SEQ + c0 + q4 * 16;
            const __nv_bfloat16* gvl = vlo + boff + (size_t)row * SEQ + c0 + q4 * 16;
            *(uint4*)(sKh + row * FSR + q4 * 32)      = *(const uint4*)(gk);
            *(uint4*)(sKh + row * FSR + q4 * 32 + 16) = *(const uint4*)(gk + 8);
            *(uint4*)(sKl + row * FSR + q4 * 32)      = *(const uint4*)(gkl);
            *(uint4*)(sKl + row * FSR + q4 * 32 + 16) = *(const uint4*)(gkl + 8);
            *(uint4*)(sVh + row * FSR + q4 * 32)      = *(const uint4*)(gv);
            *(uint4*)(sVh + row * FSR + q4 * 32 + 16) = *(const uint4*)(gv + 8);
            *(uint4*)(sVl + row * FSR + q4 * 32)      = *(const uint4*)(gvl);
            *(uint4*)(sVl + row * FSR + q4 * 32 + 16) = *(const uint4*)(gvl + 8);
        }
        __syncthreads();

        // ---- S = Q K^T (m16 x n64), 3-term split ----
        float s[8][4];
        #pragma unroll
        for (int nf = 0; nf < 8; nf++)
            #pragma unroll
            for (int r = 0; r < 4; r++) s[nf][r] = 0.f;

        #pragma unroll
        for (int kc2 = 0; kc2 < 4; kc2++) {
            uint32_t kbh[4][4], kbl[4][4];
            #pragma unroll
            for (int g = 0; g < 4; g++) {
                const uint32_t brel = (g * 16 + lB_row) * FSR + kc2 * 32 + lB_kb;
                ldsm4(kbh[g], bKh + brel);
                ldsm4(kbl[g], bKl + brel);
            }
            #pragma unroll
            for (int nf = 0; nf < 8; nf++) {
                const uint32_t* bhf = &kbh[nf >> 1][(nf & 1) * 2];
                const uint32_t* blf = &kbl[nf >> 1][(nf & 1) * 2];
                mma16816(s[nf], qfh[kc2], bhf);
                mma16816(s[nf], qfh[kc2], blf);
                mma16816(s[nf], qfl[kc2], bhf);
            }
        }

        // ---- online softmax on fragments (rows lane>>2 and +8) ----
        float m0n = -1e30f, m1n = -1e30f;
        #pragma unroll
        for (int nf = 0; nf < 8; nf++) {
            m0n = fmaxf(m0n, fmaxf(s[nf][0], s[nf][1]));
            m1n = fmaxf(m1n, fmaxf(s[nf][2], s[nf][3]));
        }
        #pragma unroll
        for (int off = 1; off <= 2; off <<= 1) {
            m0n = fmaxf(m0n, __shfl_xor_sync(0xffffffffu, m0n, off));
            m1n = fmaxf(m1n, __shfl_xor_sync(0xffffffffu, m1n, off));
        }
        const float M0 = fmaxf(mrow0, m0n);
        const float M1 = fmaxf(mrow1, m1n);
        const float a0 = __expf(mrow0 - M0);
        const float a1 = __expf(mrow1 - M1);
        mrow0 = M0; mrow1 = M1;
        float rs0 = 0.f, rs1 = 0.f;
        #pragma unroll
        for (int nf = 0; nf < 8; nf++) {
            s[nf][0] = __expf(s[nf][0] - M0); rs0 += s[nf][0];
            s[nf][1] = __expf(s[nf][1] - M0); rs0 += s[nf][1];
            s[nf][2] = __expf(s[nf][2] - M1); rs1 += s[nf][2];
            s[nf][3] = __expf(s[nf][3] - M1); rs1 += s[nf][3];
        }
        #pragma unroll
        for (int off = 1; off <= 2; off <<= 1) {
            rs0 += __shfl_xor_sync(0xffffffffu, rs0, off);
            rs1 += __shfl_xor_sync(0xffffffffu, rs1, off);
        }
        lrow0 = lrow0 * a0 + rs0;
        lrow1 = lrow1 * a1 + rs1;
        #pragma unroll
        for (int nf = 0; nf < 8; nf++) {
            o[nf][0] *= a0; o[nf][1] *= a0;
            o[nf][2] *= a1; o[nf][3] *= a1;
        }

        // ---- P -> A-fragments (hi/lo), classic C->A remap ----
        uint32_t pfh[4][4], pfl[4][4];
        #pragma unroll
        for (int pc = 0; pc < 4; pc++) {
            pack_split(s[2 * pc][0],     s[2 * pc][1],     pfh[pc][0], pfl[pc][0]);
            pack_split(s[2 * pc][2],     s[2 * pc][3],     pfh[pc][1], pfl[pc][1]);
            pack_split(s[2 * pc + 1][0], s[2 * pc + 1][1], pfh[pc][2], pfl[pc][2]);
            pack_split(s[2 * pc + 1][2], s[2 * pc + 1][3], pfh[pc][3], pfl[pc][3]);
        }

        // ---- O += P V  (k = key dim, V^T tile is [d][s] k-major) ----
        #pragma unroll
        for (int pc = 0; pc < 4; pc++) {
            uint32_t vbh[4][4], vbl[4][4];
            #pragma unroll
            for (int g = 0; g < 4; g++) {
                const uint32_t brel = (g * 16 + lB_row) * FSR + pc * 32 + lB_kb;
                ldsm4(vbh[g], bVh + brel);
                ldsm4(vbl[g], bVl + brel);
            }
            #pragma unroll
            for (int nf = 0; nf < 8; nf++) {
                const uint32_t* bhf = &vbh[nf >> 1][(nf & 1) * 2];
                const uint32_t* blf = &vbl[nf >> 1][(nf & 1) * 2];
                mma16816(o[nf], pfh[pc], bhf);
                mma16816(o[nf], pfh[pc], blf);
                mma16816(o[nf], pfl[pc], bhf);
            }
        }
    }

    // ---- epilogue: normalize, split to bf16 hi/lo, write ctx [b,s,D] ----
    const float inv0 = 1.0f / lrow0;
    const float inv1 = 1.0f / lrow1;
    const int b  = bh >> 4;
    const int hh = bh & 15;
    const int row0 = q0 + w * 16 + (lane >> 2);
    #pragma unroll
    for (int nf = 0; nf < 8; nf++) {
        const int d = hh * 64 + nf * 8 + (lane & 3) * 2;
        __nv_bfloat16 h00, l00, h01, l01, h10, l10, h11, l11;
        split1(o[nf][0] * inv0, h00, l00);
        split1(o[nf][1] * inv0, h01, l01);
        split1(o[nf][2] * inv1, h10, l10);
        split1(o[nf][3] * inv1, h11, l11);
        const size_t base0 = ((size_t)b * SEQ + row0) * D_MODEL + d;
        const size_t base1 = base0 + 8 * D_MODEL;
        *(__nv_bfloat162*)(chi + base0) = __nv_bfloat162(h00, h01);
        *(__nv_bfloat162*)(clo + base0) = __nv_bfloat162(l00, l01);
        *(__nv_bfloat162*)(chi + base1) = __nv_bfloat162(h10, h11);
        *(__nv_bfloat162*)(clo + base1) = __nv_bfloat162(l10, l11);
    }
}

// ---------------------------------------------------------------------------
extern "C" void kernel_launch(void* const* d_in, const int* in_sizes, int n_in,
                              void* d_out, int out_size)
{
    const float* x  = (const float*)d_in[0];
    const float* Wq = (const float*)d_in[1];
    const float* bq = (const float*)d_in[2];
    const float* Wk = (const float*)d_in[3];
    const float* bk = (const float*)d_in[4];
    const float* Wv = (const float*)d_in[5];
    const float* bv = (const float*)d_in[6];
    const float* Wo = (const float*)d_in[7];
    const float* bo = (const float*)d_in[8];
    float* out = (float*)d_out;

    __nv_bfloat16 *xhi, *xlo, *whi, *wlo;
    __nv_bfloat16 *qhi, *qlo, *khi, *klo, *vhi, *vlo, *chi, *clo;
    cudaGetSymbolAddress((void**)&xhi, g_xhi);
    cudaGetSymbolAddress((void**)&xlo, g_xlo);
    cudaGetSymbolAddress((void**)&whi, g_whi);
    cudaGetSymbolAddress((void**)&wlo, g_wlo);
    cudaGetSymbolAddress((void**)&qhi, g_qhi);
    cudaGetSymbolAddress((void**)&qlo, g_qlo);
    cudaGetSymbolAddress((void**)&khi, g_khi);
    cudaGetSymbolAddress((void**)&klo, g_klo);
    cudaGetSymbolAddress((void**)&vhi, g_vhi);
    cudaGetSymbolAddress((void**)&vlo, g_vlo);
    cudaGetSymbolAddress((void**)&chi, g_chi);
    cudaGetSymbolAddress((void**)&clo, g_clo);

    const int WSZ = D_MODEL * D_MODEL;
    const int xn4 = MROWS * D_MODEL / 4;
    const int wn4 = WSZ / 4;

    split_bf16<<<(xn4 + 255) / 256, 256>>>((const float4*)x,
        (uint2*)xhi, (uint2*)xlo, xn4);
    const float* Ws[4] = {Wq, Wk, Wv, Wo};
    for (int w = 0; w < 4; ++w)
        split_bf16<<<(wn4 + 255) / 256, 256>>>((const float4*)Ws[w],
            (uint2*)(whi + (size_t)w * WSZ), (uint2*)(wlo + (size_t)w * WSZ), wn4);

    const dim3 gg(D_MODEL / 128, MROWS / 128);   // (8, 64)

    gemm_proj<1><<<gg, 256>>>(xhi, xlo, whi + 0 * (size_t)WSZ, wlo + 0 * (size_t)WSZ,
                              bq, qhi, qlo, 0.125f);
    gemm_proj<1><<<gg, 256>>>(xhi, xlo, whi + 1 * (size_t)WSZ, wlo + 1 * (size_t)WSZ,
                              bk, khi, klo, 1.0f);
    gemm_proj<2><<<gg, 256>>>(xhi, xlo, whi + 2 * (size_t)WSZ, wlo + 2 * (size_t)WSZ,
                              bv, vhi, vlo, 1.0f);

    const int fsmem = 2 * 128 * FSR + 4 * 64 * FSR;   // 73728 B
    cudaFuncSetAttribute(flash_mma, cudaFuncAttributeMaxDynamicSharedMemorySize, fsmem);
    flash_mma<<<dim3(SEQ / 128, BATCH * H), 256, fsmem>>>(qhi, qlo, khi, klo,
                                                          vhi, vlo, chi, clo);

    gemm_out<<<gg, 256>>>(chi, clo, whi + 3 * (size_t)WSZ, wlo + 3 * (size_t)WSZ,
                          bo, out);
}

// round 9
// speedup vs baseline: 2.6990x; 1.0389x over previous
#include <cuda_runtime.h>
#include <cuda_bf16.h>
#include <cstdint>

// ---------------------------------------------------------------------------
// MultiHeadAttention: x[B,S,D] -> out[B,S,D]
// B=4, S=2048, D=1024, H=16, dk=64
//   0) split fp32 -> bf16 (hi, lo): x (1 launch), 4 weights (1 fused launch)
//   1) gemm_qkv (fused): Q/K -> bf16 hi/lo [b,h,s,dk] (Q scaled 1/8),
//                        V   -> bf16 hi/lo [b,h,dk,s] (transposed)
//   2) flash_mma : tensor-core flash attention (mma.sync bf16-split),
//                  cp.async double-buffered K/V; ctx out as bf16 hi/lo
//   3) gemm_out  : out = ctx @ Wo^T + bo  (fp32)
// A*B ~= Ahi*Bhi + Ahi*Blo + Alo*Bhi (fp32 accum) -> ~1e-5 rel err.
// All GEMM mainloops cp.async double-buffered.
// Target plain sm_100: mma.sync + ldmatrix + cp.async.
// ---------------------------------------------------------------------------

constexpr int D_MODEL = 1024;
constexpr int H       = 16;
constexpr int DKH     = 64;
constexpr int SEQ     = 2048;
constexpr int BATCH   = 4;
constexpr int MROWS   = BATCH * SEQ;      // 8192

__device__ __nv_bfloat16 g_xhi[MROWS * D_MODEL];
__device__ __nv_bfloat16 g_xlo[MROWS * D_MODEL];
__device__ __nv_bfloat16 g_whi[4][D_MODEL * D_MODEL];
__device__ __nv_bfloat16 g_wlo[4][D_MODEL * D_MODEL];
__device__ __nv_bfloat16 g_qhi[BATCH * H * SEQ * DKH];
__device__ __nv_bfloat16 g_qlo[BATCH * H * SEQ * DKH];
__device__ __nv_bfloat16 g_khi[BATCH * H * SEQ * DKH];
__device__ __nv_bfloat16 g_klo[BATCH * H * SEQ * DKH];
__device__ __nv_bfloat16 g_vhi[BATCH * H * DKH * SEQ];   // transposed
__device__ __nv_bfloat16 g_vlo[BATCH * H * DKH * SEQ];
__device__ __nv_bfloat16 g_chi[MROWS * D_MODEL];
__device__ __nv_bfloat16 g_clo[MROWS * D_MODEL];

// ---------------- helpers ----------------
__device__ __forceinline__ uint32_t smem_u32(const void* p) {
    uint32_t a;
    asm("{ .reg .u64 t; cvta.to.shared.u64 t, %1; cvt.u32.u64 %0, t; }"
        : "=r"(a) : "l"(p));
    return a;
}
__device__ __forceinline__ void ldsm4(uint32_t* r, uint32_t addr) {
    asm volatile("ldmatrix.sync.aligned.m8n8.x4.shared.b16 {%0,%1,%2,%3}, [%4];"
        : "=r"(r[0]), "=r"(r[1]), "=r"(r[2]), "=r"(r[3]) : "r"(addr));
}
__device__ __forceinline__ void mma16816(float* c, const uint32_t* a,
                                         const uint32_t* b) {
    asm volatile(
        "mma.sync.aligned.m16n8k16.row.col.f32.bf16.bf16.f32 "
        "{%0,%1,%2,%3}, {%4,%5,%6,%7}, {%8,%9}, {%0,%1,%2,%3};"
        : "+f"(c[0]), "+f"(c[1]), "+f"(c[2]), "+f"(c[3])
        : "r"(a[0]), "r"(a[1]), "r"(a[2]), "r"(a[3]), "r"(b[0]), "r"(b[1]));
}
__device__ __forceinline__ void split1(float v, __nv_bfloat16& h, __nv_bfloat16& l) {
    h = __float2bfloat16_rn(v);
    l = __float2bfloat16_rn(v - __bfloat162float(h));
}
__device__ __forceinline__ void pack_split(float e, float o, uint32_t& hr, uint32_t& lr) {
    __nv_bfloat16 he, le, ho, lo;
    split1(e, he, le);
    split1(o, ho, lo);
    hr = (uint32_t)__bfloat16_as_ushort(he) | ((uint32_t)__bfloat16_as_ushort(ho) << 16);
    lr = (uint32_t)__bfloat16_as_ushort(le) | ((uint32_t)__bfloat16_as_ushort(lo) << 16);
}
#define CP16(dst, src) \
    asm volatile("cp.async.cg.shared.global [%0], [%1], 16;" :: "r"(dst), "l"(src))
#define CP_COMMIT() asm volatile("cp.async.commit_group;" ::: "memory")
#define CP_WAIT0()  asm volatile("cp.async.wait_group 0;"  ::: "memory")

// ---------------------------------------------------------------------------
// split fp32 -> (bf16 hi, bf16 lo)
// ---------------------------------------------------------------------------
__global__ void __launch_bounds__(256)
split_bf16(const float4* __restrict__ src, uint2* __restrict__ hi,
           uint2* __restrict__ lo, int n4)
{
    const int i = blockIdx.x * 256 + threadIdx.x;
    if (i >= n4) return;
    float4 v = src[i];
    __nv_bfloat16 h0, l0, h1, l1, h2, l2, h3, l3;
    split1(v.x, h0, l0); split1(v.y, h1, l1);
    split1(v.z, h2, l2); split1(v.w, h3, l3);
    uint2 hw, lw;
    hw.x = (uint32_t)__bfloat16_as_ushort(h0) | ((uint32_t)__bfloat16_as_ushort(h1) << 16);
    hw.y = (uint32_t)__bfloat16_as_ushort(h2) | ((uint32_t)__bfloat16_as_ushort(h3) << 16);
    lw.x = (uint32_t)__bfloat16_as_ushort(l0) | ((uint32_t)__bfloat16_as_ushort(l1) << 16);
    lw.y = (uint32_t)__bfloat16_as_ushort(l2) | ((uint32_t)__bfloat16_as_ushort(l3) << 16);
    hi[i] = hw;
    lo[i] = lw;
}

// fused split for the 4 weight matrices (each WSZ elements)
__global__ void __launch_bounds__(256)
split_w4(const float4* __restrict__ w0, const float4* __restrict__ w1,
         const float4* __restrict__ w2, const float4* __restrict__ w3,
         uint2* __restrict__ hi, uint2* __restrict__ lo, int wn4)
{
    const int bpw = wn4 / 256;               // blocks per weight
    const int w   = blockIdx.x / bpw;
    const int i   = (blockIdx.x - w * bpw) * 256 + threadIdx.x;
    const float4* src = (w == 0) ? w0 : (w == 1) ? w1 : (w == 2) ? w2 : w3;
    float4 v = src[i];
    __nv_bfloat16 h0, l0, h1, l1, h2, l2, h3, l3;
    split1(v.x, h0, l0); split1(v.y, h1, l1);
    split1(v.z, h2, l2); split1(v.w, h3, l3);
    uint2 hw, lw;
    hw.x = (uint32_t)__bfloat16_as_ushort(h0) | ((uint32_t)__bfloat16_as_ushort(h1) << 16);
    hw.y = (uint32_t)__bfloat16_as_ushort(h2) | ((uint32_t)__bfloat16_as_ushort(h3) << 16);
    lw.x = (uint32_t)__bfloat16_as_ushort(l0) | ((uint32_t)__bfloat16_as_ushort(l1) << 16);
    lw.y = (uint32_t)__bfloat16_as_ushort(l2) | ((uint32_t)__bfloat16_as_ushort(l3) << 16);
    hi[(size_t)w * wn4 + i] = hw;
    lo[(size_t)w * wn4 + i] = lw;
}

// ---------------------------------------------------------------------------
// HMMA GEMM pipelined mainloop (cp.async double buffer).
// CTA 128x128, 8 warps (2m x 4n), BK=32, bf16-split 3-term.
// Smem: 2 buffers x 4 tiles x [128][TSTR] (TSTR=80B padded rows).
// ---------------------------------------------------------------------------
constexpr int TSTR = 80;
constexpr int GT   = 128 * TSTR;   // bytes per tile (10240)
constexpr int GB   = 4 * GT;       // bytes per buffer (40960)

#define GEMM_PIPE(AhiP, AloP, BhiP, BloP)                                       \
    extern __shared__ char smc[];                                               \
    const uint32_t sbase = smem_u32(smc);                                       \
    const int tid  = threadIdx.x;                                               \
    const int wid  = tid >> 5;                                                  \
    const int lane = tid & 31;                                                  \
    const int wm = wid >> 2, wn = wid & 3;                                      \
    const int lrow = tid >> 1, lhalf = tid & 1;                                 \
    const __nv_bfloat16* gsrc[4] = {                                            \
        (AhiP) + (size_t)(m0 + lrow) * D_MODEL + lhalf * 16,                    \
        (AloP) + (size_t)(m0 + lrow) * D_MODEL + lhalf * 16,                    \
        (BhiP) + (size_t)(n0 + lrow) * D_MODEL + lhalf * 16,                    \
        (BloP) + (size_t)(n0 + lrow) * D_MODEL + lhalf * 16 };                  \
    const int lA_row = lane & 15, lA_kb = (lane >> 4) * 16;                     \
    const int lB_row = (lane & 7) + ((lane >> 4) << 3);                         \
    const int lB_kb  = ((lane >> 3) & 1) * 16;                                  \
    const uint32_t ro = lrow * TSTR + lhalf * 32;                               \
    float acc[4][4][4];                                                         \
    _Pragma("unroll")                                                           \
    for (int mi = 0; mi < 4; mi++)                                              \
        _Pragma("unroll")                                                       \
        for (int nf = 0; nf < 4; nf++)                                          \
            _Pragma("unroll")                                                   \
            for (int r = 0; r < 4; r++) acc[mi][nf][r] = 0.f;                   \
    _Pragma("unroll")                                                           \
    for (int t = 0; t < 4; t++) {                                               \
        CP16(sbase + t * GT + ro,      gsrc[t]);                                \
        CP16(sbase + t * GT + ro + 16, gsrc[t] + 8);                            \
    }                                                                           \
    CP_COMMIT();                                                                \
    for (int c = 0; c < 32; ++c) {                                              \
        CP_WAIT0();                                                             \
        __syncthreads();                                                        \
        if (c + 1 < 32) {                                                       \
            const uint32_t db = sbase + ((c + 1) & 1) * GB;                     \
            _Pragma("unroll")                                                   \
            for (int t = 0; t < 4; t++) {                                       \
                CP16(db + t * GT + ro,      gsrc[t] + (c + 1) * 32);            \
                CP16(db + t * GT + ro + 16, gsrc[t] + (c + 1) * 32 + 8);        \
            }                                                                   \
            CP_COMMIT();                                                        \
        }                                                                       \
        const uint32_t cb = sbase + (c & 1) * GB;                               \
        _Pragma("unroll")                                                       \
        for (int ks = 0; ks < 2; ks++) {                                        \
            const int kb = ks * 32;                                             \
            uint32_t bh[2][4], bl[2][4];                                        \
            _Pragma("unroll")                                                   \
            for (int g = 0; g < 2; g++) {                                       \
                const uint32_t brel = (wn * 32 + g * 16 + lB_row) * TSTR + kb + lB_kb; \
                ldsm4(bh[g], cb + 2 * GT + brel);                               \
                ldsm4(bl[g], cb + 3 * GT + brel);                               \
            }                                                                   \
            _Pragma("unroll")                                                   \
            for (int mi = 0; mi < 4; mi++) {                                    \
                uint32_t ah[4], al[4];                                          \
                const uint32_t arel = (wm * 64 + mi * 16 + lA_row) * TSTR + kb + lA_kb; \
                ldsm4(ah, cb + arel);                                           \
                ldsm4(al, cb + GT + arel);                                      \
                _Pragma("unroll")                                               \
                for (int nf = 0; nf < 4; nf++) {                                \
                    const uint32_t* bhf = &bh[nf >> 1][(nf & 1) * 2];           \
                    const uint32_t* blf = &bl[nf >> 1][(nf & 1) * 2];           \
                    mma16816(acc[mi][nf], ah, bhf);                             \
                    mma16816(acc[mi][nf], ah, blf);                             \
                    mma16816(acc[mi][nf], al, bhf);                             \
                }                                                               \
            }                                                                   \
        }                                                                       \
    }

// Fused QKV projection: wsel = blockIdx.x/8 selects weight/bias/epilogue.
__global__ void __launch_bounds__(256, 1)
gemm_qkv(const __nv_bfloat16* __restrict__ xhi_, const __nv_bfloat16* __restrict__ xlo_,
         const __nv_bfloat16* __restrict__ whi_, const __nv_bfloat16* __restrict__ wlo_,
         const float* __restrict__ bqp, const float* __restrict__ bkp,
         const float* __restrict__ bvp,
         __nv_bfloat16* __restrict__ qhi_, __nv_bfloat16* __restrict__ qlo_,
         __nv_bfloat16* __restrict__ khi_, __nv_bfloat16* __restrict__ klo_,
         __nv_bfloat16* __restrict__ vhi_, __nv_bfloat16* __restrict__ vlo_)
{
    const int wsel = blockIdx.x >> 3;
    const int n0   = (blockIdx.x & 7) * 128;
    const int m0   = blockIdx.y * 128;
    const __nv_bfloat16* Bh = whi_ + (size_t)wsel * (D_MODEL * D_MODEL);
    const __nv_bfloat16* Bl = wlo_ + (size_t)wsel * (D_MODEL * D_MODEL);
    const float* bias = (wsel == 0) ? bqp : (wsel == 1) ? bkp : bvp;
    const float scale = (wsel == 0) ? 0.125f : 1.0f;

    GEMM_PIPE(xhi_, xlo_, Bh, Bl)

    __nv_bfloat16* Dhi = (wsel == 0) ? qhi_ : (wsel == 1) ? khi_ : vhi_;
    __nv_bfloat16* Dlo = (wsel == 0) ? qlo_ : (wsel == 1) ? klo_ : vlo_;

    #pragma unroll
    for (int mi = 0; mi < 4; mi++) {
        const int r0 = m0 + wm * 64 + mi * 16 + (lane >> 2);
        const int b  = r0 >> 11;
        const int s0 = r0 & (SEQ - 1);
        #pragma unroll
        for (int nf = 0; nf < 4; nf++) {
            const int n  = n0 + wn * 32 + nf * 8 + (lane & 3) * 2;
            const float b0 = __ldg(bias + n);
            const float b1 = __ldg(bias + n + 1);
            const float v00 = (acc[mi][nf][0] + b0) * scale;
            const float v01 = (acc[mi][nf][1] + b1) * scale;
            const float v10 = (acc[mi][nf][2] + b0) * scale;
            const float v11 = (acc[mi][nf][3] + b1) * scale;
            const int hd = n >> 6, d = n & 63;
            __nv_bfloat16 h00, l00, h01, l01, h10, l10, h11, l11;
            split1(v00, h00, l00); split1(v01, h01, l01);
            split1(v10, h10, l10); split1(v11, h11, l11);
            if (wsel < 2) {
                const size_t base = ((size_t)(b * H + hd) * SEQ + s0) * DKH + d;
                *(__nv_bfloat162*)(Dhi + base) = __nv_bfloat162(h00, h01);
                *(__nv_bfloat162*)(Dlo + base) = __nv_bfloat162(l00, l01);
                *(__nv_bfloat162*)(Dhi + base + 8 * DKH) = __nv_bfloat162(h10, h11);
                *(__nv_bfloat162*)(Dlo + base + 8 * DKH) = __nv_bfloat162(l10, l11);
            } else {
                const size_t base = ((size_t)(b * H + hd) * DKH + d) * SEQ + s0;
                Dhi[base]           = h00; Dlo[base]           = l00;
                Dhi[base + SEQ]     = h01; Dlo[base + SEQ]     = l01;
                Dhi[base + 8]       = h10; Dlo[base + 8]       = l10;
                Dhi[base + SEQ + 8] = h11; Dlo[base + SEQ + 8] = l11;
            }
        }
    }
}

__global__ void __launch_bounds__(256, 1)
gemm_out(const __nv_bfloat16* __restrict__ Ahi, const __nv_bfloat16* __restrict__ Alo,
         const __nv_bfloat16* __restrict__ Bhi, const __nv_bfloat16* __restrict__ Blo,
         const float* __restrict__ bias, float* __restrict__ C)
{
    const int m0 = blockIdx.y * 128;
    const int n0 = blockIdx.x * 128;

    GEMM_PIPE(Ahi, Alo, Bhi, Blo)

    #pragma unroll
    for (int mi = 0; mi < 4; mi++) {
        const int r0 = m0 + wm * 64 + mi * 16 + (lane >> 2);
        #pragma unroll
        for (int nf = 0; nf < 4; nf++) {
            const int n = n0 + wn * 32 + nf * 8 + (lane & 3) * 2;
            const float b0 = __ldg(bias + n);
            const float b1 = __ldg(bias + n + 1);
            float2 lo2, hi2;
            lo2.x = acc[mi][nf][0] + b0;
            lo2.y = acc[mi][nf][1] + b1;
            hi2.x = acc[mi][nf][2] + b0;
            hi2.y = acc[mi][nf][3] + b1;
            *(float2*)(C + (size_t)r0 * D_MODEL + n)       = lo2;
            *(float2*)(C + (size_t)(r0 + 8) * D_MODEL + n) = hi2;
        }
    }
}

// ---------------------------------------------------------------------------
// Tensor-core flash attention, cp.async double-buffered K/V.
// CTA = 128 q-rows of one (b,h); 8 warps x m16. KV tiled 64 keys.
// ---------------------------------------------------------------------------
constexpr int FSR = 144;              // smem row stride (64 bf16 rows)
constexpr int KVT = 64 * FSR;         // one KV tile (9216 B)
constexpr int KVB = 4 * KVT;          // Kh,Kl,Vh,Vl buffer (36864 B)

#define FLASH_KV_ISSUE(bufbase, c0_)                                            \
    {                                                                           \
        const int row = tid >> 2, q4 = tid & 3;                                 \
        const __nv_bfloat16* gk  = khi + boff + (size_t)((c0_) + row) * DKH + q4 * 16; \
        const __nv_bfloat16* gkl = klo + boff + (size_t)((c0_) + row) * DKH + q4 * 16; \
        const __nv_bfloat16* gv  = vhi + boff + (size_t)row * SEQ + (c0_) + q4 * 16;   \
        const __nv_bfloat16* gvl = vlo + boff + (size_t)row * SEQ + (c0_) + q4 * 16;   \
        const uint32_t kro = row * FSR + q4 * 32;                               \
        CP16((bufbase) + 0 * KVT + kro,      gk);                               \
        CP16((bufbase) + 0 * KVT + kro + 16, gk + 8);                           \
        CP16((bufbase) + 1 * KVT + kro,      gkl);                              \
        CP16((bufbase) + 1 * KVT + kro + 16, gkl + 8);                          \
        CP16((bufbase) + 2 * KVT + kro,      gv);                               \
        CP16((bufbase) + 2 * KVT + kro + 16, gv + 8);                           \
        CP16((bufbase) + 3 * KVT + kro,      gvl);                              \
        CP16((bufbase) + 3 * KVT + kro + 16, gvl + 8);                          \
    }

__global__ void __launch_bounds__(256, 1)
flash_mma(const __nv_bfloat16* __restrict__ qhi, const __nv_bfloat16* __restrict__ qlo,
          const __nv_bfloat16* __restrict__ khi, const __nv_bfloat16* __restrict__ klo,
          const __nv_bfloat16* __restrict__ vhi, const __nv_bfloat16* __restrict__ vlo,
          __nv_bfloat16* __restrict__ chi, __nv_bfloat16* __restrict__ clo)
{
    extern __shared__ char fsm[];
    char* sQh = fsm;
    char* sQl = fsm + 128 * FSR;
    const uint32_t bQh = smem_u32(sQh);
    const uint32_t bQl = smem_u32(sQl);
    const uint32_t bKV = bQh + 2 * 128 * FSR;   // double KV buffer base

    const int tid  = threadIdx.x;
    const int lane = tid & 31;
    const int w    = tid >> 5;
    const int bh   = blockIdx.y;
    const int q0   = blockIdx.x * 128;
    const size_t boff = (size_t)bh * SEQ * DKH;

    // issue KV chunk 0 early
    FLASH_KV_ISSUE(bKV, 0);
    CP_COMMIT();

    // Q tile (128 x 64, hi/lo): 2 threads/row, 32 elems each
    {
        const int row = tid >> 1, half = tid & 1;
        const __nv_bfloat16* gq = qhi + boff + (size_t)(q0 + row) * DKH + half * 32;
        const __nv_bfloat16* gl = qlo + boff + (size_t)(q0 + row) * DKH + half * 32;
        #pragma unroll
        for (int i = 0; i < 4; i++) {
            *(uint4*)(sQh + row * FSR + half * 64 + i * 16) = *(const uint4*)(gq + i * 8);
            *(uint4*)(sQl + row * FSR + half * 64 + i * 16) = *(const uint4*)(gl + i * 8);
        }
    }
    __syncthreads();

    const int lA_row = lane & 15;
    const int lA_kb  = (lane >> 4) * 16;
    const int lB_row = (lane & 7) + ((lane >> 4) << 3);
    const int lB_kb  = ((lane >> 3) & 1) * 16;

    uint32_t qfh[4][4], qfl[4][4];
    #pragma unroll
    for (int kc2 = 0; kc2 < 4; kc2++) {
        const uint32_t arel = (w * 16 + lA_row) * FSR + kc2 * 32 + lA_kb;
        ldsm4(qfh[kc2], bQh + arel);
        ldsm4(qfl[kc2], bQl + arel);
    }

    float o[8][4];
    #pragma unroll
    for (int nf = 0; nf < 8; nf++)
        #pragma unroll
        for (int r = 0; r < 4; r++) o[nf][r] = 0.f;
    float mrow0 = -1e30f, mrow1 = -1e30f, lrow0 = 0.f, lrow1 = 0.f;

    for (int kt = 0; kt < SEQ / 64; kt++) {
        CP_WAIT0();
        __syncthreads();
        if (kt + 1 < SEQ / 64) {
            FLASH_KV_ISSUE(bKV + ((kt + 1) & 1) * KVB, (kt + 1) * 64);
            CP_COMMIT();
        }
        const uint32_t cb  = bKV + (kt & 1) * KVB;
        const uint32_t bKh = cb;
        const uint32_t bKl = cb + KVT;
        const uint32_t bVh = cb + 2 * KVT;
        const uint32_t bVl = cb + 3 * KVT;

        // ---- S = Q K^T (m16 x n64), 3-term split ----
        float s[8][4];
        #pragma unroll
        for (int nf = 0; nf < 8; nf++)
            #pragma unroll
            for (int r = 0; r < 4; r++) s[nf][r] = 0.f;

        #pragma unroll
        for (int kc2 = 0; kc2 < 4; kc2++) {
            uint32_t kbh[4][4], kbl[4][4];
            #pragma unroll
            for (int g = 0; g < 4; g++) {
                const uint32_t brel = (g * 16 + lB_row) * FSR + kc2 * 32 + lB_kb;
                ldsm4(kbh[g], bKh + brel);
                ldsm4(kbl[g], bKl + brel);
            }
            #pragma unroll
            for (int nf = 0; nf < 8; nf++) {
                const uint32_t* bhf = &kbh[nf >> 1][(nf & 1) * 2];
                const uint32_t* blf = &kbl[nf >> 1][(nf & 1) * 2];
                mma16816(s[nf], qfh[kc2], bhf);
                mma16816(s[nf], qfh[kc2], blf);
                mma16816(s[nf], qfl[kc2], bhf);
            }
        }

        // ---- online softmax on fragments ----
        float m0n = -1e30f, m1n = -1e30f;
        #pragma unroll
        for (int nf = 0; nf < 8; nf++) {
            m0n = fmaxf(m0n, fmaxf(s[nf][0], s[nf][1]));
            m1n = fmaxf(m1n, fmaxf(s[nf][2], s[nf][3]));
        }
        #pragma unroll
        for (int off = 1; off <= 2; off <<= 1) {
            m0n = fmaxf(m0n, __shfl_xor_sync(0xffffffffu, m0n, off));
            m1n = fmaxf(m1n, __shfl_xor_sync(0xffffffffu, m1n, off));
        }
        const float M0 = fmaxf(mrow0, m0n);
        const float M1 = fmaxf(mrow1, m1n);
        const float a0 = __expf(mrow0 - M0);
        const float a1 = __expf(mrow1 - M1);
        mrow0 = M0; mrow1 = M1;
        float rs0 = 0.f, rs1 = 0.f;
        #pragma unroll
        for (int nf = 0; nf < 8; nf++) {
            s[nf][0] = __expf(s[nf][0] - M0); rs0 += s[nf][0];
            s[nf][1] = __expf(s[nf][1] - M0); rs0 += s[nf][1];
            s[nf][2] = __expf(s[nf][2] - M1); rs1 += s[nf][2];
            s[nf][3] = __expf(s[nf][3] - M1); rs1 += s[nf][3];
        }
        #pragma unroll
        for (int off = 1; off <= 2; off <<= 1) {
            rs0 += __shfl_xor_sync(0xffffffffu, rs0, off);
            rs1 += __shfl_xor_sync(0xffffffffu, rs1, off);
        }
        lrow0 = lrow0 * a0 + rs0;
        lrow1 = lrow1 * a1 + rs1;
        #pragma unroll
        for (int nf = 0; nf < 8; nf++) {
            o[nf][0] *= a0; o[nf][1] *= a0;
            o[nf][2] *= a1; o[nf][3] *= a1;
        }

        // ---- P -> A-fragments (hi/lo) ----
        uint32_t pfh[4][4], pfl[4][4];
        #pragma unroll
        for (int pc = 0; pc < 4; pc++) {
            pack_split(s[2 * pc][0],     s[2 * pc][1],     pfh[pc][0], pfl[pc][0]);
            pack_split(s[2 * pc][2],     s[2 * pc][3],     pfh[pc][1], pfl[pc][1]);
            pack_split(s[2 * pc + 1][0], s[2 * pc + 1][1], pfh[pc][2], pfl[pc][2]);
            pack_split(s[2 * pc + 1][2], s[2 * pc + 1][3], pfh[pc][3], pfl[pc][3]);
        }

        // ---- O += P V ----
        #pragma unroll
        for (int pc = 0; pc < 4; pc++) {
            uint32_t vbh[4][4], vbl[4][4];
            #pragma unroll
            for (int g = 0; g < 4; g++) {
                const uint32_t brel = (g * 16 + lB_row) * FSR + pc * 32 + lB_kb;
                ldsm4(vbh[g], bVh + brel);
                ldsm4(vbl[g], bVl + brel);
            }
            #pragma unroll
            for (int nf = 0; nf < 8; nf++) {
                const uint32_t* bhf = &vbh[nf >> 1][(nf & 1) * 2];
                const uint32_t* blf = &vbl[nf >> 1][(nf & 1) * 2];
                mma16816(o[nf], pfh[pc], bhf);
                mma16816(o[nf], pfh[pc], blf);
                mma16816(o[nf], pfl[pc], bhf);
            }
        }
    }

    // ---- epilogue ----
    const float inv0 = 1.0f / lrow0;
    const float inv1 = 1.0f / lrow1;
    const int b  = bh >> 4;
    const int hh = bh & 15;
    const int row0 = q0 + w * 16 + (lane >> 2);
    #pragma unroll
    for (int nf = 0; nf < 8; nf++) {
        const int d = hh * 64 + nf * 8 + (lane & 3) * 2;
        __nv_bfloat16 h00, l00, h01, l01, h10, l10, h11, l11;
        split1(o[nf][0] * inv0, h00, l00);
        split1(o[nf][1] * inv0, h01, l01);
        split1(o[nf][2] * inv1, h10, l10);
        split1(o[nf][3] * inv1, h11, l11);
        const size_t base0 = ((size_t)b * SEQ + row0) * D_MODEL + d;
        const size_t base1 = base0 + 8 * D_MODEL;
        *(__nv_bfloat162*)(chi + base0) = __nv_bfloat162(h00, h01);
        *(__nv_bfloat162*)(clo + base0) = __nv_bfloat162(l00, l01);
        *(__nv_bfloat162*)(chi + base1) = __nv_bfloat162(h10, h11);
        *(__nv_bfloat162*)(clo + base1) = __nv_bfloat162(l10, l11);
    }
}

// ---------------------------------------------------------------------------
extern "C" void kernel_launch(void* const* d_in, const int* in_sizes, int n_in,
                              void* d_out, int out_size)
{
    const float* x  = (const float*)d_in[0];
    const float* Wq = (const float*)d_in[1];
    const float* bq = (const float*)d_in[2];
    const float* Wk = (const float*)d_in[3];
    const float* bk = (const float*)d_in[4];
    const float* Wv = (const float*)d_in[5];
    const float* bv = (const float*)d_in[6];
    const float* Wo = (const float*)d_in[7];
    const float* bo = (const float*)d_in[8];
    float* out = (float*)d_out;

    __nv_bfloat16 *xhi, *xlo, *whi, *wlo;
    __nv_bfloat16 *qhi, *qlo, *khi, *klo, *vhi, *vlo, *chi, *clo;
    cudaGetSymbolAddress((void**)&xhi, g_xhi);
    cudaGetSymbolAddress((void**)&xlo, g_xlo);
    cudaGetSymbolAddress((void**)&whi, g_whi);
    cudaGetSymbolAddress((void**)&wlo, g_wlo);
    cudaGetSymbolAddress((void**)&qhi, g_qhi);
    cudaGetSymbolAddress((void**)&qlo, g_qlo);
    cudaGetSymbolAddress((void**)&khi, g_khi);
    cudaGetSymbolAddress((void**)&klo, g_klo);
    cudaGetSymbolAddress((void**)&vhi, g_vhi);
    cudaGetSymbolAddress((void**)&vlo, g_vlo);
    cudaGetSymbolAddress((void**)&chi, g_chi);
    cudaGetSymbolAddress((void**)&clo, g_clo);

    const int WSZ = D_MODEL * D_MODEL;
    const int xn4 = MROWS * D_MODEL / 4;
    const int wn4 = WSZ / 4;

    split_bf16<<<(xn4 + 255) / 256, 256>>>((const float4*)x,
        (uint2*)xhi, (uint2*)xlo, xn4);
    split_w4<<<4 * (wn4 / 256), 256>>>((const float4*)Wq, (const float4*)Wk,
        (const float4*)Wv, (const float4*)Wo, (uint2*)whi, (uint2*)wlo, wn4);

    const int gsmem = 2 * GB;   // 81920
    cudaFuncSetAttribute(gemm_qkv, cudaFuncAttributeMaxDynamicSharedMemorySize, gsmem);
    cudaFuncSetAttribute(gemm_out, cudaFuncAttributeMaxDynamicSharedMemorySize, gsmem);

    gemm_qkv<<<dim3(24, MROWS / 128), 256, gsmem>>>(xhi, xlo, whi, wlo,
        bq, bk, bv, qhi, qlo, khi, klo, vhi, vlo);

    const int fsmem = 2 * 128 * FSR + 2 * KVB;   // 110592
    cudaFuncSetAttribute(flash_mma, cudaFuncAttributeMaxDynamicSharedMemorySize, fsmem);
    flash_mma<<<dim3(SEQ / 128, BATCH * H), 256, fsmem>>>(qhi, qlo, khi, klo,
                                                          vhi, vlo, chi, clo);

    gemm_out<<<dim3(D_MODEL / 128, MROWS / 128), 256, gsmem>>>(
        chi, clo, whi + 3 * (size_t)WSZ, wlo + 3 * (size_t)WSZ, bo, out);
}

// round 10
// speedup vs baseline: 3.0195x; 1.1187x over previous
#include <cuda_runtime.h>
#include <cuda_bf16.h>
#include <cstdint>

// ---------------------------------------------------------------------------
// MultiHeadAttention: x[B,S,D] -> out[B,S,D]
// B=4, S=2048, D=1024, H=16, dk=64
//   0) split fp32 -> bf16 (hi, lo): x (1 launch), 4 weights (1 fused launch)
//   1) gemm_qkv (fused): Q/K -> bf16 hi/lo [b,h,s,dk] (Q scaled 1/8),
//                        V   -> bf16 hi/lo [b,h,dk,s] (transposed)
//   2) flash_mma : tensor-core flash attention (mma.sync bf16-split),
//                  cp.async double-buffered K/V; ctx out as bf16 hi/lo
//   3) gemm_out  : out = ctx @ Wo^T + bo  (fp32)
// A*B ~= Ahi*Bhi + Ahi*Blo + Alo*Bhi (fp32 accum) -> ~1e-5 rel err.
// All heavy kernels run 2 CTAs/SM (launch_bounds 256,2) for tensor-pipe overlap.
// Target plain sm_100: mma.sync + ldmatrix + cp.async.
// ---------------------------------------------------------------------------

constexpr int D_MODEL = 1024;
constexpr int H       = 16;
constexpr int DKH     = 64;
constexpr int SEQ     = 2048;
constexpr int BATCH   = 4;
constexpr int MROWS   = BATCH * SEQ;      // 8192

__device__ __nv_bfloat16 g_xhi[MROWS * D_MODEL];
__device__ __nv_bfloat16 g_xlo[MROWS * D_MODEL];
__device__ __nv_bfloat16 g_whi[4][D_MODEL * D_MODEL];
__device__ __nv_bfloat16 g_wlo[4][D_MODEL * D_MODEL];
__device__ __nv_bfloat16 g_qhi[BATCH * H * SEQ * DKH];
__device__ __nv_bfloat16 g_qlo[BATCH * H * SEQ * DKH];
__device__ __nv_bfloat16 g_khi[BATCH * H * SEQ * DKH];
__device__ __nv_bfloat16 g_klo[BATCH * H * SEQ * DKH];
__device__ __nv_bfloat16 g_vhi[BATCH * H * DKH * SEQ];   // transposed
__device__ __nv_bfloat16 g_vlo[BATCH * H * DKH * SEQ];
__device__ __nv_bfloat16 g_chi[MROWS * D_MODEL];
__device__ __nv_bfloat16 g_clo[MROWS * D_MODEL];

// ---------------- helpers ----------------
__device__ __forceinline__ uint32_t smem_u32(const void* p) {
    uint32_t a;
    asm("{ .reg .u64 t; cvta.to.shared.u64 t, %1; cvt.u32.u64 %0, t; }"
        : "=r"(a) : "l"(p));
    return a;
}
__device__ __forceinline__ void ldsm4(uint32_t* r, uint32_t addr) {
    asm volatile("ldmatrix.sync.aligned.m8n8.x4.shared.b16 {%0,%1,%2,%3}, [%4];"
        : "=r"(r[0]), "=r"(r[1]), "=r"(r[2]), "=r"(r[3]) : "r"(addr));
}
__device__ __forceinline__ void mma16816(float* c, const uint32_t* a,
                                         const uint32_t* b) {
    asm volatile(
        "mma.sync.aligned.m16n8k16.row.col.f32.bf16.bf16.f32 "
        "{%0,%1,%2,%3}, {%4,%5,%6,%7}, {%8,%9}, {%0,%1,%2,%3};"
        : "+f"(c[0]), "+f"(c[1]), "+f"(c[2]), "+f"(c[3])
        : "r"(a[0]), "r"(a[1]), "r"(a[2]), "r"(a[3]), "r"(b[0]), "r"(b[1]));
}
__device__ __forceinline__ void split1(float v, __nv_bfloat16& h, __nv_bfloat16& l) {
    h = __float2bfloat16_rn(v);
    l = __float2bfloat16_rn(v - __bfloat162float(h));
}
__device__ __forceinline__ void pack_split(float e, float o, uint32_t& hr, uint32_t& lr) {
    __nv_bfloat16 he, le, ho, lo;
    split1(e, he, le);
    split1(o, ho, lo);
    hr = (uint32_t)__bfloat16_as_ushort(he) | ((uint32_t)__bfloat16_as_ushort(ho) << 16);
    lr = (uint32_t)__bfloat16_as_ushort(le) | ((uint32_t)__bfloat16_as_ushort(lo) << 16);
}
#define CP16(dst, src) \
    asm volatile("cp.async.cg.shared.global [%0], [%1], 16;" :: "r"(dst), "l"(src))
#define CP_COMMIT() asm volatile("cp.async.commit_group;" ::: "memory")
#define CP_WAIT0()  asm volatile("cp.async.wait_group 0;"  ::: "memory")

// ---------------------------------------------------------------------------
// split fp32 -> (bf16 hi, bf16 lo)
// ---------------------------------------------------------------------------
__global__ void __launch_bounds__(256)
split_bf16(const float4* __restrict__ src, uint2* __restrict__ hi,
           uint2* __restrict__ lo, int n4)
{
    const int i = blockIdx.x * 256 + threadIdx.x;
    if (i >= n4) return;
    float4 v = src[i];
    __nv_bfloat16 h0, l0, h1, l1, h2, l2, h3, l3;
    split1(v.x, h0, l0); split1(v.y, h1, l1);
    split1(v.z, h2, l2); split1(v.w, h3, l3);
    uint2 hw, lw;
    hw.x = (uint32_t)__bfloat16_as_ushort(h0) | ((uint32_t)__bfloat16_as_ushort(h1) << 16);
    hw.y = (uint32_t)__bfloat16_as_ushort(h2) | ((uint32_t)__bfloat16_as_ushort(h3) << 16);
    lw.x = (uint32_t)__bfloat16_as_ushort(l0) | ((uint32_t)__bfloat16_as_ushort(l1) << 16);
    lw.y = (uint32_t)__bfloat16_as_ushort(l2) | ((uint32_t)__bfloat16_as_ushort(l3) << 16);
    hi[i] = hw;
    lo[i] = lw;
}

// fused split for the 4 weight matrices (each WSZ elements)
__global__ void __launch_bounds__(256)
split_w4(const float4* __restrict__ w0, const float4* __restrict__ w1,
         const float4* __restrict__ w2, const float4* __restrict__ w3,
         uint2* __restrict__ hi, uint2* __restrict__ lo, int wn4)
{
    const int bpw = wn4 / 256;               // blocks per weight
    const int w   = blockIdx.x / bpw;
    const int i   = (blockIdx.x - w * bpw) * 256 + threadIdx.x;
    const float4* src = (w == 0) ? w0 : (w == 1) ? w1 : (w == 2) ? w2 : w3;
    float4 v = src[i];
    __nv_bfloat16 h0, l0, h1, l1, h2, l2, h3, l3;
    split1(v.x, h0, l0); split1(v.y, h1, l1);
    split1(v.z, h2, l2); split1(v.w, h3, l3);
    uint2 hw, lw;
    hw.x = (uint32_t)__bfloat16_as_ushort(h0) | ((uint32_t)__bfloat16_as_ushort(h1) << 16);
    hw.y = (uint32_t)__bfloat16_as_ushort(h2) | ((uint32_t)__bfloat16_as_ushort(h3) << 16);
    lw.x = (uint32_t)__bfloat16_as_ushort(l0) | ((uint32_t)__bfloat16_as_ushort(l1) << 16);
    lw.y = (uint32_t)__bfloat16_as_ushort(l2) | ((uint32_t)__bfloat16_as_ushort(l3) << 16);
    hi[(size_t)w * wn4 + i] = hw;
    lo[(size_t)w * wn4 + i] = lw;
}

// ---------------------------------------------------------------------------
// HMMA GEMM pipelined mainloop (cp.async double buffer), 2 CTAs/SM.
// CTA 128x128, 8 warps (2m x 4n), BK=32, bf16-split 3-term.
// ---------------------------------------------------------------------------
constexpr int TSTR = 80;
constexpr int GT   = 128 * TSTR;   // bytes per tile (10240)
constexpr int GB   = 4 * GT;       // bytes per buffer (40960)

#define GEMM_PIPE(AhiP, AloP, BhiP, BloP)                                       \
    extern __shared__ char smc[];                                               \
    const uint32_t sbase = smem_u32(smc);                                       \
    const int tid  = threadIdx.x;                                               \
    const int wid  = tid >> 5;                                                  \
    const int lane = tid & 31;                                                  \
    const int wm = wid >> 2, wn = wid & 3;                                      \
    const int lrow = tid >> 1, lhalf = tid & 1;                                 \
    const __nv_bfloat16* gsrc[4] = {                                            \
        (AhiP) + (size_t)(m0 + lrow) * D_MODEL + lhalf * 16,                    \
        (AloP) + (size_t)(m0 + lrow) * D_MODEL + lhalf * 16,                    \
        (BhiP) + (size_t)(n0 + lrow) * D_MODEL + lhalf * 16,                    \
        (BloP) + (size_t)(n0 + lrow) * D_MODEL + lhalf * 16 };                  \
    const int lA_row = lane & 15, lA_kb = (lane >> 4) * 16;                     \
    const int lB_row = (lane & 7) + ((lane >> 4) << 3);                         \
    const int lB_kb  = ((lane >> 3) & 1) * 16;                                  \
    const uint32_t ro = lrow * TSTR + lhalf * 32;                               \
    float acc[4][4][4];                                                         \
    _Pragma("unroll")                                                           \
    for (int mi = 0; mi < 4; mi++)                                              \
        _Pragma("unroll")                                                       \
        for (int nf = 0; nf < 4; nf++)                                          \
            _Pragma("unroll")                                                   \
            for (int r = 0; r < 4; r++) acc[mi][nf][r] = 0.f;                   \
    _Pragma("unroll")                                                           \
    for (int t = 0; t < 4; t++) {                                               \
        CP16(sbase + t * GT + ro,      gsrc[t]);                                \
        CP16(sbase + t * GT + ro + 16, gsrc[t] + 8);                            \
    }                                                                           \
    CP_COMMIT();                                                                \
    for (int c = 0; c < 32; ++c) {                                              \
        CP_WAIT0();                                                             \
        __syncthreads();                                                        \
        if (c + 1 < 32) {                                                       \
            const uint32_t db = sbase + ((c + 1) & 1) * GB;                     \
            _Pragma("unroll")                                                   \
            for (int t = 0; t < 4; t++) {                                       \
                CP16(db + t * GT + ro,      gsrc[t] + (c + 1) * 32);            \
                CP16(db + t * GT + ro + 16, gsrc[t] + (c + 1) * 32 + 8);        \
            }                                                                   \
            CP_COMMIT();                                                        \
        }                                                                       \
        const uint32_t cb = sbase + (c & 1) * GB;                               \
        _Pragma("unroll")                                                       \
        for (int ks = 0; ks < 2; ks++) {                                        \
            const int kb = ks * 32;                                             \
            uint32_t bh[2][4], bl[2][4];                                        \
            _Pragma("unroll")                                                   \
            for (int g = 0; g < 2; g++) {                                       \
                const uint32_t brel = (wn * 32 + g * 16 + lB_row) * TSTR + kb + lB_kb; \
                ldsm4(bh[g], cb + 2 * GT + brel);                               \
                ldsm4(bl[g], cb + 3 * GT + brel);                               \
            }                                                                   \
            _Pragma("unroll")                                                   \
            for (int mi = 0; mi < 4; mi++) {                                    \
                uint32_t ah[4], al[4];                                          \
                const uint32_t arel = (wm * 64 + mi * 16 + lA_row) * TSTR + kb + lA_kb; \
                ldsm4(ah, cb + arel);                                           \
                ldsm4(al, cb + GT + arel);                                      \
                _Pragma("unroll")                                               \
                for (int nf = 0; nf < 4; nf++) {                                \
                    const uint32_t* bhf = &bh[nf >> 1][(nf & 1) * 2];           \
                    const uint32_t* blf = &bl[nf >> 1][(nf & 1) * 2];           \
                    mma16816(acc[mi][nf], ah, bhf);                             \
                    mma16816(acc[mi][nf], ah, blf);                             \
                    mma16816(acc[mi][nf], al, bhf);                             \
                }                                                               \
            }                                                                   \
        }                                                                       \
    }

// Fused QKV projection: wsel = blockIdx.x/8 selects weight/bias/epilogue.
__global__ void __launch_bounds__(256, 2)
gemm_qkv(const __nv_bfloat16* __restrict__ xhi_, const __nv_bfloat16* __restrict__ xlo_,
         const __nv_bfloat16* __restrict__ whi_, const __nv_bfloat16* __restrict__ wlo_,
         const float* __restrict__ bqp, const float* __restrict__ bkp,
         const float* __restrict__ bvp,
         __nv_bfloat16* __restrict__ qhi_, __nv_bfloat16* __restrict__ qlo_,
         __nv_bfloat16* __restrict__ khi_, __nv_bfloat16* __restrict__ klo_,
         __nv_bfloat16* __restrict__ vhi_, __nv_bfloat16* __restrict__ vlo_)
{
    const int wsel = blockIdx.x >> 3;
    const int n0   = (blockIdx.x & 7) * 128;
    const int m0   = blockIdx.y * 128;
    const __nv_bfloat16* Bh = whi_ + (size_t)wsel * (D_MODEL * D_MODEL);
    const __nv_bfloat16* Bl = wlo_ + (size_t)wsel * (D_MODEL * D_MODEL);
    const float* bias = (wsel == 0) ? bqp : (wsel == 1) ? bkp : bvp;
    const float scale = (wsel == 0) ? 0.125f : 1.0f;

    GEMM_PIPE(xhi_, xlo_, Bh, Bl)

    __nv_bfloat16* Dhi = (wsel == 0) ? qhi_ : (wsel == 1) ? khi_ : vhi_;
    __nv_bfloat16* Dlo = (wsel == 0) ? qlo_ : (wsel == 1) ? klo_ : vlo_;

    #pragma unroll
    for (int mi = 0; mi < 4; mi++) {
        const int r0 = m0 + wm * 64 + mi * 16 + (lane >> 2);
        const int b  = r0 >> 11;
        const int s0 = r0 & (SEQ - 1);
        #pragma unroll
        for (int nf = 0; nf < 4; nf++) {
            const int n  = n0 + wn * 32 + nf * 8 + (lane & 3) * 2;
            const float b0 = __ldg(bias + n);
            const float b1 = __ldg(bias + n + 1);
            const float v00 = (acc[mi][nf][0] + b0) * scale;
            const float v01 = (acc[mi][nf][1] + b1) * scale;
            const float v10 = (acc[mi][nf][2] + b0) * scale;
            const float v11 = (acc[mi][nf][3] + b1) * scale;
            const int hd = n >> 6, d = n & 63;
            __nv_bfloat16 h00, l00, h01, l01, h10, l10, h11, l11;
            split1(v00, h00, l00); split1(v01, h01, l01);
            split1(v10, h10, l10); split1(v11, h11, l11);
            if (wsel < 2) {
                const size_t base = ((size_t)(b * H + hd) * SEQ + s0) * DKH + d;
                *(__nv_bfloat162*)(Dhi + base) = __nv_bfloat162(h00, h01);
                *(__nv_bfloat162*)(Dlo + base) = __nv_bfloat162(l00, l01);
                *(__nv_bfloat162*)(Dhi + base + 8 * DKH) = __nv_bfloat162(h10, h11);
                *(__nv_bfloat162*)(Dlo + base + 8 * DKH) = __nv_bfloat162(l10, l11);
            } else {
                const size_t base = ((size_t)(b * H + hd) * DKH + d) * SEQ + s0;
                Dhi[base]           = h00; Dlo[base]           = l00;
                Dhi[base + SEQ]     = h01; Dlo[base + SEQ]     = l01;
                Dhi[base + 8]       = h10; Dlo[base + 8]       = l10;
                Dhi[base + SEQ + 8] = h11; Dlo[base + SEQ + 8] = l11;
            }
        }
    }
}

__global__ void __launch_bounds__(256, 2)
gemm_out(const __nv_bfloat16* __restrict__ Ahi, const __nv_bfloat16* __restrict__ Alo,
         const __nv_bfloat16* __restrict__ Bhi, const __nv_bfloat16* __restrict__ Blo,
         const float* __restrict__ bias, float* __restrict__ C)
{
    const int m0 = blockIdx.y * 128;
    const int n0 = blockIdx.x * 128;

    GEMM_PIPE(Ahi, Alo, Bhi, Blo)

    #pragma unroll
    for (int mi = 0; mi < 4; mi++) {
        const int r0 = m0 + wm * 64 + mi * 16 + (lane >> 2);
        #pragma unroll
        for (int nf = 0; nf < 4; nf++) {
            const int n = n0 + wn * 32 + nf * 8 + (lane & 3) * 2;
            const float b0 = __ldg(bias + n);
            const float b1 = __ldg(bias + n + 1);
            float2 lo2, hi2;
            lo2.x = acc[mi][nf][0] + b0;
            lo2.y = acc[mi][nf][1] + b1;
            hi2.x = acc[mi][nf][2] + b0;
            hi2.y = acc[mi][nf][3] + b1;
            *(float2*)(C + (size_t)r0 * D_MODEL + n)       = lo2;
            *(float2*)(C + (size_t)(r0 + 8) * D_MODEL + n) = hi2;
        }
    }
}

// ---------------------------------------------------------------------------
// Tensor-core flash attention, cp.async double-buffered K/V, 2 CTAs/SM.
// CTA = 128 q-rows of one (b,h); 8 warps x m16. KV tiled 64 keys.
// Fragment loops restructured group-wise (8 live regs) to fit the 128-reg cap.
// ---------------------------------------------------------------------------
constexpr int FSR = 144;              // smem row stride (64 bf16 rows)
constexpr int KVT = 64 * FSR;         // one KV tile (9216 B)
constexpr int KVB = 4 * KVT;          // Kh,Kl,Vh,Vl buffer (36864 B)

#define FLASH_KV_ISSUE(bufbase, c0_)                                            \
    {                                                                           \
        const int row = tid >> 2, q4 = tid & 3;                                 \
        const __nv_bfloat16* gk  = khi + boff + (size_t)((c0_) + row) * DKH + q4 * 16; \
        const __nv_bfloat16* gkl = klo + boff + (size_t)((c0_) + row) * DKH + q4 * 16; \
        const __nv_bfloat16* gv  = vhi + boff + (size_t)row * SEQ + (c0_) + q4 * 16;   \
        const __nv_bfloat16* gvl = vlo + boff + (size_t)row * SEQ + (c0_) + q4 * 16;   \
        const uint32_t kro = row * FSR + q4 * 32;                               \
        CP16((bufbase) + 0 * KVT + kro,      gk);                               \
        CP16((bufbase) + 0 * KVT + kro + 16, gk + 8);                           \
        CP16((bufbase) + 1 * KVT + kro,      gkl);                              \
        CP16((bufbase) + 1 * KVT + kro + 16, gkl + 8);                          \
        CP16((bufbase) + 2 * KVT + kro,      gv);                               \
        CP16((bufbase) + 2 * KVT + kro + 16, gv + 8);                           \
        CP16((bufbase) + 3 * KVT + kro,      gvl);                              \
        CP16((bufbase) + 3 * KVT + kro + 16, gvl + 8);                          \
    }

__global__ void __launch_bounds__(256, 2)
flash_mma(const __nv_bfloat16* __restrict__ qhi, const __nv_bfloat16* __restrict__ qlo,
          const __nv_bfloat16* __restrict__ khi, const __nv_bfloat16* __restrict__ klo,
          const __nv_bfloat16* __restrict__ vhi, const __nv_bfloat16* __restrict__ vlo,
          __nv_bfloat16* __restrict__ chi, __nv_bfloat16* __restrict__ clo)
{
    extern __shared__ char fsm[];
    char* sQh = fsm;
    char* sQl = fsm + 128 * FSR;
    const uint32_t bQh = smem_u32(sQh);
    const uint32_t bQl = smem_u32(sQl);
    const uint32_t bKV = bQh + 2 * 128 * FSR;   // double KV buffer base

    const int tid  = threadIdx.x;
    const int lane = tid & 31;
    const int w    = tid >> 5;
    const int bh   = blockIdx.y;
    const int q0   = blockIdx.x * 128;
    const size_t boff = (size_t)bh * SEQ * DKH;

    // issue KV chunk 0 early
    FLASH_KV_ISSUE(bKV, 0);
    CP_COMMIT();

    // Q tile (128 x 64, hi/lo): 2 threads/row, 32 elems each
    {
        const int row = tid >> 1, half = tid & 1;
        const __nv_bfloat16* gq = qhi + boff + (size_t)(q0 + row) * DKH + half * 32;
        const __nv_bfloat16* gl = qlo + boff + (size_t)(q0 + row) * DKH + half * 32;
        #pragma unroll
        for (int i = 0; i < 4; i++) {
            *(uint4*)(sQh + row * FSR + half * 64 + i * 16) = *(const uint4*)(gq + i * 8);
            *(uint4*)(sQl + row * FSR + half * 64 + i * 16) = *(const uint4*)(gl + i * 8);
        }
    }
    __syncthreads();

    const int lA_row = lane & 15;
    const int lA_kb  = (lane >> 4) * 16;
    const int lB_row = (lane & 7) + ((lane >> 4) << 3);
    const int lB_kb  = ((lane >> 3) & 1) * 16;

    uint32_t qfh[4][4], qfl[4][4];
    #pragma unroll
    for (int kc2 = 0; kc2 < 4; kc2++) {
        const uint32_t arel = (w * 16 + lA_row) * FSR + kc2 * 32 + lA_kb;
        ldsm4(qfh[kc2], bQh + arel);
        ldsm4(qfl[kc2], bQl + arel);
    }

    float o[8][4];
    #pragma unroll
    for (int nf = 0; nf < 8; nf++)
        #pragma unroll
        for (int r = 0; r < 4; r++) o[nf][r] = 0.f;
    float mrow0 = -1e30f, mrow1 = -1e30f, lrow0 = 0.f, lrow1 = 0.f;

    for (int kt = 0; kt < SEQ / 64; kt++) {
        CP_WAIT0();
        __syncthreads();
        if (kt + 1 < SEQ / 64) {
            FLASH_KV_ISSUE(bKV + ((kt + 1) & 1) * KVB, (kt + 1) * 64);
            CP_COMMIT();
        }
        const uint32_t cb  = bKV + (kt & 1) * KVB;
        const uint32_t bKh = cb;
        const uint32_t bKl = cb + KVT;
        const uint32_t bVh = cb + 2 * KVT;
        const uint32_t bVl = cb + 3 * KVT;

        // ---- S = Q K^T (m16 x n64), 3-term split; group-wise fragments ----
        float s[8][4];
        #pragma unroll
        for (int nf = 0; nf < 8; nf++)
            #pragma unroll
            for (int r = 0; r < 4; r++) s[nf][r] = 0.f;

        #pragma unroll
        for (int kc2 = 0; kc2 < 4; kc2++) {
            #pragma unroll
            for (int g = 0; g < 4; g++) {
                uint32_t kbh[4], kbl[4];
                const uint32_t brel = (g * 16 + lB_row) * FSR + kc2 * 32 + lB_kb;
                ldsm4(kbh, bKh + brel);
                ldsm4(kbl, bKl + brel);
                #pragma unroll
                for (int j = 0; j < 2; j++) {
                    const int nf = 2 * g + j;
                    mma16816(s[nf], qfh[kc2], &kbh[j * 2]);
                    mma16816(s[nf], qfh[kc2], &kbl[j * 2]);
                    mma16816(s[nf], qfl[kc2], &kbh[j * 2]);
                }
            }
        }

        // ---- online softmax on fragments ----
        float m0n = -1e30f, m1n = -1e30f;
        #pragma unroll
        for (int nf = 0; nf < 8; nf++) {
            m0n = fmaxf(m0n, fmaxf(s[nf][0], s[nf][1]));
            m1n = fmaxf(m1n, fmaxf(s[nf][2], s[nf][3]));
        }
        #pragma unroll
        for (int off = 1; off <= 2; off <<= 1) {
            m0n = fmaxf(m0n, __shfl_xor_sync(0xffffffffu, m0n, off));
            m1n = fmaxf(m1n, __shfl_xor_sync(0xffffffffu, m1n, off));
        }
        const float M0 = fmaxf(mrow0, m0n);
        const float M1 = fmaxf(mrow1, m1n);
        const float a0 = __expf(mrow0 - M0);
        const float a1 = __expf(mrow1 - M1);
        mrow0 = M0; mrow1 = M1;
        float rs0 = 0.f, rs1 = 0.f;
        #pragma unroll
        for (int nf = 0; nf < 8; nf++) {
            s[nf][0] = __expf(s[nf][0] - M0); rs0 += s[nf][0];
            s[nf][1] = __expf(s[nf][1] - M0); rs0 += s[nf][1];
            s[nf][2] = __expf(s[nf][2] - M1); rs1 += s[nf][2];
            s[nf][3] = __expf(s[nf][3] - M1); rs1 += s[nf][3];
        }
        #pragma unroll
        for (int off = 1; off <= 2; off <<= 1) {
            rs0 += __shfl_xor_sync(0xffffffffu, rs0, off);
            rs1 += __shfl_xor_sync(0xffffffffu, rs1, off);
        }
        lrow0 = lrow0 * a0 + rs0;
        lrow1 = lrow1 * a1 + rs1;
        #pragma unroll
        for (int nf = 0; nf < 8; nf++) {
            o[nf][0] *= a0; o[nf][1] *= a0;
            o[nf][2] *= a1; o[nf][3] *= a1;
        }

        // ---- O += P V, group-wise fragments (P packed hi/lo on the fly) ----
        #pragma unroll
        for (int pc = 0; pc < 4; pc++) {
            uint32_t pfh[4], pfl[4];
            pack_split(s[2 * pc][0],     s[2 * pc][1],     pfh[0], pfl[0]);
            pack_split(s[2 * pc][2],     s[2 * pc][3],     pfh[1], pfl[1]);
            pack_split(s[2 * pc + 1][0], s[2 * pc + 1][1], pfh[2], pfl[2]);
            pack_split(s[2 * pc + 1][2], s[2 * pc + 1][3], pfh[3], pfl[3]);
            #pragma unroll
            for (int g = 0; g < 4; g++) {
                uint32_t vbh[4], vbl[4];
                const uint32_t brel = (g * 16 + lB_row) * FSR + pc * 32 + lB_kb;
                ldsm4(vbh, bVh + brel);
                ldsm4(vbl, bVl + brel);
                #pragma unroll
                for (int j = 0; j < 2; j++) {
                    const int nf = 2 * g + j;
                    mma16816(o[nf], pfh, &vbh[j * 2]);
                    mma16816(o[nf], pfh, &vbl[j * 2]);
                    mma16816(o[nf], pfl, &vbh[j * 2]);
                }
            }
        }
    }

    // ---- epilogue ----
    const float inv0 = 1.0f / lrow0;
    const float inv1 = 1.0f / lrow1;
    const int b  = bh >> 4;
    const int hh = bh & 15;
    const int row0 = q0 + w * 16 + (lane >> 2);
    #pragma unroll
    for (int nf = 0; nf < 8; nf++) {
        const int d = hh * 64 + nf * 8 + (lane & 3) * 2;
        __nv_bfloat16 h00, l00, h01, l01, h10, l10, h11, l11;
        split1(o[nf][0] * inv0, h00, l00);
        split1(o[nf][1] * inv0, h01, l01);
        split1(o[nf][2] * inv1, h10, l10);
        split1(o[nf][3] * inv1, h11, l11);
        const size_t base0 = ((size_t)b * SEQ + row0) * D_MODEL + d;
        const size_t base1 = base0 + 8 * D_MODEL;
        *(__nv_bfloat162*)(chi + base0) = __nv_bfloat162(h00, h01);
        *(__nv_bfloat162*)(clo + base0) = __nv_bfloat162(l00, l01);
        *(__nv_bfloat162*)(chi + base1) = __nv_bfloat162(h10, h11);
        *(__nv_bfloat162*)(clo + base1) = __nv_bfloat162(l10, l11);
    }
}

// ---------------------------------------------------------------------------
extern "C" void kernel_launch(void* const* d_in, const int* in_sizes, int n_in,
                              void* d_out, int out_size)
{
    const float* x  = (const float*)d_in[0];
    const float* Wq = (const float*)d_in[1];
    const float* bq = (const float*)d_in[2];
    const float* Wk = (const float*)d_in[3];
    const float* bk = (const float*)d_in[4];
    const float* Wv = (const float*)d_in[5];
    const float* bv = (const float*)d_in[6];
    const float* Wo = (const float*)d_in[7];
    const float* bo = (const float*)d_in[8];
    float* out = (float*)d_out;

    __nv_bfloat16 *xhi, *xlo, *whi, *wlo;
    __nv_bfloat16 *qhi, *qlo, *khi, *klo, *vhi, *vlo, *chi, *clo;
    cudaGetSymbolAddress((void**)&xhi, g_xhi);
    cudaGetSymbolAddress((void**)&xlo, g_xlo);
    cudaGetSymbolAddress((void**)&whi, g_whi);
    cudaGetSymbolAddress((void**)&wlo, g_wlo);
    cudaGetSymbolAddress((void**)&qhi, g_qhi);
    cudaGetSymbolAddress((void**)&qlo, g_qlo);
    cudaGetSymbolAddress((void**)&khi, g_khi);
    cudaGetSymbolAddress((void**)&klo, g_klo);
    cudaGetSymbolAddress((void**)&vhi, g_vhi);
    cudaGetSymbolAddress((void**)&vlo, g_vlo);
    cudaGetSymbolAddress((void**)&chi, g_chi);
    cudaGetSymbolAddress((void**)&clo, g_clo);

    const int WSZ = D_MODEL * D_MODEL;
    const int xn4 = MROWS * D_MODEL / 4;
    const int wn4 = WSZ / 4;

    split_bf16<<<(xn4 + 255) / 256, 256>>>((const float4*)x,
        (uint2*)xhi, (uint2*)xlo, xn4);
    split_w4<<<4 * (wn4 / 256), 256>>>((const float4*)Wq, (const float4*)Wk,
        (const float4*)Wv, (const float4*)Wo, (uint2*)whi, (uint2*)wlo, wn4);

    const int gsmem = 2 * GB;   // 81920
    cudaFuncSetAttribute(gemm_qkv, cudaFuncAttributeMaxDynamicSharedMemorySize, gsmem);
    cudaFuncSetAttribute(gemm_out, cudaFuncAttributeMaxDynamicSharedMemorySize, gsmem);

    gemm_qkv<<<dim3(24, MROWS / 128), 256, gsmem>>>(xhi, xlo, whi, wlo,
        bq, bk, bv, qhi, qlo, khi, klo, vhi, vlo);

    const int fsmem = 2 * 128 * FSR + 2 * KVB;   // 110592
    cudaFuncSetAttribute(flash_mma, cudaFuncAttributeMaxDynamicSharedMemorySize, fsmem);
    flash_mma<<<dim3(SEQ / 128, BATCH * H), 256, fsmem>>>(qhi, qlo, khi, klo,
                                                          vhi, vlo, chi, clo);

    gemm_out<<<dim3(D_MODEL / 128, MROWS / 128), 256, gsmem>>>(
        chi, clo, whi + 3 * (size_t)WSZ, wlo + 3 * (size_t)WSZ, bo, out);
}

// round 11
// speedup vs baseline: 3.0288x; 1.0031x over previous
#include <cuda_runtime.h>
#include <cuda_bf16.h>
#include <cstdint>

// ---------------------------------------------------------------------------
// MultiHeadAttention: x[B,S,D] -> out[B,S,D]
// B=4, S=2048, D=1024, H=16, dk=64
//   0) split fp32 -> bf16 (hi, lo): x (1 launch), 4 weights (1 fused launch)
//   1) gemm_qkv (fused): Q/K -> bf16 hi/lo [b,h,s,dk] (Q scaled 1/8),
//                        V   -> bf16 hi/lo [b,h,dk,s] (transposed)
//   2) flash_mma : tensor-core flash attention (mma.sync bf16-split),
//                  cp.async double-buffered K/V; ctx out as bf16 hi/lo
//   3) gemm_out  : out = ctx @ Wo^T + bo  (fp32)
// A*B ~= Ahi*Bhi + Ahi*Blo + Alo*Bhi (fp32 accum) -> ~1e-5 rel err.
// All heavy kernels run 2 CTAs/SM (launch_bounds 256,2) for tensor-pipe overlap.
// Target plain sm_100: mma.sync + ldmatrix + cp.async.
// ---------------------------------------------------------------------------

constexpr int D_MODEL = 1024;
constexpr int H       = 16;
constexpr int DKH     = 64;
constexpr int SEQ     = 2048;
constexpr int BATCH   = 4;
constexpr int MROWS   = BATCH * SEQ;      // 8192

__device__ __nv_bfloat16 g_xhi[MROWS * D_MODEL];
__device__ __nv_bfloat16 g_xlo[MROWS * D_MODEL];
__device__ __nv_bfloat16 g_whi[4][D_MODEL * D_MODEL];
__device__ __nv_bfloat16 g_wlo[4][D_MODEL * D_MODEL];
__device__ __nv_bfloat16 g_qhi[BATCH * H * SEQ * DKH];
__device__ __nv_bfloat16 g_qlo[BATCH * H * SEQ * DKH];
__device__ __nv_bfloat16 g_khi[BATCH * H * SEQ * DKH];
__device__ __nv_bfloat16 g_klo[BATCH * H * SEQ * DKH];
__device__ __nv_bfloat16 g_vhi[BATCH * H * DKH * SEQ];   // transposed
__device__ __nv_bfloat16 g_vlo[BATCH * H * DKH * SEQ];
__device__ __nv_bfloat16 g_chi[MROWS * D_MODEL];
__device__ __nv_bfloat16 g_clo[MROWS * D_MODEL];

// ---------------- helpers ----------------
__device__ __forceinline__ uint32_t smem_u32(const void* p) {
    uint32_t a;
    asm("{ .reg .u64 t; cvta.to.shared.u64 t, %1; cvt.u32.u64 %0, t; }"
        : "=r"(a) : "l"(p));
    return a;
}
__device__ __forceinline__ void ldsm4(uint32_t* r, uint32_t addr) {
    asm volatile("ldmatrix.sync.aligned.m8n8.x4.shared.b16 {%0,%1,%2,%3}, [%4];"
        : "=r"(r[0]), "=r"(r[1]), "=r"(r[2]), "=r"(r[3]) : "r"(addr));
}
__device__ __forceinline__ void mma16816(float* c, const uint32_t* a,
                                         const uint32_t* b) {
    asm volatile(
        "mma.sync.aligned.m16n8k16.row.col.f32.bf16.bf16.f32 "
        "{%0,%1,%2,%3}, {%4,%5,%6,%7}, {%8,%9}, {%0,%1,%2,%3};"
        : "+f"(c[0]), "+f"(c[1]), "+f"(c[2]), "+f"(c[3])
        : "r"(a[0]), "r"(a[1]), "r"(a[2]), "r"(a[3]), "r"(b[0]), "r"(b[1]));
}
__device__ __forceinline__ void split1(float v, __nv_bfloat16& h, __nv_bfloat16& l) {
    h = __float2bfloat16_rn(v);
    l = __float2bfloat16_rn(v - __bfloat162float(h));
}
__device__ __forceinline__ void pack_split(float e, float o, uint32_t& hr, uint32_t& lr) {
    __nv_bfloat16 he, le, ho, lo;
    split1(e, he, le);
    split1(o, ho, lo);
    hr = (uint32_t)__bfloat16_as_ushort(he) | ((uint32_t)__bfloat16_as_ushort(ho) << 16);
    lr = (uint32_t)__bfloat16_as_ushort(le) | ((uint32_t)__bfloat16_as_ushort(lo) << 16);
}
#define CP16(dst, src) \
    asm volatile("cp.async.cg.shared.global [%0], [%1], 16;" :: "r"(dst), "l"(src))
#define CP_COMMIT() asm volatile("cp.async.commit_group;" ::: "memory")
#define CP_WAIT0()  asm volatile("cp.async.wait_group 0;"  ::: "memory")

// ---------------------------------------------------------------------------
// split fp32 -> (bf16 hi, bf16 lo)
// ---------------------------------------------------------------------------
__global__ void __launch_bounds__(256)
split_bf16(const float4* __restrict__ src, uint2* __restrict__ hi,
           uint2* __restrict__ lo, int n4)
{
    const int i = blockIdx.x * 256 + threadIdx.x;
    if (i >= n4) return;
    float4 v = src[i];
    __nv_bfloat16 h0, l0, h1, l1, h2, l2, h3, l3;
    split1(v.x, h0, l0); split1(v.y, h1, l1);
    split1(v.z, h2, l2); split1(v.w, h3, l3);
    uint2 hw, lw;
    hw.x = (uint32_t)__bfloat16_as_ushort(h0) | ((uint32_t)__bfloat16_as_ushort(h1) << 16);
    hw.y = (uint32_t)__bfloat16_as_ushort(h2) | ((uint32_t)__bfloat16_as_ushort(h3) << 16);
    lw.x = (uint32_t)__bfloat16_as_ushort(l0) | ((uint32_t)__bfloat16_as_ushort(l1) << 16);
    lw.y = (uint32_t)__bfloat16_as_ushort(l2) | ((uint32_t)__bfloat16_as_ushort(l3) << 16);
    hi[i] = hw;
    lo[i] = lw;
}

// fused split for the 4 weight matrices (each WSZ elements)
__global__ void __launch_bounds__(256)
split_w4(const float4* __restrict__ w0, const float4* __restrict__ w1,
         const float4* __restrict__ w2, const float4* __restrict__ w3,
         uint2* __restrict__ hi, uint2* __restrict__ lo, int wn4)
{
    const int bpw = wn4 / 256;               // blocks per weight
    const int w   = blockIdx.x / bpw;
    const int i   = (blockIdx.x - w * bpw) * 256 + threadIdx.x;
    const float4* src = (w == 0) ? w0 : (w == 1) ? w1 : (w == 2) ? w2 : w3;
    float4 v = src[i];
    __nv_bfloat16 h0, l0, h1, l1, h2, l2, h3, l3;
    split1(v.x, h0, l0); split1(v.y, h1, l1);
    split1(v.z, h2, l2); split1(v.w, h3, l3);
    uint2 hw, lw;
    hw.x = (uint32_t)__bfloat16_as_ushort(h0) | ((uint32_t)__bfloat16_as_ushort(h1) << 16);
    hw.y = (uint32_t)__bfloat16_as_ushort(h2) | ((uint32_t)__bfloat16_as_ushort(h3) << 16);
    lw.x = (uint32_t)__bfloat16_as_ushort(l0) | ((uint32_t)__bfloat16_as_ushort(l1) << 16);
    lw.y = (uint32_t)__bfloat16_as_ushort(l2) | ((uint32_t)__bfloat16_as_ushort(l3) << 16);
    hi[(size_t)w * wn4 + i] = hw;
    lo[(size_t)w * wn4 + i] = lw;
}

// ---------------------------------------------------------------------------
// HMMA GEMM pipelined mainloop (cp.async double buffer), 2 CTAs/SM.
// CTA 128x128, 8 warps (2m x 4n), BK=32, bf16-split 3-term.
// ---------------------------------------------------------------------------
constexpr int TSTR = 80;
constexpr int GT   = 128 * TSTR;   // bytes per tile (10240)
constexpr int GB   = 4 * GT;       // bytes per buffer (40960)

#define GEMM_PIPE(AhiP, AloP, BhiP, BloP)                                       \
    extern __shared__ char smc[];                                               \
    const uint32_t sbase = smem_u32(smc);                                       \
    const int tid  = threadIdx.x;                                               \
    const int wid  = tid >> 5;                                                  \
    const int lane = tid & 31;                                                  \
    const int wm = wid >> 2, wn = wid & 3;                                      \
    const int lrow = tid >> 1, lhalf = tid & 1;                                 \
    const __nv_bfloat16* gsrc[4] = {                                            \
        (AhiP) + (size_t)(m0 + lrow) * D_MODEL + lhalf * 16,                    \
        (AloP) + (size_t)(m0 + lrow) * D_MODEL + lhalf * 16,                    \
        (BhiP) + (size_t)(n0 + lrow) * D_MODEL + lhalf * 16,                    \
        (BloP) + (size_t)(n0 + lrow) * D_MODEL + lhalf * 16 };                  \
    const int lA_row = lane & 15, lA_kb = (lane >> 4) * 16;                     \
    const int lB_row = (lane & 7) + ((lane >> 4) << 3);                         \
    const int lB_kb  = ((lane >> 3) & 1) * 16;                                  \
    const uint32_t ro = lrow * TSTR + lhalf * 32;                               \
    float acc[4][4][4];                                                         \
    _Pragma("unroll")                                                           \
    for (int mi = 0; mi < 4; mi++)                                              \
        _Pragma("unroll")                                                       \
        for (int nf = 0; nf < 4; nf++)                                          \
            _Pragma("unroll")                                                   \
            for (int r = 0; r < 4; r++) acc[mi][nf][r] = 0.f;                   \
    _Pragma("unroll")                                                           \
    for (int t = 0; t < 4; t++) {                                               \
        CP16(sbase + t * GT + ro,      gsrc[t]);                                \
        CP16(sbase + t * GT + ro + 16, gsrc[t] + 8);                            \
    }                                                                           \
    CP_COMMIT();                                                                \
    for (int c = 0; c < 32; ++c) {                                              \
        CP_WAIT0();                                                             \
        __syncthreads();                                                        \
        if (c + 1 < 32) {                                                       \
            const uint32_t db = sbase + ((c + 1) & 1) * GB;                     \
            _Pragma("unroll")                                                   \
            for (int t = 0; t < 4; t++) {                                       \
                CP16(db + t * GT + ro,      gsrc[t] + (c + 1) * 32);            \
                CP16(db + t * GT + ro + 16, gsrc[t] + (c + 1) * 32 + 8);        \
            }                                                                   \
            CP_COMMIT();                                                        \
        }                                                                       \
        const uint32_t cb = sbase + (c & 1) * GB;                               \
        _Pragma("unroll")                                                       \
        for (int ks = 0; ks < 2; ks++) {                                        \
            const int kb = ks * 32;                                             \
            uint32_t bh[2][4], bl[2][4];                                        \
            _Pragma("unroll")                                                   \
            for (int g = 0; g < 2; g++) {                                       \
                const uint32_t brel = (wn * 32 + g * 16 + lB_row) * TSTR + kb + lB_kb; \
                ldsm4(bh[g], cb + 2 * GT + brel);                               \
                ldsm4(bl[g], cb + 3 * GT + brel);                               \
            }                                                                   \
            _Pragma("unroll")                                                   \
            for (int mi = 0; mi < 4; mi++) {                                    \
                uint32_t ah[4], al[4];                                          \
                const uint32_t arel = (wm * 64 + mi * 16 + lA_row) * TSTR + kb + lA_kb; \
                ldsm4(ah, cb + arel);                                           \
                ldsm4(al, cb + GT + arel);                                      \
                _Pragma("unroll")                                               \
                for (int nf = 0; nf < 4; nf++) {                                \
                    const uint32_t* bhf = &bh[nf >> 1][(nf & 1) * 2];           \
                    const uint32_t* blf = &bl[nf >> 1][(nf & 1) * 2];           \
                    mma16816(acc[mi][nf], ah, bhf);                             \
                    mma16816(acc[mi][nf], ah, blf);                             \
                    mma16816(acc[mi][nf], al, bhf);                             \
                }                                                               \
            }                                                                   \
        }                                                                       \
    }

// Fused QKV projection: wsel = blockIdx.x/8 selects weight/bias/epilogue.
__global__ void __launch_bounds__(256, 2)
gemm_qkv(const __nv_bfloat16* __restrict__ xhi_, const __nv_bfloat16* __restrict__ xlo_,
         const __nv_bfloat16* __restrict__ whi_, const __nv_bfloat16* __restrict__ wlo_,
         const float* __restrict__ bqp, const float* __restrict__ bkp,
         const float* __restrict__ bvp,
         __nv_bfloat16* __restrict__ qhi_, __nv_bfloat16* __restrict__ qlo_,
         __nv_bfloat16* __restrict__ khi_, __nv_bfloat16* __restrict__ klo_,
         __nv_bfloat16* __restrict__ vhi_, __nv_bfloat16* __restrict__ vlo_)
{
    const int wsel = blockIdx.x >> 3;
    const int n0   = (blockIdx.x & 7) * 128;
    const int m0   = blockIdx.y * 128;
    const __nv_bfloat16* Bh = whi_ + (size_t)wsel * (D_MODEL * D_MODEL);
    const __nv_bfloat16* Bl = wlo_ + (size_t)wsel * (D_MODEL * D_MODEL);
    const float* bias = (wsel == 0) ? bqp : (wsel == 1) ? bkp : bvp;
    const float scale = (wsel == 0) ? 0.125f : 1.0f;

    GEMM_PIPE(xhi_, xlo_, Bh, Bl)

    __nv_bfloat16* Dhi = (wsel == 0) ? qhi_ : (wsel == 1) ? khi_ : vhi_;
    __nv_bfloat16* Dlo = (wsel == 0) ? qlo_ : (wsel == 1) ? klo_ : vlo_;

    #pragma unroll
    for (int mi = 0; mi < 4; mi++) {
        const int r0 = m0 + wm * 64 + mi * 16 + (lane >> 2);
        const int b  = r0 >> 11;
        const int s0 = r0 & (SEQ - 1);
        #pragma unroll
        for (int nf = 0; nf < 4; nf++) {
            const int n  = n0 + wn * 32 + nf * 8 + (lane & 3) * 2;
            const float b0 = __ldg(bias + n);
            const float b1 = __ldg(bias + n + 1);
            const float v00 = (acc[mi][nf][0] + b0) * scale;
            const float v01 = (acc[mi][nf][1] + b1) * scale;
            const float v10 = (acc[mi][nf][2] + b0) * scale;
            const float v11 = (acc[mi][nf][3] + b1) * scale;
            const int hd = n >> 6, d = n & 63;
            __nv_bfloat16 h00, l00, h01, l01, h10, l10, h11, l11;
            split1(v00, h00, l00); split1(v01, h01, l01);
            split1(v10, h10, l10); split1(v11, h11, l11);
            if (wsel < 2) {
                const size_t base = ((size_t)(b * H + hd) * SEQ + s0) * DKH + d;
                *(__nv_bfloat162*)(Dhi + base) = __nv_bfloat162(h00, h01);
                *(__nv_bfloat162*)(Dlo + base) = __nv_bfloat162(l00, l01);
                *(__nv_bfloat162*)(Dhi + base + 8 * DKH) = __nv_bfloat162(h10, h11);
                *(__nv_bfloat162*)(Dlo + base + 8 * DKH) = __nv_bfloat162(l10, l11);
            } else {
                const size_t base = ((size_t)(b * H + hd) * DKH + d) * SEQ + s0;
                Dhi[base]           = h00; Dlo[base]           = l00;
                Dhi[base + SEQ]     = h01; Dlo[base + SEQ]     = l01;
                Dhi[base + 8]       = h10; Dlo[base + 8]       = l10;
                Dhi[base + SEQ + 8] = h11; Dlo[base + SEQ + 8] = l11;
            }
        }
    }
}

__global__ void __launch_bounds__(256, 2)
gemm_out(const __nv_bfloat16* __restrict__ Ahi, const __nv_bfloat16* __restrict__ Alo,
         const __nv_bfloat16* __restrict__ Bhi, const __nv_bfloat16* __restrict__ Blo,
         const float* __restrict__ bias, float* __restrict__ C)
{
    const int m0 = blockIdx.y * 128;
    const int n0 = blockIdx.x * 128;

    GEMM_PIPE(Ahi, Alo, Bhi, Blo)

    #pragma unroll
    for (int mi = 0; mi < 4; mi++) {
        const int r0 = m0 + wm * 64 + mi * 16 + (lane >> 2);
        #pragma unroll
        for (int nf = 0; nf < 4; nf++) {
            const int n = n0 + wn * 32 + nf * 8 + (lane & 3) * 2;
            const float b0 = __ldg(bias + n);
            const float b1 = __ldg(bias + n + 1);
            float2 lo2, hi2;
            lo2.x = acc[mi][nf][0] + b0;
            lo2.y = acc[mi][nf][1] + b1;
            hi2.x = acc[mi][nf][2] + b0;
            hi2.y = acc[mi][nf][3] + b1;
            *(float2*)(C + (size_t)r0 * D_MODEL + n)       = lo2;
            *(float2*)(C + (size_t)(r0 + 8) * D_MODEL + n) = hi2;
        }
    }
}

// ---------------------------------------------------------------------------
// Tensor-core flash attention, cp.async double-buffered K/V, 2 CTAs/SM.
// CTA = 128 q-rows of one (b,h); 8 warps x m16. KV tiled 64 keys.
// Fragment loops restructured group-wise (8 live regs) to fit the 128-reg cap.
// ---------------------------------------------------------------------------
constexpr int FSR = 144;              // smem row stride (64 bf16 rows)
constexpr int KVT = 64 * FSR;         // one KV tile (9216 B)
constexpr int KVB = 4 * KVT;          // Kh,Kl,Vh,Vl buffer (36864 B)

#define FLASH_KV_ISSUE(bufbase, c0_)                                            \
    {                                                                           \
        const int row = tid >> 2, q4 = tid & 3;                                 \
        const __nv_bfloat16* gk  = khi + boff + (size_t)((c0_) + row) * DKH + q4 * 16; \
        const __nv_bfloat16* gkl = klo + boff + (size_t)((c0_) + row) * DKH + q4 * 16; \
        const __nv_bfloat16* gv  = vhi + boff + (size_t)row * SEQ + (c0_) + q4 * 16;   \
        const __nv_bfloat16* gvl = vlo + boff + (size_t)row * SEQ + (c0_) + q4 * 16;   \
        const uint32_t kro = row * FSR + q4 * 32;                               \
        CP16((bufbase) + 0 * KVT + kro,      gk);                               \
        CP16((bufbase) + 0 * KVT + kro + 16, gk + 8);                           \
        CP16((bufbase) + 1 * KVT + kro,      gkl);                              \
        CP16((bufbase) + 1 * KVT + kro + 16, gkl + 8);                          \
        CP16((bufbase) + 2 * KVT + kro,      gv);                               \
        CP16((bufbase) + 2 * KVT + kro + 16, gv + 8);                           \
        CP16((bufbase) + 3 * KVT + kro,      gvl);                              \
        CP16((bufbase) + 3 * KVT + kro + 16, gvl + 8);                          \
    }

__global__ void __launch_bounds__(256, 2)
flash_mma(const __nv_bfloat16* __restrict__ qhi, const __nv_bfloat16* __restrict__ qlo,
          const __nv_bfloat16* __restrict__ khi, const __nv_bfloat16* __restrict__ klo,
          const __nv_bfloat16* __restrict__ vhi, const __nv_bfloat16* __restrict__ vlo,
          __nv_bfloat16* __restrict__ chi, __nv_bfloat16* __restrict__ clo)
{
    extern __shared__ char fsm[];
    char* sQh = fsm;
    char* sQl = fsm + 128 * FSR;
    const uint32_t bQh = smem_u32(sQh);
    const uint32_t bQl = smem_u32(sQl);
    const uint32_t bKV = bQh + 2 * 128 * FSR;   // double KV buffer base

    const int tid  = threadIdx.x;
    const int lane = tid & 31;
    const int w    = tid >> 5;
    const int bh   = blockIdx.y;
    const int q0   = blockIdx.x * 128;
    const size_t boff = (size_t)bh * SEQ * DKH;

    // issue KV chunk 0 early
    FLASH_KV_ISSUE(bKV, 0);
    CP_COMMIT();

    // Q tile (128 x 64, hi/lo): 2 threads/row, 32 elems each
    {
        const int row = tid >> 1, half = tid & 1;
        const __nv_bfloat16* gq = qhi + boff + (size_t)(q0 + row) * DKH + half * 32;
        const __nv_bfloat16* gl = qlo + boff + (size_t)(q0 + row) * DKH + half * 32;
        #pragma unroll
        for (int i = 0; i < 4; i++) {
            *(uint4*)(sQh + row * FSR + half * 64 + i * 16) = *(const uint4*)(gq + i * 8);
            *(uint4*)(sQl + row * FSR + half * 64 + i * 16) = *(const uint4*)(gl + i * 8);
        }
    }
    __syncthreads();

    const int lA_row = lane & 15;
    const int lA_kb  = (lane >> 4) * 16;
    const int lB_row = (lane & 7) + ((lane >> 4) << 3);
    const int lB_kb  = ((lane >> 3) & 1) * 16;

    uint32_t qfh[4][4], qfl[4][4];
    #pragma unroll
    for (int kc2 = 0; kc2 < 4; kc2++) {
        const uint32_t arel = (w * 16 + lA_row) * FSR + kc2 * 32 + lA_kb;
        ldsm4(qfh[kc2], bQh + arel);
        ldsm4(qfl[kc2], bQl + arel);
    }

    float o[8][4];
    #pragma unroll
    for (int nf = 0; nf < 8; nf++)
        #pragma unroll
        for (int r = 0; r < 4; r++) o[nf][r] = 0.f;
    float mrow0 = -1e30f, mrow1 = -1e30f, lrow0 = 0.f, lrow1 = 0.f;

    for (int kt = 0; kt < SEQ / 64; kt++) {
        CP_WAIT0();
        __syncthreads();
        if (kt + 1 < SEQ / 64) {
            FLASH_KV_ISSUE(bKV + ((kt + 1) & 1) * KVB, (kt + 1) * 64);
            CP_COMMIT();
        }
        const uint32_t cb  = bKV + (kt & 1) * KVB;
        const uint32_t bKh = cb;
        const uint32_t bKl = cb + KVT;
        const uint32_t bVh = cb + 2 * KVT;
        const uint32_t bVl = cb + 3 * KVT;

        // ---- S = Q K^T (m16 x n64), 3-term split; group-wise fragments ----
        float s[8][4];
        #pragma unroll
        for (int nf = 0; nf < 8; nf++)
            #pragma unroll
            for (int r = 0; r < 4; r++) s[nf][r] = 0.f;

        #pragma unroll
        for (int kc2 = 0; kc2 < 4; kc2++) {
            #pragma unroll
            for (int g = 0; g < 4; g++) {
                uint32_t kbh[4], kbl[4];
                const uint32_t brel = (g * 16 + lB_row) * FSR + kc2 * 32 + lB_kb;
                ldsm4(kbh, bKh + brel);
                ldsm4(kbl, bKl + brel);
                #pragma unroll
                for (int j = 0; j < 2; j++) {
                    const int nf = 2 * g + j;
                    mma16816(s[nf], qfh[kc2], &kbh[j * 2]);
                    mma16816(s[nf], qfh[kc2], &kbl[j * 2]);
                    mma16816(s[nf], qfl[kc2], &kbh[j * 2]);
                }
            }
        }

        // ---- online softmax on fragments ----
        float m0n = -1e30f, m1n = -1e30f;
        #pragma unroll
        for (int nf = 0; nf < 8; nf++) {
            m0n = fmaxf(m0n, fmaxf(s[nf][0], s[nf][1]));
            m1n = fmaxf(m1n, fmaxf(s[nf][2], s[nf][3]));
        }
        #pragma unroll
        for (int off = 1; off <= 2; off <<= 1) {
            m0n = fmaxf(m0n, __shfl_xor_sync(0xffffffffu, m0n, off));
            m1n = fmaxf(m1n, __shfl_xor_sync(0xffffffffu, m1n, off));
        }
        const float M0 = fmaxf(mrow0, m0n);
        const float M1 = fmaxf(mrow1, m1n);
        const float a0 = __expf(mrow0 - M0);
        const float a1 = __expf(mrow1 - M1);
        mrow0 = M0; mrow1 = M1;
        float rs0 = 0.f, rs1 = 0.f;
        #pragma unroll
        for (int nf = 0; nf < 8; nf++) {
            s[nf][0] = __expf(s[nf][0] - M0); rs0 += s[nf][0];
            s[nf][1] = __expf(s[nf][1] - M0); rs0 += s[nf][1];
            s[nf][2] = __expf(s[nf][2] - M1); rs1 += s[nf][2];
            s[nf][3] = __expf(s[nf][3] - M1); rs1 += s[nf][3];
        }
        #pragma unroll
        for (int off = 1; off <= 2; off <<= 1) {
            rs0 += __shfl_xor_sync(0xffffffffu, rs0, off);
            rs1 += __shfl_xor_sync(0xffffffffu, rs1, off);
        }
        lrow0 = lrow0 * a0 + rs0;
        lrow1 = lrow1 * a1 + rs1;
        #pragma unroll
        for (int nf = 0; nf < 8; nf++) {
            o[nf][0] *= a0; o[nf][1] *= a0;
            o[nf][2] *= a1; o[nf][3] *= a1;
        }

        // ---- O += P V, group-wise fragments (P packed hi/lo on the fly) ----
        #pragma unroll
        for (int pc = 0; pc < 4; pc++) {
            uint32_t pfh[4], pfl[4];
            pack_split(s[2 * pc][0],     s[2 * pc][1],     pfh[0], pfl[0]);
            pack_split(s[2 * pc][2],     s[2 * pc][3],     pfh[1], pfl[1]);
            pack_split(s[2 * pc + 1][0], s[2 * pc + 1][1], pfh[2], pfl[2]);
            pack_split(s[2 * pc + 1][2], s[2 * pc + 1][3], pfh[3], pfl[3]);
            #pragma unroll
            for (int g = 0; g < 4; g++) {
                uint32_t vbh[4], vbl[4];
                const uint32_t brel = (g * 16 + lB_row) * FSR + pc * 32 + lB_kb;
                ldsm4(vbh, bVh + brel);
                ldsm4(vbl, bVl + brel);
                #pragma unroll
                for (int j = 0; j < 2; j++) {
                    const int nf = 2 * g + j;
                    mma16816(o[nf], pfh, &vbh[j * 2]);
                    mma16816(o[nf], pfh, &vbl[j * 2]);
                    mma16816(o[nf], pfl, &vbh[j * 2]);
                }
            }
        }
    }

    // ---- epilogue ----
    const float inv0 = 1.0f / lrow0;
    const float inv1 = 1.0f / lrow1;
    const int b  = bh >> 4;
    const int hh = bh & 15;
    const int row0 = q0 + w * 16 + (lane >> 2);
    #pragma unroll
    for (int nf = 0; nf < 8; nf++) {
        const int d = hh * 64 + nf * 8 + (lane & 3) * 2;
        __nv_bfloat16 h00, l00, h01, l01, h10, l10, h11, l11;
        split1(o[nf][0] * inv0, h00, l00);
        split1(o[nf][1] * inv0, h01, l01);
        split1(o[nf][2] * inv1, h10, l10);
        split1(o[nf][3] * inv1, h11, l11);
        const size_t base0 = ((size_t)b * SEQ + row0) * D_MODEL + d;
        const size_t base1 = base0 + 8 * D_MODEL;
        *(__nv_bfloat162*)(chi + base0) = __nv_bfloat162(h00, h01);
        *(__nv_bfloat162*)(clo + base0) = __nv_bfloat162(l00, l01);
        *(__nv_bfloat162*)(chi + base1) = __nv_bfloat162(h10, h11);
        *(__nv_bfloat162*)(clo + base1) = __nv_bfloat162(l10, l11);
    }
}

// ---------------------------------------------------------------------------
extern "C" void kernel_launch(void* const* d_in, const int* in_sizes, int n_in,
                              void* d_out, int out_size)
{
    const float* x  = (const float*)d_in[0];
    const float* Wq = (const float*)d_in[1];
    const float* bq = (const float*)d_in[2];
    const float* Wk = (const float*)d_in[3];
    const float* bk = (const float*)d_in[4];
    const float* Wv = (const float*)d_in[5];
    const float* bv = (const float*)d_in[6];
    const float* Wo = (const float*)d_in[7];
    const float* bo = (const float*)d_in[8];
    float* out = (float*)d_out;

    __nv_bfloat16 *xhi, *xlo, *whi, *wlo;
    __nv_bfloat16 *qhi, *qlo, *khi, *klo, *vhi, *vlo, *chi, *clo;
    cudaGetSymbolAddress((void**)&xhi, g_xhi);
    cudaGetSymbolAddress((void**)&xlo, g_xlo);
    cudaGetSymbolAddress((void**)&whi, g_whi);
    cudaGetSymbolAddress((void**)&wlo, g_wlo);
    cudaGetSymbolAddress((void**)&qhi, g_qhi);
    cudaGetSymbolAddress((void**)&qlo, g_qlo);
    cudaGetSymbolAddress((void**)&khi, g_khi);
    cudaGetSymbolAddress((void**)&klo, g_klo);
    cudaGetSymbolAddress((void**)&vhi, g_vhi);
    cudaGetSymbolAddress((void**)&vlo, g_vlo);
    cudaGetSymbolAddress((void**)&chi, g_chi);
    cudaGetSymbolAddress((void**)&clo, g_clo);

    const int WSZ = D_MODEL * D_MODEL;
    const int xn4 = MROWS * D_MODEL / 4;
    const int wn4 = WSZ / 4;

    split_bf16<<<(xn4 + 255) / 256, 256>>>((const float4*)x,
        (uint2*)xhi, (uint2*)xlo, xn4);
    split_w4<<<4 * (wn4 / 256), 256>>>((const float4*)Wq, (const float4*)Wk,
        (const float4*)Wv, (const float4*)Wo, (uint2*)whi, (uint2*)wlo, wn4);

    const int gsmem = 2 * GB;   // 81920
    cudaFuncSetAttribute(gemm_qkv, cudaFuncAttributeMaxDynamicSharedMemorySize, gsmem);
    cudaFuncSetAttribute(gemm_out, cudaFuncAttributeMaxDynamicSharedMemorySize, gsmem);

    gemm_qkv<<<dim3(24, MROWS / 128), 256, gsmem>>>(xhi, xlo, whi, wlo,
        bq, bk, bv, qhi, qlo, khi, klo, vhi, vlo);

    const int fsmem = 2 * 128 * FSR + 2 * KVB;   // 110592
    cudaFuncSetAttribute(flash_mma, cudaFuncAttributeMaxDynamicSharedMemorySize, fsmem);
    flash_mma<<<dim3(SEQ / 128, BATCH * H), 256, fsmem>>>(qhi, qlo, khi, klo,
                                                          vhi, vlo, chi, clo);

    gemm_out<<<dim3(D_MODEL / 128, MROWS / 128), 256, gsmem>>>(
        chi, clo, whi + 3 * (size_t)WSZ, wlo + 3 * (size_t)WSZ, bo, out);
}

// round 12
// speedup vs baseline: 3.0299x; 1.0003x over previous
#include <cuda_runtime.h>
#include <cuda_bf16.h>
#include <cstdint>

// ---------------------------------------------------------------------------
// MultiHeadAttention: x[B,S,D] -> out[B,S,D]
// B=4, S=2048, D=1024, H=16, dk=64
//   0) split fp32 -> bf16 (hi, lo): x (1 launch), 4 weights (1 fused launch)
//   1) gemm_qkv (fused): Q/K -> bf16 hi/lo [b,h,s,dk] (Q scaled 1/8),
//                        V   -> bf16 hi/lo [b,h,dk,s] (transposed)
//   2) flash_mma : tensor-core flash attention (mma.sync bf16-split),
//                  cp.async double-buffered K/V; ctx out as bf16 hi/lo
//   3) gemm_out  : out = ctx @ Wo^T + bo  (fp32)
// A*B ~= Ahi*Bhi + Ahi*Blo + Alo*Bhi (fp32 accum) -> ~1e-5 rel err.
// All heavy kernels run 2 CTAs/SM (launch_bounds 256,2) for tensor-pipe overlap.
// Target plain sm_100: mma.sync + ldmatrix + cp.async.
// ---------------------------------------------------------------------------

constexpr int D_MODEL = 1024;
constexpr int H       = 16;
constexpr int DKH     = 64;
constexpr int SEQ     = 2048;
constexpr int BATCH   = 4;
constexpr int MROWS   = BATCH * SEQ;      // 8192

__device__ __nv_bfloat16 g_xhi[MROWS * D_MODEL];
__device__ __nv_bfloat16 g_xlo[MROWS * D_MODEL];
__device__ __nv_bfloat16 g_whi[4][D_MODEL * D_MODEL];
__device__ __nv_bfloat16 g_wlo[4][D_MODEL * D_MODEL];
__device__ __nv_bfloat16 g_qhi[BATCH * H * SEQ * DKH];
__device__ __nv_bfloat16 g_qlo[BATCH * H * SEQ * DKH];
__device__ __nv_bfloat16 g_khi[BATCH * H * SEQ * DKH];
__device__ __nv_bfloat16 g_klo[BATCH * H * SEQ * DKH];
__device__ __nv_bfloat16 g_vhi[BATCH * H * DKH * SEQ];   // transposed
__device__ __nv_bfloat16 g_vlo[BATCH * H * DKH * SEQ];
__device__ __nv_bfloat16 g_chi[MROWS * D_MODEL];
__device__ __nv_bfloat16 g_clo[MROWS * D_MODEL];

// ---------------- helpers ----------------
__device__ __forceinline__ uint32_t smem_u32(const void* p) {
    uint32_t a;
    asm("{ .reg .u64 t; cvta.to.shared.u64 t, %1; cvt.u32.u64 %0, t; }"
        : "=r"(a) : "l"(p));
    return a;
}
__device__ __forceinline__ void ldsm4(uint32_t* r, uint32_t addr) {
    asm volatile("ldmatrix.sync.aligned.m8n8.x4.shared.b16 {%0,%1,%2,%3}, [%4];"
        : "=r"(r[0]), "=r"(r[1]), "=r"(r[2]), "=r"(r[3]) : "r"(addr));
}
__device__ __forceinline__ void mma16816(float* c, const uint32_t* a,
                                         const uint32_t* b) {
    asm volatile(
        "mma.sync.aligned.m16n8k16.row.col.f32.bf16.bf16.f32 "
        "{%0,%1,%2,%3}, {%4,%5,%6,%7}, {%8,%9}, {%0,%1,%2,%3};"
        : "+f"(c[0]), "+f"(c[1]), "+f"(c[2]), "+f"(c[3])
        : "r"(a[0]), "r"(a[1]), "r"(a[2]), "r"(a[3]), "r"(b[0]), "r"(b[1]));
}
__device__ __forceinline__ void split1(float v, __nv_bfloat16& h, __nv_bfloat16& l) {
    h = __float2bfloat16_rn(v);
    l = __float2bfloat16_rn(v - __bfloat162float(h));
}
__device__ __forceinline__ void pack_split(float e, float o, uint32_t& hr, uint32_t& lr) {
    __nv_bfloat16 he, le, ho, lo;
    split1(e, he, le);
    split1(o, ho, lo);
    hr = (uint32_t)__bfloat16_as_ushort(he) | ((uint32_t)__bfloat16_as_ushort(ho) << 16);
    lr = (uint32_t)__bfloat16_as_ushort(le) | ((uint32_t)__bfloat16_as_ushort(lo) << 16);
}
#define CP16(dst, src) \
    asm volatile("cp.async.cg.shared.global [%0], [%1], 16;" :: "r"(dst), "l"(src))
#define CP_COMMIT() asm volatile("cp.async.commit_group;" ::: "memory")
#define CP_WAIT0()  asm volatile("cp.async.wait_group 0;"  ::: "memory")

// ---------------------------------------------------------------------------
// split fp32 -> (bf16 hi, bf16 lo)
// ---------------------------------------------------------------------------
__global__ void __launch_bounds__(256)
split_bf16(const float4* __restrict__ src, uint2* __restrict__ hi,
           uint2* __restrict__ lo, int n4)
{
    const int i = blockIdx.x * 256 + threadIdx.x;
    if (i >= n4) return;
    float4 v = src[i];
    __nv_bfloat16 h0, l0, h1, l1, h2, l2, h3, l3;
    split1(v.x, h0, l0); split1(v.y, h1, l1);
    split1(v.z, h2, l2); split1(v.w, h3, l3);
    uint2 hw, lw;
    hw.x = (uint32_t)__bfloat16_as_ushort(h0) | ((uint32_t)__bfloat16_as_ushort(h1) << 16);
    hw.y = (uint32_t)__bfloat16_as_ushort(h2) | ((uint32_t)__bfloat16_as_ushort(h3) << 16);
    lw.x = (uint32_t)__bfloat16_as_ushort(l0) | ((uint32_t)__bfloat16_as_ushort(l1) << 16);
    lw.y = (uint32_t)__bfloat16_as_ushort(l2) | ((uint32_t)__bfloat16_as_ushort(l3) << 16);
    hi[i] = hw;
    lo[i] = lw;
}

// fused split for the 4 weight matrices (each WSZ elements)
__global__ void __launch_bounds__(256)
split_w4(const float4* __restrict__ w0, const float4* __restrict__ w1,
         const float4* __restrict__ w2, const float4* __restrict__ w3,
         uint2* __restrict__ hi, uint2* __restrict__ lo, int wn4)
{
    const int bpw = wn4 / 256;               // blocks per weight
    const int w   = blockIdx.x / bpw;
    const int i   = (blockIdx.x - w * bpw) * 256 + threadIdx.x;
    const float4* src = (w == 0) ? w0 : (w == 1) ? w1 : (w == 2) ? w2 : w3;
    float4 v = src[i];
    __nv_bfloat16 h0, l0, h1, l1, h2, l2, h3, l3;
    split1(v.x, h0, l0); split1(v.y, h1, l1);
    split1(v.z, h2, l2); split1(v.w, h3, l3);
    uint2 hw, lw;
    hw.x = (uint32_t)__bfloat16_as_ushort(h0) | ((uint32_t)__bfloat16_as_ushort(h1) << 16);
    hw.y = (uint32_t)__bfloat16_as_ushort(h2) | ((uint32_t)__bfloat16_as_ushort(h3) << 16);
    lw.x = (uint32_t)__bfloat16_as_ushort(l0) | ((uint32_t)__bfloat16_as_ushort(l1) << 16);
    lw.y = (uint32_t)__bfloat16_as_ushort(l2) | ((uint32_t)__bfloat16_as_ushort(l3) << 16);
    hi[(size_t)w * wn4 + i] = hw;
    lo[(size_t)w * wn4 + i] = lw;
}

// ---------------------------------------------------------------------------
// HMMA GEMM pipelined mainloop (cp.async double buffer), 2 CTAs/SM.
// CTA 128x128, 8 warps (2m x 4n), BK=32, bf16-split 3-term.
// ---------------------------------------------------------------------------
constexpr int TSTR = 80;
constexpr int GT   = 128 * TSTR;   // bytes per tile (10240)
constexpr int GB   = 4 * GT;       // bytes per buffer (40960)

#define GEMM_PIPE(AhiP, AloP, BhiP, BloP)                                       \
    extern __shared__ char smc[];                                               \
    const uint32_t sbase = smem_u32(smc);                                       \
    const int tid  = threadIdx.x;                                               \
    const int wid  = tid >> 5;                                                  \
    const int lane = tid & 31;                                                  \
    const int wm = wid >> 2, wn = wid & 3;                                      \
    const int lrow = tid >> 1, lhalf = tid & 1;                                 \
    const __nv_bfloat16* gsrc[4] = {                                            \
        (AhiP) + (size_t)(m0 + lrow) * D_MODEL + lhalf * 16,                    \
        (AloP) + (size_t)(m0 + lrow) * D_MODEL + lhalf * 16,                    \
        (BhiP) + (size_t)(n0 + lrow) * D_MODEL + lhalf * 16,                    \
        (BloP) + (size_t)(n0 + lrow) * D_MODEL + lhalf * 16 };                  \
    const int lA_row = lane & 15, lA_kb = (lane >> 4) * 16;                     \
    const int lB_row = (lane & 7) + ((lane >> 4) << 3);                         \
    const int lB_kb  = ((lane >> 3) & 1) * 16;                                  \
    const uint32_t ro = lrow * TSTR + lhalf * 32;                               \
    float acc[4][4][4];                                                         \
    _Pragma("unroll")                                                           \
    for (int mi = 0; mi < 4; mi++)                                              \
        _Pragma("unroll")                                                       \
        for (int nf = 0; nf < 4; nf++)                                          \
            _Pragma("unroll")                                                   \
            for (int r = 0; r < 4; r++) acc[mi][nf][r] = 0.f;                   \
    _Pragma("unroll")                                                           \
    for (int t = 0; t < 4; t++) {                                               \
        CP16(sbase + t * GT + ro,      gsrc[t]);                                \
        CP16(sbase + t * GT + ro + 16, gsrc[t] + 8);                            \
    }                                                                           \
    CP_COMMIT();                                                                \
    for (int c = 0; c < 32; ++c) {                                              \
        CP_WAIT0();                                                             \
        __syncthreads();                                                        \
        if (c + 1 < 32) {                                                       \
            const uint32_t db = sbase + ((c + 1) & 1) * GB;                     \
            _Pragma("unroll")                                                   \
            for (int t = 0; t < 4; t++) {                                       \
                CP16(db + t * GT + ro,      gsrc[t] + (c + 1) * 32);            \
                CP16(db + t * GT + ro + 16, gsrc[t] + (c + 1) * 32 + 8);        \
            }                                                                   \
            CP_COMMIT();                                                        \
        }                                                                       \
        const uint32_t cb = sbase + (c & 1) * GB;                               \
        _Pragma("unroll")                                                       \
        for (int ks = 0; ks < 2; ks++) {                                        \
            const int kb = ks * 32;                                             \
            uint32_t bh[2][4], bl[2][4];                                        \
            _Pragma("unroll")                                                   \
            for (int g = 0; g < 2; g++) {                                       \
                const uint32_t brel = (wn * 32 + g * 16 + lB_row) * TSTR + kb + lB_kb; \
                ldsm4(bh[g], cb + 2 * GT + brel);                               \
                ldsm4(bl[g], cb + 3 * GT + brel);                               \
            }                                                                   \
            _Pragma("unroll")                                                   \
            for (int mi = 0; mi < 4; mi++) {                                    \
                uint32_t ah[4], al[4];                                          \
                const uint32_t arel = (wm * 64 + mi * 16 + lA_row) * TSTR + kb + lA_kb; \
                ldsm4(ah, cb + arel);                                           \
                ldsm4(al, cb + GT + arel);                                      \
                _Pragma("unroll")                                               \
                for (int nf = 0; nf < 4; nf++) {                                \
                    const uint32_t* bhf = &bh[nf >> 1][(nf & 1) * 2];           \
                    const uint32_t* blf = &bl[nf >> 1][(nf & 1) * 2];           \
                    mma16816(acc[mi][nf], ah, bhf);                             \
                    mma16816(acc[mi][nf], ah, blf);                             \
                    mma16816(acc[mi][nf], al, bhf);                             \
                }                                                               \
            }                                                                   \
        }                                                                       \
    }

// Fused QKV projection: wsel = blockIdx.x/8 selects weight/bias/epilogue.
__global__ void __launch_bounds__(256, 2)
gemm_qkv(const __nv_bfloat16* __restrict__ xhi_, const __nv_bfloat16* __restrict__ xlo_,
         const __nv_bfloat16* __restrict__ whi_, const __nv_bfloat16* __restrict__ wlo_,
         const float* __restrict__ bqp, const float* __restrict__ bkp,
         const float* __restrict__ bvp,
         __nv_bfloat16* __restrict__ qhi_, __nv_bfloat16* __restrict__ qlo_,
         __nv_bfloat16* __restrict__ khi_, __nv_bfloat16* __restrict__ klo_,
         __nv_bfloat16* __restrict__ vhi_, __nv_bfloat16* __restrict__ vlo_)
{
    const int wsel = blockIdx.x >> 3;
    const int n0   = (blockIdx.x & 7) * 128;
    const int m0   = blockIdx.y * 128;
    const __nv_bfloat16* Bh = whi_ + (size_t)wsel * (D_MODEL * D_MODEL);
    const __nv_bfloat16* Bl = wlo_ + (size_t)wsel * (D_MODEL * D_MODEL);
    const float* bias = (wsel == 0) ? bqp : (wsel == 1) ? bkp : bvp;
    const float scale = (wsel == 0) ? 0.125f : 1.0f;

    GEMM_PIPE(xhi_, xlo_, Bh, Bl)

    __nv_bfloat16* Dhi = (wsel == 0) ? qhi_ : (wsel == 1) ? khi_ : vhi_;
    __nv_bfloat16* Dlo = (wsel == 0) ? qlo_ : (wsel == 1) ? klo_ : vlo_;

    #pragma unroll
    for (int mi = 0; mi < 4; mi++) {
        const int r0 = m0 + wm * 64 + mi * 16 + (lane >> 2);
        const int b  = r0 >> 11;
        const int s0 = r0 & (SEQ - 1);
        #pragma unroll
        for (int nf = 0; nf < 4; nf++) {
            const int n  = n0 + wn * 32 + nf * 8 + (lane & 3) * 2;
            const float b0 = __ldg(bias + n);
            const float b1 = __ldg(bias + n + 1);
            const float v00 = (acc[mi][nf][0] + b0) * scale;
            const float v01 = (acc[mi][nf][1] + b1) * scale;
            const float v10 = (acc[mi][nf][2] + b0) * scale;
            const float v11 = (acc[mi][nf][3] + b1) * scale;
            const int hd = n >> 6, d = n & 63;
            __nv_bfloat16 h00, l00, h01, l01, h10, l10, h11, l11;
            split1(v00, h00, l00); split1(v01, h01, l01);
            split1(v10, h10, l10); split1(v11, h11, l11);
            if (wsel < 2) {
                const size_t base = ((size_t)(b * H + hd) * SEQ + s0) * DKH + d;
                *(__nv_bfloat162*)(Dhi + base) = __nv_bfloat162(h00, h01);
                *(__nv_bfloat162*)(Dlo + base) = __nv_bfloat162(l00, l01);
                *(__nv_bfloat162*)(Dhi + base + 8 * DKH) = __nv_bfloat162(h10, h11);
                *(__nv_bfloat162*)(Dlo + base + 8 * DKH) = __nv_bfloat162(l10, l11);
            } else {
                const size_t base = ((size_t)(b * H + hd) * DKH + d) * SEQ + s0;
                Dhi[base]           = h00; Dlo[base]           = l00;
                Dhi[base + SEQ]     = h01; Dlo[base + SEQ]     = l01;
                Dhi[base + 8]       = h10; Dlo[base + 8]       = l10;
                Dhi[base + SEQ + 8] = h11; Dlo[base + SEQ + 8] = l11;
            }
        }
    }
}

__global__ void __launch_bounds__(256, 2)
gemm_out(const __nv_bfloat16* __restrict__ Ahi, const __nv_bfloat16* __restrict__ Alo,
         const __nv_bfloat16* __restrict__ Bhi, const __nv_bfloat16* __restrict__ Blo,
         const float* __restrict__ bias, float* __restrict__ C)
{
    const int m0 = blockIdx.y * 128;
    const int n0 = blockIdx.x * 128;

    GEMM_PIPE(Ahi, Alo, Bhi, Blo)

    #pragma unroll
    for (int mi = 0; mi < 4; mi++) {
        const int r0 = m0 + wm * 64 + mi * 16 + (lane >> 2);
        #pragma unroll
        for (int nf = 0; nf < 4; nf++) {
            const int n = n0 + wn * 32 + nf * 8 + (lane & 3) * 2;
            const float b0 = __ldg(bias + n);
            const float b1 = __ldg(bias + n + 1);
            float2 lo2, hi2;
            lo2.x = acc[mi][nf][0] + b0;
            lo2.y = acc[mi][nf][1] + b1;
            hi2.x = acc[mi][nf][2] + b0;
            hi2.y = acc[mi][nf][3] + b1;
            *(float2*)(C + (size_t)r0 * D_MODEL + n)       = lo2;
            *(float2*)(C + (size_t)(r0 + 8) * D_MODEL + n) = hi2;
        }
    }
}

// ---------------------------------------------------------------------------
// Tensor-core flash attention, cp.async double-buffered K/V, 2 CTAs/SM.
// CTA = 128 q-rows of one (b,h); 8 warps x m16. KV tiled 64 keys.
// Fragment loops restructured group-wise (8 live regs) to fit the 128-reg cap.
// ---------------------------------------------------------------------------
constexpr int FSR = 144;              // smem row stride (64 bf16 rows)
constexpr int KVT = 64 * FSR;         // one KV tile (9216 B)
constexpr int KVB = 4 * KVT;          // Kh,Kl,Vh,Vl buffer (36864 B)

#define FLASH_KV_ISSUE(bufbase, c0_)                                            \
    {                                                                           \
        const int row = tid >> 2, q4 = tid & 3;                                 \
        const __nv_bfloat16* gk  = khi + boff + (size_t)((c0_) + row) * DKH + q4 * 16; \
        const __nv_bfloat16* gkl = klo + boff + (size_t)((c0_) + row) * DKH + q4 * 16; \
        const __nv_bfloat16* gv  = vhi + boff + (size_t)row * SEQ + (c0_) + q4 * 16;   \
        const __nv_bfloat16* gvl = vlo + boff + (size_t)row * SEQ + (c0_) + q4 * 16;   \
        const uint32_t kro = row * FSR + q4 * 32;                               \
        CP16((bufbase) + 0 * KVT + kro,      gk);                               \
        CP16((bufbase) + 0 * KVT + kro + 16, gk + 8);                           \
        CP16((bufbase) + 1 * KVT + kro,      gkl);                              \
        CP16((bufbase) + 1 * KVT + kro + 16, gkl + 8);                          \
        CP16((bufbase) + 2 * KVT + kro,      gv);                               \
        CP16((bufbase) + 2 * KVT + kro + 16, gv + 8);                           \
        CP16((bufbase) + 3 * KVT + kro,      gvl);                              \
        CP16((bufbase) + 3 * KVT + kro + 16, gvl + 8);                          \
    }

__global__ void __launch_bounds__(256, 2)
flash_mma(const __nv_bfloat16* __restrict__ qhi, const __nv_bfloat16* __restrict__ qlo,
          const __nv_bfloat16* __restrict__ khi, const __nv_bfloat16* __restrict__ klo,
          const __nv_bfloat16* __restrict__ vhi, const __nv_bfloat16* __restrict__ vlo,
          __nv_bfloat16* __restrict__ chi, __nv_bfloat16* __restrict__ clo)
{
    extern __shared__ char fsm[];
    char* sQh = fsm;
    char* sQl = fsm + 128 * FSR;
    const uint32_t bQh = smem_u32(sQh);
    const uint32_t bQl = smem_u32(sQl);
    const uint32_t bKV = bQh + 2 * 128 * FSR;   // double KV buffer base

    const int tid  = threadIdx.x;
    const int lane = tid & 31;
    const int w    = tid >> 5;
    const int bh   = blockIdx.y;
    const int q0   = blockIdx.x * 128;
    const size_t boff = (size_t)bh * SEQ * DKH;

    // issue KV chunk 0 early
    FLASH_KV_ISSUE(bKV, 0);
    CP_COMMIT();

    // Q tile (128 x 64, hi/lo): 2 threads/row, 32 elems each
    {
        const int row = tid >> 1, half = tid & 1;
        const __nv_bfloat16* gq = qhi + boff + (size_t)(q0 + row) * DKH + half * 32;
        const __nv_bfloat16* gl = qlo + boff + (size_t)(q0 + row) * DKH + half * 32;
        #pragma unroll
        for (int i = 0; i < 4; i++) {
            *(uint4*)(sQh + row * FSR + half * 64 + i * 16) = *(const uint4*)(gq + i * 8);
            *(uint4*)(sQl + row * FSR + half * 64 + i * 16) = *(const uint4*)(gl + i * 8);
        }
    }
    __syncthreads();

    const int lA_row = lane & 15;
    const int lA_kb  = (lane >> 4) * 16;
    const int lB_row = (lane & 7) + ((lane >> 4) << 3);
    const int lB_kb  = ((lane >> 3) & 1) * 16;

    uint32_t qfh[4][4], qfl[4][4];
    #pragma unroll
    for (int kc2 = 0; kc2 < 4; kc2++) {
        const uint32_t arel = (w * 16 + lA_row) * FSR + kc2 * 32 + lA_kb;
        ldsm4(qfh[kc2], bQh + arel);
        ldsm4(qfl[kc2], bQl + arel);
    }

    float o[8][4];
    #pragma unroll
    for (int nf = 0; nf < 8; nf++)
        #pragma unroll
        for (int r = 0; r < 4; r++) o[nf][r] = 0.f;
    float mrow0 = -1e30f, mrow1 = -1e30f, lrow0 = 0.f, lrow1 = 0.f;

    for (int kt = 0; kt < SEQ / 64; kt++) {
        CP_WAIT0();
        __syncthreads();
        if (kt + 1 < SEQ / 64) {
            FLASH_KV_ISSUE(bKV + ((kt + 1) & 1) * KVB, (kt + 1) * 64);
            CP_COMMIT();
        }
        const uint32_t cb  = bKV + (kt & 1) * KVB;
        const uint32_t bKh = cb;
        const uint32_t bKl = cb + KVT;
        const uint32_t bVh = cb + 2 * KVT;
        const uint32_t bVl = cb + 3 * KVT;

        // ---- S = Q K^T (m16 x n64), 3-term split; group-wise fragments ----
        float s[8][4];
        #pragma unroll
        for (int nf = 0; nf < 8; nf++)
            #pragma unroll
            for (int r = 0; r < 4; r++) s[nf][r] = 0.f;

        #pragma unroll
        for (int kc2 = 0; kc2 < 4; kc2++) {
            #pragma unroll
            for (int g = 0; g < 4; g++) {
                uint32_t kbh[4], kbl[4];
                const uint32_t brel = (g * 16 + lB_row) * FSR + kc2 * 32 + lB_kb;
                ldsm4(kbh, bKh + brel);
                ldsm4(kbl, bKl + brel);
                #pragma unroll
                for (int j = 0; j < 2; j++) {
                    const int nf = 2 * g + j;
                    mma16816(s[nf], qfh[kc2], &kbh[j * 2]);
                    mma16816(s[nf], qfh[kc2], &kbl[j * 2]);
                    mma16816(s[nf], qfl[kc2], &kbh[j * 2]);
                }
            }
        }

        // ---- online softmax on fragments ----
        float m0n = -1e30f, m1n = -1e30f;
        #pragma unroll
        for (int nf = 0; nf < 8; nf++) {
            m0n = fmaxf(m0n, fmaxf(s[nf][0], s[nf][1]));
            m1n = fmaxf(m1n, fmaxf(s[nf][2], s[nf][3]));
        }
        #pragma unroll
        for (int off = 1; off <= 2; off <<= 1) {
            m0n = fmaxf(m0n, __shfl_xor_sync(0xffffffffu, m0n, off));
            m1n = fmaxf(m1n, __shfl_xor_sync(0xffffffffu, m1n, off));
        }
        const float M0 = fmaxf(mrow0, m0n);
        const float M1 = fmaxf(mrow1, m1n);
        const float a0 = __expf(mrow0 - M0);
        const float a1 = __expf(mrow1 - M1);
        mrow0 = M0; mrow1 = M1;
        float rs0 = 0.f, rs1 = 0.f;
        #pragma unroll
        for (int nf = 0; nf < 8; nf++) {
            s[nf][0] = __expf(s[nf][0] - M0); rs0 += s[nf][0];
            s[nf][1] = __expf(s[nf][1] - M0); rs0 += s[nf][1];
            s[nf][2] = __expf(s[nf][2] - M1); rs1 += s[nf][2];
            s[nf][3] = __expf(s[nf][3] - M1); rs1 += s[nf][3];
        }
        #pragma unroll
        for (int off = 1; off <= 2; off <<= 1) {
            rs0 += __shfl_xor_sync(0xffffffffu, rs0, off);
            rs1 += __shfl_xor_sync(0xffffffffu, rs1, off);
        }
        lrow0 = lrow0 * a0 + rs0;
        lrow1 = lrow1 * a1 + rs1;
        #pragma unroll
        for (int nf = 0; nf < 8; nf++) {
            o[nf][0] *= a0; o[nf][1] *= a0;
            o[nf][2] *= a1; o[nf][3] *= a1;
        }

        // ---- O += P V, group-wise fragments (P packed hi/lo on the fly) ----
        #pragma unroll
        for (int pc = 0; pc < 4; pc++) {
            uint32_t pfh[4], pfl[4];
            pack_split(s[2 * pc][0],     s[2 * pc][1],     pfh[0], pfl[0]);
            pack_split(s[2 * pc][2],     s[2 * pc][3],     pfh[1], pfl[1]);
            pack_split(s[2 * pc + 1][0], s[2 * pc + 1][1], pfh[2], pfl[2]);
            pack_split(s[2 * pc + 1][2], s[2 * pc + 1][3], pfh[3], pfl[3]);
            #pragma unroll
            for (int g = 0; g < 4; g++) {
                uint32_t vbh[4], vbl[4];
                const uint32_t brel = (g * 16 + lB_row) * FSR + pc * 32 + lB_kb;
                ldsm4(vbh, bVh + brel);
                ldsm4(vbl, bVl + brel);
                #pragma unroll
                for (int j = 0; j < 2; j++) {
                    const int nf = 2 * g + j;
                    mma16816(o[nf], pfh, &vbh[j * 2]);
                    mma16816(o[nf], pfh, &vbl[j * 2]);
                    mma16816(o[nf], pfl, &vbh[j * 2]);
                }
            }
        }
    }

    // ---- epilogue ----
    const float inv0 = 1.0f / lrow0;
    const float inv1 = 1.0f / lrow1;
    const int b  = bh >> 4;
    const int hh = bh & 15;
    const int row0 = q0 + w * 16 + (lane >> 2);
    #pragma unroll
    for (int nf = 0; nf < 8; nf++) {
        const int d = hh * 64 + nf * 8 + (lane & 3) * 2;
        __nv_bfloat16 h00, l00, h01, l01, h10, l10, h11, l11;
        split1(o[nf][0] * inv0, h00, l00);
        split1(o[nf][1] * inv0, h01, l01);
        split1(o[nf][2] * inv1, h10, l10);
        split1(o[nf][3] * inv1, h11, l11);
        const size_t base0 = ((size_t)b * SEQ + row0) * D_MODEL + d;
        const size_t base1 = base0 + 8 * D_MODEL;
        *(__nv_bfloat162*)(chi + base0) = __nv_bfloat162(h00, h01);
        *(__nv_bfloat162*)(clo + base0) = __nv_bfloat162(l00, l01);
        *(__nv_bfloat162*)(chi + base1) = __nv_bfloat162(h10, h11);
        *(__nv_bfloat162*)(clo + base1) = __nv_bfloat162(l10, l11);
    }
}

// ---------------------------------------------------------------------------
extern "C" void kernel_launch(void* const* d_in, const int* in_sizes, int n_in,
                              void* d_out, int out_size)
{
    const float* x  = (const float*)d_in[0];
    const float* Wq = (const float*)d_in[1];
    const float* bq = (const float*)d_in[2];
    const float* Wk = (const float*)d_in[3];
    const float* bk = (const float*)d_in[4];
    const float* Wv = (const float*)d_in[5];
    const float* bv = (const float*)d_in[6];
    const float* Wo = (const float*)d_in[7];
    const float* bo = (const float*)d_in[8];
    float* out = (float*)d_out;

    __nv_bfloat16 *xhi, *xlo, *whi, *wlo;
    __nv_bfloat16 *qhi, *qlo, *khi, *klo, *vhi, *vlo, *chi, *clo;
    cudaGetSymbolAddress((void**)&xhi, g_xhi);
    cudaGetSymbolAddress((void**)&xlo, g_xlo);
    cudaGetSymbolAddress((void**)&whi, g_whi);
    cudaGetSymbolAddress((void**)&wlo, g_wlo);
    cudaGetSymbolAddress((void**)&qhi, g_qhi);
    cudaGetSymbolAddress((void**)&qlo, g_qlo);
    cudaGetSymbolAddress((void**)&khi, g_khi);
    cudaGetSymbolAddress((void**)&klo, g_klo);
    cudaGetSymbolAddress((void**)&vhi, g_vhi);
    cudaGetSymbolAddress((void**)&vlo, g_vlo);
    cudaGetSymbolAddress((void**)&chi, g_chi);
    cudaGetSymbolAddress((void**)&clo, g_clo);

    const int WSZ = D_MODEL * D_MODEL;
    const int xn4 = MROWS * D_MODEL / 4;
    const int wn4 = WSZ / 4;

    split_bf16<<<(xn4 + 255) / 256, 256>>>((const float4*)x,
        (uint2*)xhi, (uint2*)xlo, xn4);
    split_w4<<<4 * (wn4 / 256), 256>>>((const float4*)Wq, (const float4*)Wk,
        (const float4*)Wv, (const float4*)Wo, (uint2*)whi, (uint2*)wlo, wn4);

    const int gsmem = 2 * GB;   // 81920
    cudaFuncSetAttribute(gemm_qkv, cudaFuncAttributeMaxDynamicSharedMemorySize, gsmem);
    cudaFuncSetAttribute(gemm_out, cudaFuncAttributeMaxDynamicSharedMemorySize, gsmem);

    gemm_qkv<<<dim3(24, MROWS / 128), 256, gsmem>>>(xhi, xlo, whi, wlo,
        bq, bk, bv, qhi, qlo, khi, klo, vhi, vlo);

    const int fsmem = 2 * 128 * FSR + 2 * KVB;   // 110592
    cudaFuncSetAttribute(flash_mma, cudaFuncAttributeMaxDynamicSharedMemorySize, fsmem);
    flash_mma<<<dim3(SEQ / 128, BATCH * H), 256, fsmem>>>(qhi, qlo, khi, klo,
                                                          vhi, vlo, chi, clo);

    gemm_out<<<dim3(D_MODEL / 128, MROWS / 128), 256, gsmem>>>(
        chi, clo, whi + 3 * (size_t)WSZ, wlo + 3 * (size_t)WSZ, bo, out);
}

// round 13
// speedup vs baseline: 7.1823x; 2.3705x over previous
#include <cuda_runtime.h>
#include <cuda_fp16.h>
#include <cstdint>

// ---------------------------------------------------------------------------
// MultiHeadAttention: x[B,S,D] -> out[B,S,D]
// B=4, S=2048, D=1024, H=16, dk=64
//   0) convert fp32 -> fp16: x (1 launch), 4 weights (1 fused launch)
//   1) gemm_qkv (fused): Q/K -> fp16 [b,h,s,dk] (Q scaled 1/8),
//                        V   -> fp16 [b,h,dk,s] (transposed)
//   2) flash_mma : tensor-core flash attention (mma.sync fp16, fp32 accum),
//                  cp.async double-buffered K/V; ctx out fp16
//   3) gemm_out  : out = ctx @ Wo^T + bo  (fp32)
// Plain fp16 storage (11-bit mantissa) + fp32 accum: predicted rel_err ~3-6e-4
// (vs 1e-3 gate). 1 MMA per product (3x less tensor work than bf16 3-term),
// half the memory traffic. Target plain sm_100: mma.sync + ldmatrix + cp.async.
// ---------------------------------------------------------------------------

constexpr int D_MODEL = 1024;
constexpr int H       = 16;
constexpr int DKH     = 64;
constexpr int SEQ     = 2048;
constexpr int BATCH   = 4;
constexpr int MROWS   = BATCH * SEQ;      // 8192

__device__ __half g_xh[MROWS * D_MODEL];
__device__ __half g_wh[4][D_MODEL * D_MODEL];
__device__ __half g_qh[BATCH * H * SEQ * DKH];
__device__ __half g_kh[BATCH * H * SEQ * DKH];
__device__ __half g_vh[BATCH * H * DKH * SEQ];   // transposed [b,h,dk,s]
__device__ __half g_ch[MROWS * D_MODEL];

// ---------------- helpers ----------------
__device__ __forceinline__ uint32_t smem_u32(const void* p) {
    uint32_t a;
    asm("{ .reg .u64 t; cvta.to.shared.u64 t, %1; cvt.u32.u64 %0, t; }"
        : "=r"(a) : "l"(p));
    return a;
}
__device__ __forceinline__ void ldsm4(uint32_t* r, uint32_t addr) {
    asm volatile("ldmatrix.sync.aligned.m8n8.x4.shared.b16 {%0,%1,%2,%3}, [%4];"
        : "=r"(r[0]), "=r"(r[1]), "=r"(r[2]), "=r"(r[3]) : "r"(addr));
}
__device__ __forceinline__ void mma16816(float* c, const uint32_t* a,
                                         const uint32_t* b) {
    asm volatile(
        "mma.sync.aligned.m16n8k16.row.col.f32.f16.f16.f32 "
        "{%0,%1,%2,%3}, {%4,%5,%6,%7}, {%8,%9}, {%0,%1,%2,%3};"
        : "+f"(c[0]), "+f"(c[1]), "+f"(c[2]), "+f"(c[3])
        : "r"(a[0]), "r"(a[1]), "r"(a[2]), "r"(a[3]), "r"(b[0]), "r"(b[1]));
}
__device__ __forceinline__ uint32_t packh2(float a, float b) {
    __half2 h = __floats2half2_rn(a, b);
    return *reinterpret_cast<uint32_t*>(&h);
}
#define CP16(dst, src) \
    asm volatile("cp.async.cg.shared.global [%0], [%1], 16;" :: "r"(dst), "l"(src))
#define CP_COMMIT() asm volatile("cp.async.commit_group;" ::: "memory")
#define CP_WAIT0()  asm volatile("cp.async.wait_group 0;"  ::: "memory")

// ---------------------------------------------------------------------------
// convert fp32 -> fp16, 4-wide
// ---------------------------------------------------------------------------
__global__ void __launch_bounds__(256)
cvt_h(const float4* __restrict__ src, uint2* __restrict__ dst, int n4)
{
    const int i = blockIdx.x * 256 + threadIdx.x;
    if (i >= n4) return;
    float4 v = src[i];
    uint2 o;
    o.x = packh2(v.x, v.y);
    o.y = packh2(v.z, v.w);
    dst[i] = o;
}

__global__ void __launch_bounds__(256)
cvt_w4(const float4* __restrict__ w0, const float4* __restrict__ w1,
       const float4* __restrict__ w2, const float4* __restrict__ w3,
       uint2* __restrict__ dst, int wn4)
{
    const int bpw = wn4 / 256;
    const int w   = blockIdx.x / bpw;
    const int i   = (blockIdx.x - w * bpw) * 256 + threadIdx.x;
    const float4* src = (w == 0) ? w0 : (w == 1) ? w1 : (w == 2) ? w2 : w3;
    float4 v = src[i];
    uint2 o;
    o.x = packh2(v.x, v.y);
    o.y = packh2(v.z, v.w);
    dst[(size_t)w * wn4 + i] = o;
}

// ---------------------------------------------------------------------------
// fp16 HMMA GEMM, cp.async double buffer, 2 CTAs/SM.
// CTA 128x128, 8 warps (2m x 4n), BK=32, 1 MMA per (A,B) pair.
// Smem: 2 buffers x 2 tiles x [128][TSTR] (TSTR=80B padded rows).
// ---------------------------------------------------------------------------
constexpr int TSTR = 80;
constexpr int GT   = 128 * TSTR;   // bytes per tile (10240)
constexpr int GB2  = 2 * GT;       // bytes per buffer (20480)

#define GEMM_PIPE(AhP, BhP)                                                     \
    extern __shared__ char smc[];                                               \
    const uint32_t sbase = smem_u32(smc);                                       \
    const int tid  = threadIdx.x;                                               \
    const int wid  = tid >> 5;                                                  \
    const int lane = tid & 31;                                                  \
    const int wm = wid >> 2, wn = wid & 3;                                      \
    const int lrow = tid >> 1, lhalf = tid & 1;                                 \
    const __half* gA = (AhP) + (size_t)(m0 + lrow) * D_MODEL + lhalf * 16;      \
    const __half* gB = (BhP) + (size_t)(n0 + lrow) * D_MODEL + lhalf * 16;      \
    const int lA_row = lane & 15, lA_kb = (lane >> 4) * 16;                     \
    const int lB_row = (lane & 7) + ((lane >> 4) << 3);                         \
    const int lB_kb  = ((lane >> 3) & 1) * 16;                                  \
    const uint32_t ro = lrow * TSTR + lhalf * 32;                               \
    float acc[4][4][4];                                                         \
    _Pragma("unroll")                                                           \
    for (int mi = 0; mi < 4; mi++)                                              \
        _Pragma("unroll")                                                       \
        for (int nf = 0; nf < 4; nf++)                                          \
            _Pragma("unroll")                                                   \
            for (int r = 0; r < 4; r++) acc[mi][nf][r] = 0.f;                   \
    CP16(sbase + ro,           gA);                                             \
    CP16(sbase + ro + 16,      gA + 8);                                         \
    CP16(sbase + GT + ro,      gB);                                             \
    CP16(sbase + GT + ro + 16, gB + 8);                                         \
    CP_COMMIT();                                                                \
    for (int c = 0; c < 32; ++c) {                                              \
        CP_WAIT0();                                                             \
        __syncthreads();                                                        \
        if (c + 1 < 32) {                                                       \
            const uint32_t db = sbase + ((c + 1) & 1) * GB2;                    \
            CP16(db + ro,           gA + (c + 1) * 32);                         \
            CP16(db + ro + 16,      gA + (c + 1) * 32 + 8);                     \
            CP16(db + GT + ro,      gB + (c + 1) * 32);                         \
            CP16(db + GT + ro + 16, gB + (c + 1) * 32 + 8);                     \
            CP_COMMIT();                                                        \
        }                                                                       \
        const uint32_t cb = sbase + (c & 1) * GB2;                              \
        _Pragma("unroll")                                                       \
        for (int ks = 0; ks < 2; ks++) {                                        \
            const int kb = ks * 32;                                             \
            uint32_t bfrag[2][4];                                               \
            _Pragma("unroll")                                                   \
            for (int g = 0; g < 2; g++) {                                       \
                const uint32_t brel = (wn * 32 + g * 16 + lB_row) * TSTR + kb + lB_kb; \
                ldsm4(bfrag[g], cb + GT + brel);                                \
            }                                                                   \
            _Pragma("unroll")                                                   \
            for (int mi = 0; mi < 4; mi++) {                                    \
                uint32_t afrag[4];                                              \
                const uint32_t arel = (wm * 64 + mi * 16 + lA_row) * TSTR + kb + lA_kb; \
                ldsm4(afrag, cb + arel);                                        \
                _Pragma("unroll")                                               \
                for (int nf = 0; nf < 4; nf++)                                  \
                    mma16816(acc[mi][nf], afrag, &bfrag[nf >> 1][(nf & 1) * 2]); \
            }                                                                   \
        }                                                                       \
    }

// Fused QKV projection: wsel = blockIdx.x/8 selects weight/bias/epilogue.
__global__ void __launch_bounds__(256, 2)
gemm_qkv(const __half* __restrict__ xh, const __half* __restrict__ wh,
         const float* __restrict__ bqp, const float* __restrict__ bkp,
         const float* __restrict__ bvp,
         __half* __restrict__ qh, __half* __restrict__ kh,
         __half* __restrict__ vh)
{
    const int wsel = blockIdx.x >> 3;
    const int n0   = (blockIdx.x & 7) * 128;
    const int m0   = blockIdx.y * 128;
    const __half* Bh = wh + (size_t)wsel * (D_MODEL * D_MODEL);
    const float* bias = (wsel == 0) ? bqp : (wsel == 1) ? bkp : bvp;
    const float scale = (wsel == 0) ? 0.125f : 1.0f;

    GEMM_PIPE(xh, Bh)

    __half* Dh = (wsel == 0) ? qh : (wsel == 1) ? kh : vh;

    #pragma unroll
    for (int mi = 0; mi < 4; mi++) {
        const int r0 = m0 + wm * 64 + mi * 16 + (lane >> 2);
        const int b  = r0 >> 11;
        const int s0 = r0 & (SEQ - 1);
        #pragma unroll
        for (int nf = 0; nf < 4; nf++) {
            const int n  = n0 + wn * 32 + nf * 8 + (lane & 3) * 2;
            const float b0 = __ldg(bias + n);
            const float b1 = __ldg(bias + n + 1);
            const float v00 = (acc[mi][nf][0] + b0) * scale;
            const float v01 = (acc[mi][nf][1] + b1) * scale;
            const float v10 = (acc[mi][nf][2] + b0) * scale;
            const float v11 = (acc[mi][nf][3] + b1) * scale;
            const int hd = n >> 6, d = n & 63;
            if (wsel < 2) {
                const size_t base = ((size_t)(b * H + hd) * SEQ + s0) * DKH + d;
                *(__half2*)(Dh + base)           = __floats2half2_rn(v00, v01);
                *(__half2*)(Dh + base + 8 * DKH) = __floats2half2_rn(v10, v11);
            } else {
                const size_t base = ((size_t)(b * H + hd) * DKH + d) * SEQ + s0;
                Dh[base]           = __float2half_rn(v00);
                Dh[base + SEQ]     = __float2half_rn(v01);
                Dh[base + 8]       = __float2half_rn(v10);
                Dh[base + SEQ + 8] = __float2half_rn(v11);
            }
        }
    }
}

__global__ void __launch_bounds__(256, 2)
gemm_out(const __half* __restrict__ Ah, const __half* __restrict__ Bh,
         const float* __restrict__ bias, float* __restrict__ C)
{
    const int m0 = blockIdx.y * 128;
    const int n0 = blockIdx.x * 128;

    GEMM_PIPE(Ah, Bh)

    #pragma unroll
    for (int mi = 0; mi < 4; mi++) {
        const int r0 = m0 + wm * 64 + mi * 16 + (lane >> 2);
        #pragma unroll
        for (int nf = 0; nf < 4; nf++) {
            const int n = n0 + wn * 32 + nf * 8 + (lane & 3) * 2;
            const float b0 = __ldg(bias + n);
            const float b1 = __ldg(bias + n + 1);
            float2 lo2, hi2;
            lo2.x = acc[mi][nf][0] + b0;
            lo2.y = acc[mi][nf][1] + b1;
            hi2.x = acc[mi][nf][2] + b0;
            hi2.y = acc[mi][nf][3] + b1;
            *(float2*)(C + (size_t)r0 * D_MODEL + n)       = lo2;
            *(float2*)(C + (size_t)(r0 + 8) * D_MODEL + n) = hi2;
        }
    }
}

// ---------------------------------------------------------------------------
// fp16 tensor-core flash attention, cp.async double-buffered K/V, 2 CTAs/SM.
// CTA = 128 q-rows of one (b,h); 8 warps x m16. KV tiled 64 keys.
// ---------------------------------------------------------------------------
constexpr int FSR  = 144;             // smem row stride (64 fp16 rows)
constexpr int KVT  = 64 * FSR;        // one tile (9216 B)
constexpr int KVB2 = 2 * KVT;         // K,V buffer (18432 B)

#define FLASH_KV_ISSUE(bufbase, c0_)                                            \
    {                                                                           \
        const int row = tid >> 2, q4 = tid & 3;                                 \
        const __half* gk = kh + boff + (size_t)((c0_) + row) * DKH + q4 * 16;   \
        const __half* gv = vh + boff + (size_t)row * SEQ + (c0_) + q4 * 16;     \
        const uint32_t kro = row * FSR + q4 * 32;                               \
        CP16((bufbase) + kro,            gk);                                   \
        CP16((bufbase) + kro + 16,       gk + 8);                               \
        CP16((bufbase) + KVT + kro,      gv);                                   \
        CP16((bufbase) + KVT + kro + 16, gv + 8);                               \
    }

__global__ void __launch_bounds__(256, 2)
flash_mma(const __half* __restrict__ qh, const __half* __restrict__ kh,
          const __half* __restrict__ vh, __half* __restrict__ ch)
{
    extern __shared__ char fsm[];
    const uint32_t bQ  = smem_u32(fsm);
    const uint32_t bKV = bQ + 128 * FSR;     // double KV buffer base

    const int tid  = threadIdx.x;
    const int lane = tid & 31;
    const int w    = tid >> 5;
    const int bh   = blockIdx.y;
    const int q0   = blockIdx.x * 128;
    const size_t boff = (size_t)bh * SEQ * DKH;

    FLASH_KV_ISSUE(bKV, 0);
    CP_COMMIT();

    // Q tile (128 x 64): 2 threads/row, 32 halves each
    {
        const int row = tid >> 1, half = tid & 1;
        const __half* gq = qh + boff + (size_t)(q0 + row) * DKH + half * 32;
        #pragma unroll
        for (int i = 0; i < 4; i++)
            *(uint4*)(fsm + row * FSR + half * 64 + i * 16) = *(const uint4*)(gq + i * 8);
    }
    __syncthreads();

    const int lA_row = lane & 15;
    const int lA_kb  = (lane >> 4) * 16;
    const int lB_row = (lane & 7) + ((lane >> 4) << 3);
    const int lB_kb  = ((lane >> 3) & 1) * 16;

    uint32_t qf[4][4];
    #pragma unroll
    for (int kc2 = 0; kc2 < 4; kc2++) {
        const uint32_t arel = (w * 16 + lA_row) * FSR + kc2 * 32 + lA_kb;
        ldsm4(qf[kc2], bQ + arel);
    }

    float o[8][4];
    #pragma unroll
    for (int nf = 0; nf < 8; nf++)
        #pragma unroll
        for (int r = 0; r < 4; r++) o[nf][r] = 0.f;
    float mrow0 = -1e30f, mrow1 = -1e30f, lrow0 = 0.f, lrow1 = 0.f;

    for (int kt = 0; kt < SEQ / 64; kt++) {
        CP_WAIT0();
        __syncthreads();
        if (kt + 1 < SEQ / 64) {
            FLASH_KV_ISSUE(bKV + ((kt + 1) & 1) * KVB2, (kt + 1) * 64);
            CP_COMMIT();
        }
        const uint32_t bK = bKV + (kt & 1) * KVB2;
        const uint32_t bV = bK + KVT;

        // ---- S = Q K^T (m16 x n64) ----
        float s[8][4];
        #pragma unroll
        for (int nf = 0; nf < 8; nf++)
            #pragma unroll
            for (int r = 0; r < 4; r++) s[nf][r] = 0.f;

        #pragma unroll
        for (int kc2 = 0; kc2 < 4; kc2++) {
            #pragma unroll
            for (int g = 0; g < 4; g++) {
                uint32_t kb[4];
                const uint32_t brel = (g * 16 + lB_row) * FSR + kc2 * 32 + lB_kb;
                ldsm4(kb, bK + brel);
                mma16816(s[2 * g],     qf[kc2], &kb[0]);
                mma16816(s[2 * g + 1], qf[kc2], &kb[2]);
            }
        }

        // ---- online softmax on fragments ----
        float m0n = -1e30f, m1n = -1e30f;
        #pragma unroll
        for (int nf = 0; nf < 8; nf++) {
            m0n = fmaxf(m0n, fmaxf(s[nf][0], s[nf][1]));
            m1n = fmaxf(m1n, fmaxf(s[nf][2], s[nf][3]));
        }
        #pragma unroll
        for (int off = 1; off <= 2; off <<= 1) {
            m0n = fmaxf(m0n, __shfl_xor_sync(0xffffffffu, m0n, off));
            m1n = fmaxf(m1n, __shfl_xor_sync(0xffffffffu, m1n, off));
        }
        const float M0 = fmaxf(mrow0, m0n);
        const float M1 = fmaxf(mrow1, m1n);
        const float a0 = __expf(mrow0 - M0);
        const float a1 = __expf(mrow1 - M1);
        mrow0 = M0; mrow1 = M1;
        float rs0 = 0.f, rs1 = 0.f;
        #pragma unroll
        for (int nf = 0; nf < 8; nf++) {
            s[nf][0] = __expf(s[nf][0] - M0); rs0 += s[nf][0];
            s[nf][1] = __expf(s[nf][1] - M0); rs0 += s[nf][1];
            s[nf][2] = __expf(s[nf][2] - M1); rs1 += s[nf][2];
            s[nf][3] = __expf(s[nf][3] - M1); rs1 += s[nf][3];
        }
        #pragma unroll
        for (int off = 1; off <= 2; off <<= 1) {
            rs0 += __shfl_xor_sync(0xffffffffu, rs0, off);
            rs1 += __shfl_xor_sync(0xffffffffu, rs1, off);
        }
        lrow0 = lrow0 * a0 + rs0;
        lrow1 = lrow1 * a1 + rs1;
        #pragma unroll
        for (int nf = 0; nf < 8; nf++) {
            o[nf][0] *= a0; o[nf][1] *= a0;
            o[nf][2] *= a1; o[nf][3] *= a1;
        }

        // ---- O += P V ----
        #pragma unroll
        for (int pc = 0; pc < 4; pc++) {
            uint32_t pf[4];
            pf[0] = packh2(s[2 * pc][0],     s[2 * pc][1]);
            pf[1] = packh2(s[2 * pc][2],     s[2 * pc][3]);
            pf[2] = packh2(s[2 * pc + 1][0], s[2 * pc + 1][1]);
            pf[3] = packh2(s[2 * pc + 1][2], s[2 * pc + 1][3]);
            #pragma unroll
            for (int g = 0; g < 4; g++) {
                uint32_t vb[4];
                const uint32_t brel = (g * 16 + lB_row) * FSR + pc * 32 + lB_kb;
                ldsm4(vb, bV + brel);
                mma16816(o[2 * g],     pf, &vb[0]);
                mma16816(o[2 * g + 1], pf, &vb[2]);
            }
        }
    }

    // ---- epilogue: normalize, write ctx fp16 [b,s,D] ----
    const float inv0 = 1.0f / lrow0;
    const float inv1 = 1.0f / lrow1;
    const int b  = bh >> 4;
    const int hh = bh & 15;
    const int row0 = q0 + w * 16 + (lane >> 2);
    #pragma unroll
    for (int nf = 0; nf < 8; nf++) {
        const int d = hh * 64 + nf * 8 + (lane & 3) * 2;
        const size_t base0 = ((size_t)b * SEQ + row0) * D_MODEL + d;
        const size_t base1 = base0 + 8 * D_MODEL;
        *(__half2*)(ch + base0) = __floats2half2_rn(o[nf][0] * inv0, o[nf][1] * inv0);
        *(__half2*)(ch + base1) = __floats2half2_rn(o[nf][2] * inv1, o[nf][3] * inv1);
    }
}

// ---------------------------------------------------------------------------
extern "C" void kernel_launch(void* const* d_in, const int* in_sizes, int n_in,
                              void* d_out, int out_size)
{
    const float* x  = (const float*)d_in[0];
    const float* Wq = (const float*)d_in[1];
    const float* bq = (const float*)d_in[2];
    const float* Wk = (const float*)d_in[3];
    const float* bk = (const float*)d_in[4];
    const float* Wv = (const float*)d_in[5];
    const float* bv = (const float*)d_in[6];
    const float* Wo = (const float*)d_in[7];
    const float* bo = (const float*)d_in[8];
    float* out = (float*)d_out;

    __half *xh, *wh, *qh, *kh, *vh, *ch;
    cudaGetSymbolAddress((void**)&xh, g_xh);
    cudaGetSymbolAddress((void**)&wh, g_wh);
    cudaGetSymbolAddress((void**)&qh, g_qh);
    cudaGetSymbolAddress((void**)&kh, g_kh);
    cudaGetSymbolAddress((void**)&vh, g_vh);
    cudaGetSymbolAddress((void**)&ch, g_ch);

    const int WSZ = D_MODEL * D_MODEL;
    const int xn4 = MROWS * D_MODEL / 4;
    const int wn4 = WSZ / 4;

    cvt_h<<<(xn4 + 255) / 256, 256>>>((const float4*)x, (uint2*)xh, xn4);
    cvt_w4<<<4 * (wn4 / 256), 256>>>((const float4*)Wq, (const float4*)Wk,
        (const float4*)Wv, (const float4*)Wo, (uint2*)wh, wn4);

    const int gsmem = 2 * GB2;   // 40960
    cudaFuncSetAttribute(gemm_qkv, cudaFuncAttributeMaxDynamicSharedMemorySize, gsmem);
    cudaFuncSetAttribute(gemm_out, cudaFuncAttributeMaxDynamicSharedMemorySize, gsmem);

    gemm_qkv<<<dim3(24, MROWS / 128), 256, gsmem>>>(xh, wh, bq, bk, bv,
                                                    qh, kh, vh);

    const int fsmem = 128 * FSR + 2 * KVB2;   // 55296
    cudaFuncSetAttribute(flash_mma, cudaFuncAttributeMaxDynamicSharedMemorySize, fsmem);
    flash_mma<<<dim3(SEQ / 128, BATCH * H), 256, fsmem>>>(qh, kh, vh, ch);

    gemm_out<<<dim3(D_MODEL / 128, MROWS / 128), 256, gsmem>>>(
        ch, wh + 3 * (size_t)WSZ, bo, out);
}